// round 1
// baseline (speedup 1.0000x reference)
#include <cuda_runtime.h>
#include <cuda_bf16.h>
#include <math.h>

// Problem constants
#define BB 2
#define SS 2048
#define DM 2048
#define NH 32
#define NKV 8
#define HD 64
#define MTOT (BB * SS)          // 4096
#define QDIM (NH * HD)          // 2048
#define KVDIM (NKV * HD)        // 512

// ---------------------------------------------------------------------------
// Scratch (device globals; no dynamic allocation allowed)
// ---------------------------------------------------------------------------
__device__ float g_Q[MTOT * QDIM];    // 32 MB
__device__ float g_K[MTOT * KVDIM];   //  8 MB
__device__ float g_V[MTOT * KVDIM];   //  8 MB
__device__ float g_O[MTOT * QDIM];    // 32 MB

// ---------------------------------------------------------------------------
// SGEMM: C[M,N] = A[M,K] * B[N,K]^T   (both K-major, "NT")
// 128x128 tile, BK=8, 256 threads, 8x8 per thread
// ---------------------------------------------------------------------------
__global__ __launch_bounds__(256) void gemm_nt(const float* __restrict__ A,
                                               const float* __restrict__ B,
                                               float* __restrict__ C,
                                               int M, int N, int K) {
    __shared__ float sA[8][128];
    __shared__ float sB[8][128];

    const int tid = threadIdx.x;
    const int m0 = blockIdx.y * 128;
    const int n0 = blockIdx.x * 128;
    const int tr = tid >> 4;        // 0..15
    const int tc = tid & 15;        // 0..15

    const int loadRow = tid >> 1;       // 0..127
    const int loadK = (tid & 1) << 2;   // 0 or 4

    const float* Aptr = A + (m0 + loadRow) * K + loadK;
    const float* Bptr = B + (n0 + loadRow) * K + loadK;

    float acc[8][8];
#pragma unroll
    for (int i = 0; i < 8; i++)
#pragma unroll
        for (int j = 0; j < 8; j++) acc[i][j] = 0.0f;

    for (int k0 = 0; k0 < K; k0 += 8) {
        float4 av = *(const float4*)(Aptr + k0);
        float4 bv = *(const float4*)(Bptr + k0);
        sA[loadK + 0][loadRow] = av.x;
        sA[loadK + 1][loadRow] = av.y;
        sA[loadK + 2][loadRow] = av.z;
        sA[loadK + 3][loadRow] = av.w;
        sB[loadK + 0][loadRow] = bv.x;
        sB[loadK + 1][loadRow] = bv.y;
        sB[loadK + 2][loadRow] = bv.z;
        sB[loadK + 3][loadRow] = bv.w;
        __syncthreads();

#pragma unroll
        for (int k = 0; k < 8; k++) {
            float4 a0 = *(const float4*)&sA[k][tr * 8];
            float4 a1 = *(const float4*)&sA[k][tr * 8 + 4];
            float4 b0 = *(const float4*)&sB[k][tc * 8];
            float4 b1 = *(const float4*)&sB[k][tc * 8 + 4];
            float ar[8] = {a0.x, a0.y, a0.z, a0.w, a1.x, a1.y, a1.z, a1.w};
            float br[8] = {b0.x, b0.y, b0.z, b0.w, b1.x, b1.y, b1.z, b1.w};
#pragma unroll
            for (int i = 0; i < 8; i++)
#pragma unroll
                for (int j = 0; j < 8; j++) acc[i][j] = fmaf(ar[i], br[j], acc[i][j]);
        }
        __syncthreads();
    }

#pragma unroll
    for (int i = 0; i < 8; i++) {
        float* cp = C + (m0 + tr * 8 + i) * N + n0 + tc * 8;
        float4 v0 = {acc[i][0], acc[i][1], acc[i][2], acc[i][3]};
        float4 v1 = {acc[i][4], acc[i][5], acc[i][6], acc[i][7]};
        *(float4*)(cp) = v0;
        *(float4*)(cp + 4) = v1;
    }
}

// ---------------------------------------------------------------------------
// RoPE (reference convention: rotate_half over halves, cos repeat_interleave)
// out[d]    = q[d]*cos[d/2]        - q[d+32]*sin[d/2]
// out[d+32] = q[d+32]*cos[16+d/2]  + q[d]*sin[16+d/2]
// mat: [MTOT, nheads*64]
// ---------------------------------------------------------------------------
__global__ void rope_kernel(float* __restrict__ mat,
                            const float* __restrict__ cosT,
                            const float* __restrict__ sinT,
                            int nheads) {
    int idx = blockIdx.x * blockDim.x + threadIdx.x;
    int total = MTOT * nheads * 32;
    if (idx >= total) return;
    int d = idx & 31;
    int h = (idx >> 5) % nheads;
    int m = idx / (32 * nheads);
    int s = m & (SS - 1);

    float* p = mat + (size_t)m * (nheads * 64) + h * 64 + d;
    float a = p[0];
    float b = p[32];
    int ci = s * 32 + (d >> 1);
    float c1 = cosT[ci], s1 = sinT[ci];
    float c2 = cosT[ci + 16], s2 = sinT[ci + 16];
    p[0] = a * c1 - b * s1;
    p[32] = b * c2 + a * s2;
}

// ---------------------------------------------------------------------------
// Flash attention (causal, GQA). grid (S/64, H, B), 256 threads.
// Each thread: one q row (r = tid/4), 16 of the 64 head dims (dq = (tid%4)*16).
// Online softmax replicated across the 4 lanes of each row group.
// ---------------------------------------------------------------------------
__global__ __launch_bounds__(256) void flash_kernel(const float* __restrict__ Q,
                                                    const float* __restrict__ K,
                                                    const float* __restrict__ V,
                                                    float* __restrict__ O) {
    __shared__ float sK[64 * 64];
    __shared__ float sV[64 * 64];

    const int qb = blockIdx.x;
    const int h = blockIdx.y;
    const int b = blockIdx.z;
    const int kvh = h >> 2;  // 4 query heads per kv head

    const int tid = threadIdx.x;
    const int r = tid >> 2;
    const int dq = (tid & 3) << 4;  // 0,16,32,48
    const int qrow = qb * 64 + r;

    const float scale = 0.125f;  // 1/sqrt(64)

    float q[16];
    {
        const float* qp = Q + ((size_t)(b * SS + qrow)) * QDIM + h * HD + dq;
#pragma unroll
        for (int c = 0; c < 4; c++) {
            float4 v = *(const float4*)(qp + c * 4);
            q[c * 4 + 0] = v.x * scale;
            q[c * 4 + 1] = v.y * scale;
            q[c * 4 + 2] = v.z * scale;
            q[c * 4 + 3] = v.w * scale;
        }
    }

    float m = -INFINITY, l = 0.0f;
    float o[16];
#pragma unroll
    for (int i = 0; i < 16; i++) o[i] = 0.0f;

    for (int j0 = 0; j0 <= qb * 64; j0 += 64) {
        // stage K,V tile (64 x 64)
#pragma unroll
        for (int i = 0; i < 4; i++) {
            int idx = tid + i * 256;
            int row = idx >> 4;
            int cq = (idx & 15) << 2;
            const float* kp = K + ((size_t)(b * SS + j0 + row)) * KVDIM + kvh * HD + cq;
            const float* vp = V + ((size_t)(b * SS + j0 + row)) * KVDIM + kvh * HD + cq;
            *(float4*)(sK + row * 64 + cq) = *(const float4*)kp;
            *(float4*)(sV + row * 64 + cq) = *(const float4*)vp;
        }
        __syncthreads();

        const bool full = (j0 + 63 <= qrow);
#pragma unroll 4
        for (int j = 0; j < 64; j++) {
            // partial dot over my 16 dims
            const float* kr = sK + j * 64 + dq;
            float4 k0 = *(const float4*)(kr);
            float4 k1 = *(const float4*)(kr + 4);
            float4 k2 = *(const float4*)(kr + 8);
            float4 k3 = *(const float4*)(kr + 12);
            float part = q[0] * k0.x + q[1] * k0.y + q[2] * k0.z + q[3] * k0.w;
            part += q[4] * k1.x + q[5] * k1.y + q[6] * k1.z + q[7] * k1.w;
            part += q[8] * k2.x + q[9] * k2.y + q[10] * k2.z + q[11] * k2.w;
            part += q[12] * k3.x + q[13] * k3.y + q[14] * k3.z + q[15] * k3.w;
            part += __shfl_xor_sync(0xffffffffu, part, 1);
            part += __shfl_xor_sync(0xffffffffu, part, 2);
            float s = part;

            if (full || (j0 + j <= qrow)) {
                if (s > m) {
                    float f = __expf(m - s);
                    m = s;
                    l *= f;
#pragma unroll
                    for (int i = 0; i < 16; i++) o[i] *= f;
                }
                float p = __expf(s - m);
                l += p;
                const float* vr = sV + j * 64 + dq;
                float4 v0 = *(const float4*)(vr);
                float4 v1 = *(const float4*)(vr + 4);
                float4 v2 = *(const float4*)(vr + 8);
                float4 v3 = *(const float4*)(vr + 12);
                o[0] += p * v0.x;  o[1] += p * v0.y;  o[2] += p * v0.z;  o[3] += p * v0.w;
                o[4] += p * v1.x;  o[5] += p * v1.y;  o[6] += p * v1.z;  o[7] += p * v1.w;
                o[8] += p * v2.x;  o[9] += p * v2.y;  o[10] += p * v2.z; o[11] += p * v2.w;
                o[12] += p * v3.x; o[13] += p * v3.y; o[14] += p * v3.z; o[15] += p * v3.w;
            }
        }
        __syncthreads();
    }

    float inv = 1.0f / l;
    float* op = O + ((size_t)(b * SS + qrow)) * QDIM + h * HD + dq;
#pragma unroll
    for (int c = 0; c < 4; c++) {
        float4 v = {o[c * 4 + 0] * inv, o[c * 4 + 1] * inv,
                    o[c * 4 + 2] * inv, o[c * 4 + 3] * inv};
        *(float4*)(op + c * 4) = v;
    }
}

// ---------------------------------------------------------------------------
// Launch
// ---------------------------------------------------------------------------
extern "C" void kernel_launch(void* const* d_in, const int* in_sizes, int n_in,
                              void* d_out, int out_size) {
    const float* x = (const float*)d_in[0];
    const float* wq = (const float*)d_in[1];
    const float* wk = (const float*)d_in[2];
    const float* wv = (const float*)d_in[3];
    const float* wo = (const float*)d_in[4];
    const float* cosT = (const float*)d_in[5];
    const float* sinT = (const float*)d_in[6];
    float* out = (float*)d_out;

    float *Qp, *Kp, *Vp, *Op;
    cudaGetSymbolAddress((void**)&Qp, g_Q);
    cudaGetSymbolAddress((void**)&Kp, g_K);
    cudaGetSymbolAddress((void**)&Vp, g_V);
    cudaGetSymbolAddress((void**)&Op, g_O);

    // QKV projections
    gemm_nt<<<dim3(QDIM / 128, MTOT / 128), 256>>>(x, wq, Qp, MTOT, QDIM, DM);
    gemm_nt<<<dim3(KVDIM / 128, MTOT / 128), 256>>>(x, wk, Kp, MTOT, KVDIM, DM);
    gemm_nt<<<dim3(KVDIM / 128, MTOT / 128), 256>>>(x, wv, Vp, MTOT, KVDIM, DM);

    // RoPE on Q and K
    {
        int totQ = MTOT * NH * 32;
        rope_kernel<<<(totQ + 255) / 256, 256>>>(Qp, cosT, sinT, NH);
        int totK = MTOT * NKV * 32;
        rope_kernel<<<(totK + 255) / 256, 256>>>(Kp, cosT, sinT, NKV);
    }

    // Attention
    flash_kernel<<<dim3(SS / 64, NH, BB), 256>>>(Qp, Kp, Vp, Op);

    // Output projection
    gemm_nt<<<dim3(DM / 128, MTOT / 128), 256>>>(Op, wo, out, MTOT, DM, QDIM);
}

// round 3
// speedup vs baseline: 1.3052x; 1.3052x over previous
#include <cuda_runtime.h>
#include <cuda_bf16.h>
#include <math.h>
#include <stdint.h>

// Problem constants
#define BB 2
#define SS 2048
#define DM 2048
#define NH 32
#define NKV 8
#define HD 64
#define MTOT (BB * SS)          // 4096
#define QDIM (NH * HD)          // 2048
#define KVDIM (NKV * HD)        // 512
#define QKVD (QDIM + 2 * KVDIM) // 3072

// ---------------------------------------------------------------------------
// Scratch (device globals; no dynamic allocation allowed)
// ---------------------------------------------------------------------------
__device__ float g_QKV[MTOT * QKVD];          // 48 MB  (Q | K | V per row)
__device__ float g_O[MTOT * QDIM];            // 32 MB  attention output
__device__ __nv_bfloat16 g_xh[MTOT * DM];
__device__ __nv_bfloat16 g_xl[MTOT * DM];
__device__ __nv_bfloat16 g_Wch[QKVD * DM];
__device__ __nv_bfloat16 g_Wcl[QKVD * DM];
__device__ __nv_bfloat16 g_Oh[MTOT * QDIM];
__device__ __nv_bfloat16 g_Ol[MTOT * QDIM];
__device__ __nv_bfloat16 g_Woh[DM * QDIM];
__device__ __nv_bfloat16 g_Wol[DM * QDIM];

// ---------------------------------------------------------------------------
// PTX helpers (sm_80-era: compiles for baseline sm_100)
// ---------------------------------------------------------------------------
__device__ __forceinline__ uint32_t smem_u32(const void* p) {
    uint32_t a;
    asm("{ .reg .u64 t; cvta.to.shared.u64 t, %1; cvt.u32.u64 %0, t; }" : "=r"(a) : "l"(p));
    return a;
}
__device__ __forceinline__ void ldsm4(uint32_t* r, uint32_t addr) {
    asm volatile("ldmatrix.sync.aligned.m8n8.x4.shared.b16 {%0,%1,%2,%3}, [%4];"
                 : "=r"(r[0]), "=r"(r[1]), "=r"(r[2]), "=r"(r[3]) : "r"(addr));
}
__device__ __forceinline__ void mma16816(float* c, const uint32_t* a, const uint32_t* b) {
    asm volatile(
        "mma.sync.aligned.m16n8k16.row.col.f32.bf16.bf16.f32 "
        "{%0,%1,%2,%3}, {%4,%5,%6,%7}, {%8,%9}, {%0,%1,%2,%3};"
        : "+f"(c[0]), "+f"(c[1]), "+f"(c[2]), "+f"(c[3])
        : "r"(a[0]), "r"(a[1]), "r"(a[2]), "r"(a[3]), "r"(b[0]), "r"(b[1]));
}
__device__ __forceinline__ void cp_async16(uint32_t saddr, const void* gaddr) {
    asm volatile("cp.async.cg.shared.global [%0], [%1], 16;" :: "r"(saddr), "l"(gaddr));
}

// ---------------------------------------------------------------------------
// Split-bf16 HMMA GEMM: C[M,NN] = A[M,K] * B[NN,K]^T (fp32 out)
// A ≈ Ah+Al, B ≈ Bh+Bl.  D = AhBh + AhBl + AlBh.
// CTA 128x128, BK=32, 256 threads (8 warps, 4x2), cp.async double buffer.
// SMEM row stride 40 bf16 (80B): conflict-free ldmatrix.
// ---------------------------------------------------------------------------
#define GT_ARR 10240                 // 128 rows * 80 B
#define GT_STAGE (4 * GT_ARR)        // Ah, Al, Bh, Bl
#define GT_SMEM_TOTAL (2 * GT_STAGE) // 81920 B

__global__ __launch_bounds__(256, 1) void gemm_tc(
    const __nv_bfloat16* __restrict__ Ah, const __nv_bfloat16* __restrict__ Al,
    const __nv_bfloat16* __restrict__ Bh, const __nv_bfloat16* __restrict__ Bl,
    float* __restrict__ C, int NN, int K)
{
    extern __shared__ char smem[];
    const uint32_t sb = smem_u32(smem);
    const int tid = threadIdx.x;
    const int wid = tid >> 5;
    const int lane = tid & 31;
    const int wm = wid & 3;          // 0..3 -> 32 rows each
    const int wn = wid >> 2;         // 0..1 -> 64 cols each
    const int m0 = blockIdx.y * 128;
    const int n0 = blockIdx.x * 128;

    const __nv_bfloat16* const baseArr[4] = {
        Ah + (size_t)m0 * K, Al + (size_t)m0 * K,
        Bh + (size_t)n0 * K, Bl + (size_t)n0 * K};

    float acc[2][8][4];
#pragma unroll
    for (int i = 0; i < 2; i++)
#pragma unroll
        for (int j = 0; j < 8; j++)
#pragma unroll
            for (int q = 0; q < 4; q++) acc[i][j][q] = 0.0f;

    const int NC = K / 32;

    // ldmatrix lane address components
    const int lg = lane >> 3;   // group 0..3
    const int lr = lane & 7;    // row within group

#define LOADSTAGE(cc) do {                                                     \
    const uint32_t stg = ((cc) & 1) ? GT_STAGE : 0;                            \
    const int k0 = (cc) * 32;                                                  \
    _Pragma("unroll")                                                          \
    for (int i = 0; i < 8; i++) {                                              \
        int gidx = tid + i * 256;                                              \
        int arr = gidx >> 9;                                                   \
        int wi = gidx & 511;                                                   \
        int row = wi >> 2;                                                     \
        int q = wi & 3;                                                        \
        const void* g = baseArr[arr] + (size_t)row * K + k0 + q * 8;           \
        uint32_t s = sb + stg + arr * GT_ARR + row * 80 + q * 16;              \
        cp_async16(s, g);                                                      \
    }                                                                          \
    asm volatile("cp.async.commit_group;" ::: "memory");                       \
} while (0)

    LOADSTAGE(0);

    for (int c = 0; c < NC; c++) {
        asm volatile("cp.async.wait_group 0;" ::: "memory");
        __syncthreads();
        if (c + 1 < NC) LOADSTAGE(c + 1);

        const uint32_t stg = sb + ((c & 1) ? GT_STAGE : 0);
        const uint32_t sAh = stg;
        const uint32_t sAl = stg + GT_ARR;
        const uint32_t sBh = stg + 2 * GT_ARR;
        const uint32_t sBl = stg + 3 * GT_ARR;

#pragma unroll
        for (int kk = 0; kk < 2; kk++) {
            const int kbyte = kk * 32;
            // A fragments: two m16 tiles, hi & lo
            uint32_t fAh[2][4], fAl[2][4];
#pragma unroll
            for (int mt = 0; mt < 2; mt++) {
                int arow = wm * 32 + mt * 16 + (lg & 1) * 8 + lr;
                uint32_t aoff = (uint32_t)(arow * 80 + kbyte + (lg >> 1) * 16);
                ldsm4(fAh[mt], sAh + aoff);
                ldsm4(fAl[mt], sAl + aoff);
            }
#pragma unroll
            for (int np = 0; np < 4; np++) {  // pairs of n8 tiles
                int brow = wn * 64 + np * 16 + (lg >> 1) * 8 + lr;
                uint32_t boff = (uint32_t)(brow * 80 + kbyte + (lg & 1) * 16);
                uint32_t fBh[4], fBl[4];
                ldsm4(fBh, sBh + boff);
                ldsm4(fBl, sBl + boff);
#pragma unroll
                for (int mt = 0; mt < 2; mt++) {
                    mma16816(acc[mt][np * 2], fAh[mt], fBh);
                    mma16816(acc[mt][np * 2], fAl[mt], fBh);
                    mma16816(acc[mt][np * 2], fAh[mt], fBl);
                    mma16816(acc[mt][np * 2 + 1], fAh[mt], fBh + 2);
                    mma16816(acc[mt][np * 2 + 1], fAl[mt], fBh + 2);
                    mma16816(acc[mt][np * 2 + 1], fAh[mt], fBl + 2);
                }
            }
        }
        __syncthreads();
    }

    // Epilogue: write fp32 accumulators
#pragma unroll
    for (int mt = 0; mt < 2; mt++) {
        int row0 = m0 + wm * 32 + mt * 16 + (lane >> 2);
#pragma unroll
        for (int nt = 0; nt < 8; nt++) {
            int col = n0 + wn * 64 + nt * 8 + (lane & 3) * 2;
            float2 v0 = {acc[mt][nt][0], acc[mt][nt][1]};
            float2 v1 = {acc[mt][nt][2], acc[mt][nt][3]};
            *(float2*)(C + (size_t)row0 * NN + col) = v0;
            *(float2*)(C + (size_t)(row0 + 8) * NN + col) = v1;
        }
    }
#undef LOADSTAGE
}

// ---------------------------------------------------------------------------
// fp32 -> bf16 hi/lo split
// ---------------------------------------------------------------------------
__global__ void cvt2(const float* __restrict__ in, __nv_bfloat16* __restrict__ hi,
                     __nv_bfloat16* __restrict__ lo, int n2) {
    int i = blockIdx.x * blockDim.x + threadIdx.x;
    if (i >= n2) return;
    float2 v = ((const float2*)in)[i];
    __nv_bfloat16 h0 = __float2bfloat16(v.x);
    __nv_bfloat16 h1 = __float2bfloat16(v.y);
    float r0 = v.x - __bfloat162float(h0);
    float r1 = v.y - __bfloat162float(h1);
    __nv_bfloat162 hv; hv.x = h0; hv.y = h1;
    __nv_bfloat162 lv; lv.x = __float2bfloat16(r0); lv.y = __float2bfloat16(r1);
    ((__nv_bfloat162*)hi)[i] = hv;
    ((__nv_bfloat162*)lo)[i] = lv;
}

// ---------------------------------------------------------------------------
// RoPE on a column range of g_QKV (rowStride 3072)
// ---------------------------------------------------------------------------
__global__ void rope_kernel(float* __restrict__ mat, int rowStride, int colBase,
                            int nheads, const float* __restrict__ cosT,
                            const float* __restrict__ sinT) {
    int idx = blockIdx.x * blockDim.x + threadIdx.x;
    int total = MTOT * nheads * 32;
    if (idx >= total) return;
    int d = idx & 31;
    int h = (idx >> 5) % nheads;
    int m = idx / (32 * nheads);
    int s = m & (SS - 1);

    float* p = mat + (size_t)m * rowStride + colBase + h * 64 + d;
    float a = p[0];
    float b = p[32];
    int ci = s * 32 + (d >> 1);
    float c1 = cosT[ci], s1 = sinT[ci];
    float c2 = cosT[ci + 16], s2 = sinT[ci + 16];
    p[0] = a * c1 - b * s1;
    p[32] = b * c2 + a * s2;
}

// ---------------------------------------------------------------------------
// Flash attention (causal, GQA) over the fused QKV buffer (row stride 3072)
// ---------------------------------------------------------------------------
__global__ __launch_bounds__(256) void flash_kernel(const float* __restrict__ QKV,
                                                    float* __restrict__ O) {
    __shared__ float sK[64 * 64];
    __shared__ float sV[64 * 64];

    const int qb = blockIdx.x;
    const int h = blockIdx.y;
    const int b = blockIdx.z;
    const int kvh = h >> 2;

    const int tid = threadIdx.x;
    const int r = tid >> 2;
    const int dq = (tid & 3) << 4;
    const int qrow = qb * 64 + r;

    const float scale = 0.125f;

    float q[16];
    {
        const float* qp = QKV + ((size_t)(b * SS + qrow)) * QKVD + h * HD + dq;
#pragma unroll
        for (int c = 0; c < 4; c++) {
            float4 v = *(const float4*)(qp + c * 4);
            q[c * 4 + 0] = v.x * scale;
            q[c * 4 + 1] = v.y * scale;
            q[c * 4 + 2] = v.z * scale;
            q[c * 4 + 3] = v.w * scale;
        }
    }

    float m = -INFINITY, l = 0.0f;
    float o[16];
#pragma unroll
    for (int i = 0; i < 16; i++) o[i] = 0.0f;

    for (int j0 = 0; j0 <= qb * 64; j0 += 64) {
#pragma unroll
        for (int i = 0; i < 4; i++) {
            int idx = tid + i * 256;
            int row = idx >> 4;
            int cq = (idx & 15) << 2;
            const float* kp = QKV + ((size_t)(b * SS + j0 + row)) * QKVD + QDIM + kvh * HD + cq;
            const float* vp = kp + KVDIM;
            *(float4*)(sK + row * 64 + cq) = *(const float4*)kp;
            *(float4*)(sV + row * 64 + cq) = *(const float4*)vp;
        }
        __syncthreads();

        const bool full = (j0 + 63 <= qrow);
#pragma unroll 4
        for (int j = 0; j < 64; j++) {
            const float* kr = sK + j * 64 + dq;
            float4 k0 = *(const float4*)(kr);
            float4 k1 = *(const float4*)(kr + 4);
            float4 k2 = *(const float4*)(kr + 8);
            float4 k3 = *(const float4*)(kr + 12);
            float part = q[0] * k0.x + q[1] * k0.y + q[2] * k0.z + q[3] * k0.w;
            part += q[4] * k1.x + q[5] * k1.y + q[6] * k1.z + q[7] * k1.w;
            part += q[8] * k2.x + q[9] * k2.y + q[10] * k2.z + q[11] * k2.w;
            part += q[12] * k3.x + q[13] * k3.y + q[14] * k3.z + q[15] * k3.w;
            part += __shfl_xor_sync(0xffffffffu, part, 1);
            part += __shfl_xor_sync(0xffffffffu, part, 2);
            float s = part;

            if (full || (j0 + j <= qrow)) {
                if (s > m) {
                    float f = __expf(m - s);
                    m = s;
                    l *= f;
#pragma unroll
                    for (int i = 0; i < 16; i++) o[i] *= f;
                }
                float p = __expf(s - m);
                l += p;
                const float* vr = sV + j * 64 + dq;
                float4 v0 = *(const float4*)(vr);
                float4 v1 = *(const float4*)(vr + 4);
                float4 v2 = *(const float4*)(vr + 8);
                float4 v3 = *(const float4*)(vr + 12);
                o[0] += p * v0.x;  o[1] += p * v0.y;  o[2] += p * v0.z;  o[3] += p * v0.w;
                o[4] += p * v1.x;  o[5] += p * v1.y;  o[6] += p * v1.z;  o[7] += p * v1.w;
                o[8] += p * v2.x;  o[9] += p * v2.y;  o[10] += p * v2.z; o[11] += p * v2.w;
                o[12] += p * v3.x; o[13] += p * v3.y; o[14] += p * v3.z; o[15] += p * v3.w;
            }
        }
        __syncthreads();
    }

    float inv = 1.0f / l;
    float* op = O + ((size_t)(b * SS + qrow)) * QDIM + h * HD + dq;
#pragma unroll
    for (int c = 0; c < 4; c++) {
        float4 v = {o[c * 4 + 0] * inv, o[c * 4 + 1] * inv,
                    o[c * 4 + 2] * inv, o[c * 4 + 3] * inv};
        *(float4*)(op + c * 4) = v;
    }
}

// ---------------------------------------------------------------------------
// Launch
// ---------------------------------------------------------------------------
extern "C" void kernel_launch(void* const* d_in, const int* in_sizes, int n_in,
                              void* d_out, int out_size) {
    const float* x = (const float*)d_in[0];
    const float* wq = (const float*)d_in[1];
    const float* wk = (const float*)d_in[2];
    const float* wv = (const float*)d_in[3];
    const float* wo = (const float*)d_in[4];
    const float* cosT = (const float*)d_in[5];
    const float* sinT = (const float*)d_in[6];
    float* out = (float*)d_out;

    float *QKVp, *Op;
    __nv_bfloat16 *xh, *xl, *Wch, *Wcl, *Oh, *Ol, *Woh, *Wol;
    cudaGetSymbolAddress((void**)&QKVp, g_QKV);
    cudaGetSymbolAddress((void**)&Op, g_O);
    cudaGetSymbolAddress((void**)&xh, g_xh);
    cudaGetSymbolAddress((void**)&xl, g_xl);
    cudaGetSymbolAddress((void**)&Wch, g_Wch);
    cudaGetSymbolAddress((void**)&Wcl, g_Wcl);
    cudaGetSymbolAddress((void**)&Oh, g_Oh);
    cudaGetSymbolAddress((void**)&Ol, g_Ol);
    cudaGetSymbolAddress((void**)&Woh, g_Woh);
    cudaGetSymbolAddress((void**)&Wol, g_Wol);

    cudaFuncSetAttribute(gemm_tc, cudaFuncAttributeMaxDynamicSharedMemorySize,
                         GT_SMEM_TOTAL);

    // Splits
    {
        int n2 = MTOT * DM / 2;
        cvt2<<<(n2 + 255) / 256, 256>>>(x, xh, xl, n2);
        n2 = QDIM * DM / 2;
        cvt2<<<(n2 + 255) / 256, 256>>>(wq, Wch, Wcl, n2);
        n2 = KVDIM * DM / 2;
        cvt2<<<(n2 + 255) / 256, 256>>>(wk, Wch + (size_t)QDIM * DM, Wcl + (size_t)QDIM * DM, n2);
        cvt2<<<(n2 + 255) / 256, 256>>>(wv, Wch + (size_t)(QDIM + KVDIM) * DM,
                                        Wcl + (size_t)(QDIM + KVDIM) * DM, n2);
        n2 = DM * QDIM / 2;
        cvt2<<<(n2 + 255) / 256, 256>>>(wo, Woh, Wol, n2);
    }

    // Fused QKV projection: [4096,3072] = x @ [wq;wk;wv]^T
    gemm_tc<<<dim3(QKVD / 128, MTOT / 128), 256, GT_SMEM_TOTAL>>>(
        xh, xl, Wch, Wcl, QKVp, QKVD, DM);

    // RoPE on Q and K parts of the fused buffer
    {
        int totQ = MTOT * NH * 32;
        rope_kernel<<<(totQ + 255) / 256, 256>>>(QKVp, QKVD, 0, NH, cosT, sinT);
        int totK = MTOT * NKV * 32;
        rope_kernel<<<(totK + 255) / 256, 256>>>(QKVp, QKVD, QDIM, NKV, cosT, sinT);
    }

    // Attention
    flash_kernel<<<dim3(SS / 64, NH, BB), 256>>>(QKVp, Op);

    // Output projection: out = O @ wo^T
    {
        int n2 = MTOT * QDIM / 2;
        cvt2<<<(n2 + 255) / 256, 256>>>(Op, Oh, Ol, n2);
    }
    gemm_tc<<<dim3(DM / 128, MTOT / 128), 256, GT_SMEM_TOTAL>>>(
        Oh, Ol, Woh, Wol, out, DM, QDIM);
}

// round 4
// speedup vs baseline: 5.4174x; 4.1506x over previous
#include <cuda_runtime.h>
#include <cuda_bf16.h>
#include <math.h>
#include <stdint.h>

// Problem constants
#define BB 2
#define SS 2048
#define DM 2048
#define NH 32
#define NKV 8
#define HD 64
#define MTOT (BB * SS)          // 4096
#define QDIM (NH * HD)          // 2048
#define KVDIM (NKV * HD)        // 512
#define QKVD (QDIM + 2 * KVDIM) // 3072

// scale/log2 fold: (1/sqrt(64)) * log2(e)
#define QSCALE 0.18033688011112042f

// ---------------------------------------------------------------------------
// Scratch (device globals)
// ---------------------------------------------------------------------------
__device__ float g_QKV[MTOT * QKVD];            // 48 MB
__device__ __nv_bfloat16 g_xh[MTOT * DM];
__device__ __nv_bfloat16 g_xl[MTOT * DM];
__device__ __nv_bfloat16 g_Wch[QKVD * DM];
__device__ __nv_bfloat16 g_Wcl[QKVD * DM];
__device__ __nv_bfloat16 g_Woh[DM * QDIM];
__device__ __nv_bfloat16 g_Wol[DM * QDIM];
// per-head attention operand buffers [b][h][s][64]
__device__ __nv_bfloat16 g_Qh[BB * NH * SS * HD];
__device__ __nv_bfloat16 g_Ql[BB * NH * SS * HD];
__device__ __nv_bfloat16 g_Kh[BB * NKV * SS * HD];
__device__ __nv_bfloat16 g_Kl[BB * NKV * SS * HD];
__device__ __nv_bfloat16 g_Vh[BB * NKV * SS * HD];
__device__ __nv_bfloat16 g_Vl[BB * NKV * SS * HD];
// attention output split, [b][s][2048] (GEMM-ready)
__device__ __nv_bfloat16 g_Oh[MTOT * QDIM];
__device__ __nv_bfloat16 g_Ol[MTOT * QDIM];

// ---------------------------------------------------------------------------
// PTX helpers
// ---------------------------------------------------------------------------
__device__ __forceinline__ uint32_t smem_u32(const void* p) {
    uint32_t a;
    asm("{ .reg .u64 t; cvta.to.shared.u64 t, %1; cvt.u32.u64 %0, t; }" : "=r"(a) : "l"(p));
    return a;
}
__device__ __forceinline__ void ldsm4(uint32_t* r, uint32_t addr) {
    asm volatile("ldmatrix.sync.aligned.m8n8.x4.shared.b16 {%0,%1,%2,%3}, [%4];"
                 : "=r"(r[0]), "=r"(r[1]), "=r"(r[2]), "=r"(r[3]) : "r"(addr));
}
__device__ __forceinline__ void ldsm4t(uint32_t* r, uint32_t addr) {
    asm volatile("ldmatrix.sync.aligned.m8n8.x4.trans.shared.b16 {%0,%1,%2,%3}, [%4];"
                 : "=r"(r[0]), "=r"(r[1]), "=r"(r[2]), "=r"(r[3]) : "r"(addr));
}
__device__ __forceinline__ void mma16816(float* c, const uint32_t* a, const uint32_t* b) {
    asm volatile(
        "mma.sync.aligned.m16n8k16.row.col.f32.bf16.bf16.f32 "
        "{%0,%1,%2,%3}, {%4,%5,%6,%7}, {%8,%9}, {%0,%1,%2,%3};"
        : "+f"(c[0]), "+f"(c[1]), "+f"(c[2]), "+f"(c[3])
        : "r"(a[0]), "r"(a[1]), "r"(a[2]), "r"(a[3]), "r"(b[0]), "r"(b[1]));
}
__device__ __forceinline__ void cp_async16(uint32_t saddr, const void* gaddr) {
    asm volatile("cp.async.cg.shared.global [%0], [%1], 16;" :: "r"(saddr), "l"(gaddr));
}
__device__ __forceinline__ float ex2f(float x) {
    float y;
    asm("ex2.approx.ftz.f32 %0, %1;" : "=f"(y) : "f"(x));
    return y;
}
__device__ __forceinline__ void pack_split(float x, float y, uint32_t& hi, uint32_t& lo) {
    __nv_bfloat162 h = __floats2bfloat162_rn(x, y);
    float rx = x - __bfloat162float(h.x);
    float ry = y - __bfloat162float(h.y);
    __nv_bfloat162 l = __floats2bfloat162_rn(rx, ry);
    hi = *(uint32_t*)&h;
    lo = *(uint32_t*)&l;
}

// ---------------------------------------------------------------------------
// Split-bf16 HMMA GEMM (unchanged from R3; passed)
// ---------------------------------------------------------------------------
#define GT_ARR 10240
#define GT_STAGE (4 * GT_ARR)
#define GT_SMEM_TOTAL (2 * GT_STAGE)

__global__ __launch_bounds__(256, 1) void gemm_tc(
    const __nv_bfloat16* __restrict__ Ah, const __nv_bfloat16* __restrict__ Al,
    const __nv_bfloat16* __restrict__ Bh, const __nv_bfloat16* __restrict__ Bl,
    float* __restrict__ C, int NN, int K)
{
    extern __shared__ char smem[];
    const uint32_t sb = smem_u32(smem);
    const int tid = threadIdx.x;
    const int wid = tid >> 5;
    const int lane = tid & 31;
    const int wm = wid & 3;
    const int wn = wid >> 2;
    const int m0 = blockIdx.y * 128;
    const int n0 = blockIdx.x * 128;

    const __nv_bfloat16* const baseArr[4] = {
        Ah + (size_t)m0 * K, Al + (size_t)m0 * K,
        Bh + (size_t)n0 * K, Bl + (size_t)n0 * K};

    float acc[2][8][4];
#pragma unroll
    for (int i = 0; i < 2; i++)
#pragma unroll
        for (int j = 0; j < 8; j++)
#pragma unroll
            for (int q = 0; q < 4; q++) acc[i][j][q] = 0.0f;

    const int NC = K / 32;
    const int lg = lane >> 3;
    const int lr = lane & 7;

#define LOADSTAGE(cc) do {                                                     \
    const uint32_t stg = ((cc) & 1) ? GT_STAGE : 0;                            \
    const int k0 = (cc) * 32;                                                  \
    _Pragma("unroll")                                                          \
    for (int i = 0; i < 8; i++) {                                              \
        int gidx = tid + i * 256;                                              \
        int arr = gidx >> 9;                                                   \
        int wi = gidx & 511;                                                   \
        int row = wi >> 2;                                                     \
        int q = wi & 3;                                                        \
        const void* g = baseArr[arr] + (size_t)row * K + k0 + q * 8;           \
        uint32_t s = sb + stg + arr * GT_ARR + row * 80 + q * 16;              \
        cp_async16(s, g);                                                      \
    }                                                                          \
    asm volatile("cp.async.commit_group;" ::: "memory");                       \
} while (0)

    LOADSTAGE(0);

    for (int c = 0; c < NC; c++) {
        asm volatile("cp.async.wait_group 0;" ::: "memory");
        __syncthreads();
        if (c + 1 < NC) LOADSTAGE(c + 1);

        const uint32_t stg = sb + ((c & 1) ? GT_STAGE : 0);
        const uint32_t sAh = stg;
        const uint32_t sAl = stg + GT_ARR;
        const uint32_t sBh = stg + 2 * GT_ARR;
        const uint32_t sBl = stg + 3 * GT_ARR;

#pragma unroll
        for (int kk = 0; kk < 2; kk++) {
            const int kbyte = kk * 32;
            uint32_t fAh[2][4], fAl[2][4];
#pragma unroll
            for (int mt = 0; mt < 2; mt++) {
                int arow = wm * 32 + mt * 16 + (lg & 1) * 8 + lr;
                uint32_t aoff = (uint32_t)(arow * 80 + kbyte + (lg >> 1) * 16);
                ldsm4(fAh[mt], sAh + aoff);
                ldsm4(fAl[mt], sAl + aoff);
            }
#pragma unroll
            for (int np = 0; np < 4; np++) {
                int brow = wn * 64 + np * 16 + (lg >> 1) * 8 + lr;
                uint32_t boff = (uint32_t)(brow * 80 + kbyte + (lg & 1) * 16);
                uint32_t fBh[4], fBl[4];
                ldsm4(fBh, sBh + boff);
                ldsm4(fBl, sBl + boff);
#pragma unroll
                for (int mt = 0; mt < 2; mt++) {
                    mma16816(acc[mt][np * 2], fAh[mt], fBh);
                    mma16816(acc[mt][np * 2], fAl[mt], fBh);
                    mma16816(acc[mt][np * 2], fAh[mt], fBl);
                    mma16816(acc[mt][np * 2 + 1], fAh[mt], fBh + 2);
                    mma16816(acc[mt][np * 2 + 1], fAl[mt], fBh + 2);
                    mma16816(acc[mt][np * 2 + 1], fAh[mt], fBl + 2);
                }
            }
        }
        __syncthreads();
    }

#pragma unroll
    for (int mt = 0; mt < 2; mt++) {
        int row0 = m0 + wm * 32 + mt * 16 + (lane >> 2);
#pragma unroll
        for (int nt = 0; nt < 8; nt++) {
            int col = n0 + wn * 64 + nt * 8 + (lane & 3) * 2;
            float2 v0 = {acc[mt][nt][0], acc[mt][nt][1]};
            float2 v1 = {acc[mt][nt][2], acc[mt][nt][3]};
            *(float2*)(C + (size_t)row0 * NN + col) = v0;
            *(float2*)(C + (size_t)(row0 + 8) * NN + col) = v1;
        }
    }
#undef LOADSTAGE
}

// ---------------------------------------------------------------------------
// fp32 -> bf16 hi/lo split (for x and weights)
// ---------------------------------------------------------------------------
__global__ void cvt2(const float* __restrict__ in, __nv_bfloat16* __restrict__ hi,
                     __nv_bfloat16* __restrict__ lo, int n2) {
    int i = blockIdx.x * blockDim.x + threadIdx.x;
    if (i >= n2) return;
    float2 v = ((const float2*)in)[i];
    uint32_t h, l;
    pack_split(v.x, v.y, h, l);
    ((uint32_t*)hi)[i] = h;
    ((uint32_t*)lo)[i] = l;
}

// ---------------------------------------------------------------------------
// RoPE + split + relayout for Q and K (Q gets QSCALE folded in)
// ---------------------------------------------------------------------------
__global__ void rope_split(const float* __restrict__ QKV,
                           const float* __restrict__ cosT, const float* __restrict__ sinT,
                           __nv_bfloat16* __restrict__ Qh, __nv_bfloat16* __restrict__ Ql,
                           __nv_bfloat16* __restrict__ Kh, __nv_bfloat16* __restrict__ Kl) {
    int idx = blockIdx.x * blockDim.x + threadIdx.x;
    const int TQ = MTOT * NH * 32;
    const int TK = MTOT * NKV * 32;
    if (idx >= TQ + TK) return;
    bool isQ = idx < TQ;
    int id = isQ ? idx : idx - TQ;
    int nheads = isQ ? NH : NKV;
    int d = id & 31;
    int h = (id >> 5) % nheads;
    int m = id / (32 * nheads);
    int s = m & (SS - 1);
    int b = m >> 11;  // m / SS

    const float* p = QKV + (size_t)m * QKVD + (isQ ? 0 : QDIM) + h * 64 + d;
    float a = p[0];
    float bb = p[32];
    int ci = s * 32 + (d >> 1);
    float c1 = cosT[ci], s1 = sinT[ci];
    float c2 = cosT[ci + 16], s2 = sinT[ci + 16];
    float ra = a * c1 - bb * s1;
    float rb = bb * c2 + a * s2;
    if (isQ) { ra *= QSCALE; rb *= QSCALE; }

    size_t o = ((size_t)(b * nheads + h) * SS + s) * 64 + d;
    __nv_bfloat16* dh = isQ ? Qh : Kh;
    __nv_bfloat16* dl = isQ ? Ql : Kl;
    __nv_bfloat16 ha = __float2bfloat16(ra);
    __nv_bfloat16 hb = __float2bfloat16(rb);
    dh[o] = ha;       dh[o + 32] = hb;
    dl[o] = __float2bfloat16(ra - __bfloat162float(ha));
    dl[o + 32] = __float2bfloat16(rb - __bfloat162float(hb));
}

// V: split + relayout only
__global__ void v_split(const float* __restrict__ QKV,
                        __nv_bfloat16* __restrict__ Vh, __nv_bfloat16* __restrict__ Vl) {
    int u = blockIdx.x * blockDim.x + threadIdx.x;
    if (u >= MTOT * NKV * 32) return;
    int d2 = u & 31;
    int kvh = (u >> 5) & 7;
    int m = u >> 8;
    int s = m & (SS - 1);
    int b = m >> 11;
    float2 v = *(const float2*)(QKV + (size_t)m * QKVD + QDIM + KVDIM + kvh * 64 + 2 * d2);
    uint32_t h, l;
    pack_split(v.x, v.y, h, l);
    size_t o = (((size_t)(b * NKV + kvh) * SS + s) * 64 + 2 * d2) >> 1;  // in u32 units
    ((uint32_t*)Vh)[o] = h;
    ((uint32_t*)Vl)[o] = l;
}

// ---------------------------------------------------------------------------
// MMA flash attention (causal, GQA). grid (S/128, NH, BB), 256 threads.
// Split-bf16 on both QK^T and PV. Softmax in base-2 (scale folded into Q).
// ---------------------------------------------------------------------------
#define FSTRB 144                    // smem row stride bytes (72 bf16)
#define FQ_BYTES (128 * FSTRB)       // 18432 per Q array
#define FARR (64 * FSTRB)            // 9216 per K/V array
#define FKV0 (2 * FQ_BYTES)          // 36864
#define FSTAGE (4 * FARR)            // 36864
#define FL_SMEM (FKV0 + 2 * FSTAGE)  // 110592

__global__ __launch_bounds__(256, 1) void flash_mma(
    const __nv_bfloat16* __restrict__ Qh, const __nv_bfloat16* __restrict__ Ql,
    const __nv_bfloat16* __restrict__ Kh, const __nv_bfloat16* __restrict__ Kl,
    const __nv_bfloat16* __restrict__ Vh, const __nv_bfloat16* __restrict__ Vl,
    __nv_bfloat16* __restrict__ Oh, __nv_bfloat16* __restrict__ Ol)
{
    extern __shared__ char sm[];
    const uint32_t sb = smem_u32(sm);
    const int tid = threadIdx.x;
    const int lane = tid & 31;
    const int wm = tid >> 5;       // warp 0..7 -> rows wm*16
    const int qb = blockIdx.x;
    const int h = blockIdx.y;
    const int b = blockIdx.z;
    const int kvh = h >> 2;
    const int nkt = 2 * (qb + 1);

    const size_t qg = ((size_t)(b * NH + h) * SS + qb * 128) * 64;
    const size_t kg = ((size_t)(b * NKV + kvh) * SS) * 64;

    // ---- Q load (group 0) ----
    {
        const __nv_bfloat16* qarr[2] = {Qh + qg, Ql + qg};
#pragma unroll
        for (int i = 0; i < 8; i++) {
            int g = tid + i * 256;      // 0..2047
            int arr = g >> 10;
            int w = g & 1023;
            int row = w >> 3;
            int ch = w & 7;
            cp_async16(sb + arr * FQ_BYTES + row * FSTRB + ch * 16,
                       qarr[arr] + (size_t)row * 64 + ch * 8);
        }
        asm volatile("cp.async.commit_group;" ::: "memory");
    }

#define LOADKV(kt_) do {                                                        \
    int j0_ = (kt_) * 64;                                                       \
    uint32_t stg_ = sb + FKV0 + ((kt_) & 1) * FSTAGE;                           \
    const __nv_bfloat16* karr[4] = {                                            \
        Kh + kg + (size_t)j0_ * 64, Kl + kg + (size_t)j0_ * 64,                 \
        Vh + kg + (size_t)j0_ * 64, Vl + kg + (size_t)j0_ * 64};                \
    _Pragma("unroll")                                                           \
    for (int i = 0; i < 8; i++) {                                               \
        int g = tid + i * 256;                                                  \
        int arr = g >> 9;                                                       \
        int w = g & 511;                                                        \
        int row = w >> 3;                                                       \
        int ch = w & 7;                                                         \
        cp_async16(stg_ + arr * FARR + row * FSTRB + ch * 16,                   \
                   karr[arr] + (size_t)row * 64 + ch * 8);                      \
    }                                                                           \
    asm volatile("cp.async.commit_group;" ::: "memory");                        \
} while (0)

    LOADKV(0);
    if (nkt > 1) LOADKV(1);

    // wait for Q + KV0 (leave at most 1 group (KV1) in flight)
    if (nkt > 1) { asm volatile("cp.async.wait_group 1;" ::: "memory"); }
    else         { asm volatile("cp.async.wait_group 0;" ::: "memory"); }
    __syncthreads();

    // ---- Q fragments, register-resident for whole kernel ----
    uint32_t qfh[4][4], qfl[4][4];
#pragma unroll
    for (int kk = 0; kk < 4; kk++) {
        uint32_t addr = sb + (uint32_t)((wm * 16 + (lane & 15)) * FSTRB
                                        + kk * 32 + (lane >> 4) * 16);
        ldsm4(qfh[kk], addr);
        ldsm4(qfl[kk], addr + FQ_BYTES);
    }

    float co[8][4];
#pragma unroll
    for (int i = 0; i < 8; i++)
#pragma unroll
        for (int j = 0; j < 4; j++) co[i][j] = 0.0f;
    float m0 = -1e30f, m1 = -1e30f, l0 = 0.0f, l1 = 0.0f;

    const int lg = lane >> 3;
    const int lr = lane & 7;
    const int qr0 = qb * 128 + wm * 16 + (lane >> 2);

    for (int kt = 0; kt < nkt; kt++) {
        if (kt > 0) {
            if (kt + 1 < nkt) { asm volatile("cp.async.wait_group 1;" ::: "memory"); }
            else              { asm volatile("cp.async.wait_group 0;" ::: "memory"); }
            __syncthreads();
        }
        const uint32_t sKh = sb + FKV0 + (kt & 1) * FSTAGE;
        const uint32_t sKl = sKh + FARR;
        const uint32_t sVh = sKh + 2 * FARR;
        const uint32_t sVl = sKh + 3 * FARR;

        // ---- S = Q K^T ----
        float cs[8][4];
#pragma unroll
        for (int i = 0; i < 8; i++)
#pragma unroll
            for (int j = 0; j < 4; j++) cs[i][j] = 0.0f;

#pragma unroll
        for (int kk = 0; kk < 4; kk++) {
#pragma unroll
            for (int ng = 0; ng < 4; ng++) {
                uint32_t boff = (uint32_t)((ng * 16 + (lg >> 1) * 8 + lr) * FSTRB
                                           + kk * 32 + (lg & 1) * 16);
                uint32_t bh[4], bl[4];
                ldsm4(bh, sKh + boff);
                ldsm4(bl, sKl + boff);
                mma16816(cs[ng * 2], qfh[kk], bh);
                mma16816(cs[ng * 2], qfl[kk], bh);
                mma16816(cs[ng * 2], qfh[kk], bl);
                mma16816(cs[ng * 2 + 1], qfh[kk], bh + 2);
                mma16816(cs[ng * 2 + 1], qfl[kk], bh + 2);
                mma16816(cs[ng * 2 + 1], qfh[kk], bl + 2);
            }
        }

        // ---- causal mask (only the 2 diagonal tiles need it) ----
        if (kt >= nkt - 2) {
            int gcol0 = kt * 64 + (lane & 3) * 2;
#pragma unroll
            for (int n = 0; n < 8; n++) {
#pragma unroll
                for (int t = 0; t < 2; t++) {
                    int col = gcol0 + n * 8 + t;
                    if (col > qr0) cs[n][t] = -1e30f;
                    if (col > qr0 + 8) cs[n][t + 2] = -1e30f;
                }
            }
        }

        // ---- online softmax (base-2) ----
        float mx0 = -1e30f, mx1 = -1e30f;
#pragma unroll
        for (int n = 0; n < 8; n++) {
            mx0 = fmaxf(mx0, fmaxf(cs[n][0], cs[n][1]));
            mx1 = fmaxf(mx1, fmaxf(cs[n][2], cs[n][3]));
        }
        mx0 = fmaxf(mx0, __shfl_xor_sync(0xffffffffu, mx0, 1));
        mx0 = fmaxf(mx0, __shfl_xor_sync(0xffffffffu, mx0, 2));
        mx1 = fmaxf(mx1, __shfl_xor_sync(0xffffffffu, mx1, 1));
        mx1 = fmaxf(mx1, __shfl_xor_sync(0xffffffffu, mx1, 2));
        float nm0 = fmaxf(m0, mx0);
        float nm1 = fmaxf(m1, mx1);
        float f0 = ex2f(m0 - nm0);
        float f1 = ex2f(m1 - nm1);
        float s0 = 0.0f, s1 = 0.0f;
#pragma unroll
        for (int n = 0; n < 8; n++) {
            cs[n][0] = ex2f(cs[n][0] - nm0); s0 += cs[n][0];
            cs[n][1] = ex2f(cs[n][1] - nm0); s0 += cs[n][1];
            cs[n][2] = ex2f(cs[n][2] - nm1); s1 += cs[n][2];
            cs[n][3] = ex2f(cs[n][3] - nm1); s1 += cs[n][3];
        }
        l0 = l0 * f0 + s0;
        l1 = l1 * f1 + s1;
#pragma unroll
        for (int n = 0; n < 8; n++) {
            co[n][0] *= f0; co[n][1] *= f0;
            co[n][2] *= f1; co[n][3] *= f1;
        }
        m0 = nm0; m1 = nm1;

        // ---- O += P V  (split P, split V) ----
#pragma unroll
        for (int kk = 0; kk < 4; kk++) {
            uint32_t ah[4], al[4];
            pack_split(cs[2 * kk][0], cs[2 * kk][1], ah[0], al[0]);
            pack_split(cs[2 * kk][2], cs[2 * kk][3], ah[1], al[1]);
            pack_split(cs[2 * kk + 1][0], cs[2 * kk + 1][1], ah[2], al[2]);
            pack_split(cs[2 * kk + 1][2], cs[2 * kk + 1][3], ah[3], al[3]);
#pragma unroll
            for (int ng = 0; ng < 4; ng++) {
                uint32_t vaddr = (uint32_t)((kk * 16 + (lane & 15)) * FSTRB
                                            + (ng * 16 + (lane >> 4) * 8) * 2);
                uint32_t vh[4], vl[4];
                ldsm4t(vh, sVh + vaddr);
                ldsm4t(vl, sVl + vaddr);
                mma16816(co[ng * 2], ah, vh);
                mma16816(co[ng * 2], al, vh);
                mma16816(co[ng * 2], ah, vl);
                mma16816(co[ng * 2 + 1], ah, vh + 2);
                mma16816(co[ng * 2 + 1], al, vh + 2);
                mma16816(co[ng * 2 + 1], ah, vl + 2);
            }
        }

        __syncthreads();                // all warps done with stage before refill
        if (kt + 2 < nkt) LOADKV(kt + 2);
    }

    // ---- epilogue: normalize, split to bf16 hi/lo, write [b][s][2048] ----
    l0 += __shfl_xor_sync(0xffffffffu, l0, 1);
    l0 += __shfl_xor_sync(0xffffffffu, l0, 2);
    l1 += __shfl_xor_sync(0xffffffffu, l1, 1);
    l1 += __shfl_xor_sync(0xffffffffu, l1, 2);
    float inv0 = 1.0f / l0;
    float inv1 = 1.0f / l1;

    int srow = qb * 128 + wm * 16 + (lane >> 2);
    size_t base0 = ((size_t)(b * SS) + srow) * QDIM + h * 64 + (lane & 3) * 2;
    size_t base1 = base0 + (size_t)8 * QDIM;
#pragma unroll
    for (int nd = 0; nd < 8; nd++) {
        uint32_t hh, ll;
        pack_split(co[nd][0] * inv0, co[nd][1] * inv0, hh, ll);
        *(uint32_t*)(Oh + base0 + nd * 8) = hh;
        *(uint32_t*)(Ol + base0 + nd * 8) = ll;
        pack_split(co[nd][2] * inv1, co[nd][3] * inv1, hh, ll);
        *(uint32_t*)(Oh + base1 + nd * 8) = hh;
        *(uint32_t*)(Ol + base1 + nd * 8) = ll;
    }
#undef LOADKV
}

// ---------------------------------------------------------------------------
// Launch
// ---------------------------------------------------------------------------
extern "C" void kernel_launch(void* const* d_in, const int* in_sizes, int n_in,
                              void* d_out, int out_size) {
    const float* x = (const float*)d_in[0];
    const float* wq = (const float*)d_in[1];
    const float* wk = (const float*)d_in[2];
    const float* wv = (const float*)d_in[3];
    const float* wo = (const float*)d_in[4];
    const float* cosT = (const float*)d_in[5];
    const float* sinT = (const float*)d_in[6];
    float* out = (float*)d_out;

    float* QKVp;
    __nv_bfloat16 *xh, *xl, *Wch, *Wcl, *Woh, *Wol;
    __nv_bfloat16 *Qh, *Ql, *Kh, *Kl, *Vh, *Vl, *Oh, *Ol;
    cudaGetSymbolAddress((void**)&QKVp, g_QKV);
    cudaGetSymbolAddress((void**)&xh, g_xh);
    cudaGetSymbolAddress((void**)&xl, g_xl);
    cudaGetSymbolAddress((void**)&Wch, g_Wch);
    cudaGetSymbolAddress((void**)&Wcl, g_Wcl);
    cudaGetSymbolAddress((void**)&Woh, g_Woh);
    cudaGetSymbolAddress((void**)&Wol, g_Wol);
    cudaGetSymbolAddress((void**)&Qh, g_Qh);
    cudaGetSymbolAddress((void**)&Ql, g_Ql);
    cudaGetSymbolAddress((void**)&Kh, g_Kh);
    cudaGetSymbolAddress((void**)&Kl, g_Kl);
    cudaGetSymbolAddress((void**)&Vh, g_Vh);
    cudaGetSymbolAddress((void**)&Vl, g_Vl);
    cudaGetSymbolAddress((void**)&Oh, g_Oh);
    cudaGetSymbolAddress((void**)&Ol, g_Ol);

    cudaFuncSetAttribute(gemm_tc, cudaFuncAttributeMaxDynamicSharedMemorySize,
                         GT_SMEM_TOTAL);
    cudaFuncSetAttribute(flash_mma, cudaFuncAttributeMaxDynamicSharedMemorySize,
                         FL_SMEM);

    // Splits of inputs
    {
        int n2 = MTOT * DM / 2;
        cvt2<<<(n2 + 255) / 256, 256>>>(x, xh, xl, n2);
        n2 = QDIM * DM / 2;
        cvt2<<<(n2 + 255) / 256, 256>>>(wq, Wch, Wcl, n2);
        n2 = KVDIM * DM / 2;
        cvt2<<<(n2 + 255) / 256, 256>>>(wk, Wch + (size_t)QDIM * DM, Wcl + (size_t)QDIM * DM, n2);
        cvt2<<<(n2 + 255) / 256, 256>>>(wv, Wch + (size_t)(QDIM + KVDIM) * DM,
                                        Wcl + (size_t)(QDIM + KVDIM) * DM, n2);
        n2 = DM * QDIM / 2;
        cvt2<<<(n2 + 255) / 256, 256>>>(wo, Woh, Wol, n2);
    }

    // Fused QKV projection
    gemm_tc<<<dim3(QKVD / 128, MTOT / 128), 256, GT_SMEM_TOTAL>>>(
        xh, xl, Wch, Wcl, QKVp, QKVD, DM);

    // RoPE + split + relayout
    {
        int tot = MTOT * (NH + NKV) * 32;
        rope_split<<<(tot + 255) / 256, 256>>>(QKVp, cosT, sinT, Qh, Ql, Kh, Kl);
        int tv = MTOT * NKV * 32;
        v_split<<<(tv + 255) / 256, 256>>>(QKVp, Vh, Vl);
    }

    // Attention (writes split O directly)
    flash_mma<<<dim3(SS / 128, NH, BB), 256, FL_SMEM>>>(Qh, Ql, Kh, Kl, Vh, Vl, Oh, Ol);

    // Output projection
    gemm_tc<<<dim3(DM / 128, MTOT / 128), 256, GT_SMEM_TOTAL>>>(
        Oh, Ol, Woh, Wol, out, DM, QDIM);
}

// round 5
// speedup vs baseline: 5.5803x; 1.0301x over previous
#include <cuda_runtime.h>
#include <cuda_bf16.h>
#include <cuda_fp16.h>
#include <math.h>
#include <stdint.h>

// Problem constants
#define BB 2
#define SS 2048
#define DM 2048
#define NH 32
#define NKV 8
#define HD 64
#define MTOT (BB * SS)          // 4096
#define QDIM (NH * HD)          // 2048
#define KVDIM (NKV * HD)        // 512
#define QKVD (QDIM + 2 * KVDIM) // 3072

// scale/log2 fold: (1/sqrt(64)) * log2(e)
#define QSCALE 0.18033688011112042f

// ---------------------------------------------------------------------------
// Scratch (device globals)
// ---------------------------------------------------------------------------
__device__ float g_QKV[MTOT * QKVD];            // 48 MB
__device__ __nv_bfloat16 g_xh[MTOT * DM];
__device__ __nv_bfloat16 g_xl[MTOT * DM];
__device__ __nv_bfloat16 g_Wch[QKVD * DM];
__device__ __nv_bfloat16 g_Wcl[QKVD * DM];
__device__ __nv_bfloat16 g_Woh[DM * QDIM];
__device__ __nv_bfloat16 g_Wol[DM * QDIM];
// per-head attention operand buffers [b][h][s][64]
__device__ __nv_bfloat16 g_Qh[BB * NH * SS * HD];
__device__ __nv_bfloat16 g_Ql[BB * NH * SS * HD];
__device__ __nv_bfloat16 g_Kh[BB * NKV * SS * HD];
__device__ __nv_bfloat16 g_Kl[BB * NKV * SS * HD];
__device__ __half g_Vh[BB * NKV * SS * HD];       // V now fp16 split
__device__ __half g_Vl[BB * NKV * SS * HD];
// attention output split, [b][s][2048] (GEMM-ready)
__device__ __nv_bfloat16 g_Oh[MTOT * QDIM];
__device__ __nv_bfloat16 g_Ol[MTOT * QDIM];

// ---------------------------------------------------------------------------
// PTX helpers
// ---------------------------------------------------------------------------
__device__ __forceinline__ uint32_t smem_u32(const void* p) {
    uint32_t a;
    asm("{ .reg .u64 t; cvta.to.shared.u64 t, %1; cvt.u32.u64 %0, t; }" : "=r"(a) : "l"(p));
    return a;
}
__device__ __forceinline__ void ldsm4(uint32_t* r, uint32_t addr) {
    asm volatile("ldmatrix.sync.aligned.m8n8.x4.shared.b16 {%0,%1,%2,%3}, [%4];"
                 : "=r"(r[0]), "=r"(r[1]), "=r"(r[2]), "=r"(r[3]) : "r"(addr));
}
__device__ __forceinline__ void ldsm4t(uint32_t* r, uint32_t addr) {
    asm volatile("ldmatrix.sync.aligned.m8n8.x4.trans.shared.b16 {%0,%1,%2,%3}, [%4];"
                 : "=r"(r[0]), "=r"(r[1]), "=r"(r[2]), "=r"(r[3]) : "r"(addr));
}
__device__ __forceinline__ void ldsm2t(uint32_t* r, uint32_t addr) {
    asm volatile("ldmatrix.sync.aligned.m8n8.x2.trans.shared.b16 {%0,%1}, [%2];"
                 : "=r"(r[0]), "=r"(r[1]) : "r"(addr));
}
__device__ __forceinline__ void mma16816(float* c, const uint32_t* a, const uint32_t* b) {
    asm volatile(
        "mma.sync.aligned.m16n8k16.row.col.f32.bf16.bf16.f32 "
        "{%0,%1,%2,%3}, {%4,%5,%6,%7}, {%8,%9}, {%0,%1,%2,%3};"
        : "+f"(c[0]), "+f"(c[1]), "+f"(c[2]), "+f"(c[3])
        : "r"(a[0]), "r"(a[1]), "r"(a[2]), "r"(a[3]), "r"(b[0]), "r"(b[1]));
}
__device__ __forceinline__ void mma16816h(float* c, const uint32_t* a, const uint32_t* b) {
    asm volatile(
        "mma.sync.aligned.m16n8k16.row.col.f32.f16.f16.f32 "
        "{%0,%1,%2,%3}, {%4,%5,%6,%7}, {%8,%9}, {%0,%1,%2,%3};"
        : "+f"(c[0]), "+f"(c[1]), "+f"(c[2]), "+f"(c[3])
        : "r"(a[0]), "r"(a[1]), "r"(a[2]), "r"(a[3]), "r"(b[0]), "r"(b[1]));
}
__device__ __forceinline__ void cp_async16(uint32_t saddr, const void* gaddr) {
    asm volatile("cp.async.cg.shared.global [%0], [%1], 16;" :: "r"(saddr), "l"(gaddr));
}
__device__ __forceinline__ float ex2f(float x) {
    float y;
    asm("ex2.approx.ftz.f32 %0, %1;" : "=f"(y) : "f"(x));
    return y;
}
__device__ __forceinline__ uint32_t pack_f16x2(float lo, float hi) {
    uint32_t d;  // first src operand -> high half
    asm("cvt.rn.f16x2.f32 %0, %1, %2;" : "=r"(d) : "f"(hi), "f"(lo));
    return d;
}
__device__ __forceinline__ uint32_t ex2_f16x2(uint32_t x) {
    uint32_t y;
    asm("ex2.approx.f16x2 %0, %1;" : "=r"(y) : "r"(x));
    return y;
}
__device__ __forceinline__ void pack_split(float x, float y, uint32_t& hi, uint32_t& lo) {
    __nv_bfloat162 h = __floats2bfloat162_rn(x, y);
    float rx = x - __bfloat162float(h.x);
    float ry = y - __bfloat162float(h.y);
    __nv_bfloat162 l = __floats2bfloat162_rn(rx, ry);
    hi = *(uint32_t*)&h;
    lo = *(uint32_t*)&l;
}

// ---------------------------------------------------------------------------
// Split-bf16 HMMA GEMM (unchanged; passed R3/R4)
// ---------------------------------------------------------------------------
#define GT_ARR 10240
#define GT_STAGE (4 * GT_ARR)
#define GT_SMEM_TOTAL (2 * GT_STAGE)

__global__ __launch_bounds__(256, 1) void gemm_tc(
    const __nv_bfloat16* __restrict__ Ah, const __nv_bfloat16* __restrict__ Al,
    const __nv_bfloat16* __restrict__ Bh, const __nv_bfloat16* __restrict__ Bl,
    float* __restrict__ C, int NN, int K)
{
    extern __shared__ char smem[];
    const uint32_t sb = smem_u32(smem);
    const int tid = threadIdx.x;
    const int wid = tid >> 5;
    const int lane = tid & 31;
    const int wm = wid & 3;
    const int wn = wid >> 2;
    const int m0 = blockIdx.y * 128;
    const int n0 = blockIdx.x * 128;

    const __nv_bfloat16* const baseArr[4] = {
        Ah + (size_t)m0 * K, Al + (size_t)m0 * K,
        Bh + (size_t)n0 * K, Bl + (size_t)n0 * K};

    float acc[2][8][4];
#pragma unroll
    for (int i = 0; i < 2; i++)
#pragma unroll
        for (int j = 0; j < 8; j++)
#pragma unroll
            for (int q = 0; q < 4; q++) acc[i][j][q] = 0.0f;

    const int NC = K / 32;
    const int lg = lane >> 3;
    const int lr = lane & 7;

#define LOADSTAGE(cc) do {                                                     \
    const uint32_t stg = ((cc) & 1) ? GT_STAGE : 0;                            \
    const int k0 = (cc) * 32;                                                  \
    _Pragma("unroll")                                                          \
    for (int i = 0; i < 8; i++) {                                              \
        int gidx = tid + i * 256;                                              \
        int arr = gidx >> 9;                                                   \
        int wi = gidx & 511;                                                   \
        int row = wi >> 2;                                                     \
        int q = wi & 3;                                                        \
        const void* g = baseArr[arr] + (size_t)row * K + k0 + q * 8;           \
        uint32_t s = sb + stg + arr * GT_ARR + row * 80 + q * 16;              \
        cp_async16(s, g);                                                      \
    }                                                                          \
    asm volatile("cp.async.commit_group;" ::: "memory");                       \
} while (0)

    LOADSTAGE(0);

    for (int c = 0; c < NC; c++) {
        asm volatile("cp.async.wait_group 0;" ::: "memory");
        __syncthreads();
        if (c + 1 < NC) LOADSTAGE(c + 1);

        const uint32_t stg = sb + ((c & 1) ? GT_STAGE : 0);
        const uint32_t sAh = stg;
        const uint32_t sAl = stg + GT_ARR;
        const uint32_t sBh = stg + 2 * GT_ARR;
        const uint32_t sBl = stg + 3 * GT_ARR;

#pragma unroll
        for (int kk = 0; kk < 2; kk++) {
            const int kbyte = kk * 32;
            uint32_t fAh[2][4], fAl[2][4];
#pragma unroll
            for (int mt = 0; mt < 2; mt++) {
                int arow = wm * 32 + mt * 16 + (lg & 1) * 8 + lr;
                uint32_t aoff = (uint32_t)(arow * 80 + kbyte + (lg >> 1) * 16);
                ldsm4(fAh[mt], sAh + aoff);
                ldsm4(fAl[mt], sAl + aoff);
            }
#pragma unroll
            for (int np = 0; np < 4; np++) {
                int brow = wn * 64 + np * 16 + (lg >> 1) * 8 + lr;
                uint32_t boff = (uint32_t)(brow * 80 + kbyte + (lg & 1) * 16);
                uint32_t fBh[4], fBl[4];
                ldsm4(fBh, sBh + boff);
                ldsm4(fBl, sBl + boff);
#pragma unroll
                for (int mt = 0; mt < 2; mt++) {
                    mma16816(acc[mt][np * 2], fAh[mt], fBh);
                    mma16816(acc[mt][np * 2], fAl[mt], fBh);
                    mma16816(acc[mt][np * 2], fAh[mt], fBl);
                    mma16816(acc[mt][np * 2 + 1], fAh[mt], fBh + 2);
                    mma16816(acc[mt][np * 2 + 1], fAl[mt], fBh + 2);
                    mma16816(acc[mt][np * 2 + 1], fAh[mt], fBl + 2);
                }
            }
        }
        __syncthreads();
    }

#pragma unroll
    for (int mt = 0; mt < 2; mt++) {
        int row0 = m0 + wm * 32 + mt * 16 + (lane >> 2);
#pragma unroll
        for (int nt = 0; nt < 8; nt++) {
            int col = n0 + wn * 64 + nt * 8 + (lane & 3) * 2;
            float2 v0 = {acc[mt][nt][0], acc[mt][nt][1]};
            float2 v1 = {acc[mt][nt][2], acc[mt][nt][3]};
            *(float2*)(C + (size_t)row0 * NN + col) = v0;
            *(float2*)(C + (size_t)(row0 + 8) * NN + col) = v1;
        }
    }
#undef LOADSTAGE
}

// ---------------------------------------------------------------------------
// fp32 -> bf16 hi/lo split
// ---------------------------------------------------------------------------
__global__ void cvt2(const float* __restrict__ in, __nv_bfloat16* __restrict__ hi,
                     __nv_bfloat16* __restrict__ lo, int n2) {
    int i = blockIdx.x * blockDim.x + threadIdx.x;
    if (i >= n2) return;
    float2 v = ((const float2*)in)[i];
    uint32_t h, l;
    pack_split(v.x, v.y, h, l);
    ((uint32_t*)hi)[i] = h;
    ((uint32_t*)lo)[i] = l;
}

// ---------------------------------------------------------------------------
// RoPE + split + relayout for Q and K (Q gets QSCALE folded in)
// ---------------------------------------------------------------------------
__global__ void rope_split(const float* __restrict__ QKV,
                           const float* __restrict__ cosT, const float* __restrict__ sinT,
                           __nv_bfloat16* __restrict__ Qh, __nv_bfloat16* __restrict__ Ql,
                           __nv_bfloat16* __restrict__ Kh, __nv_bfloat16* __restrict__ Kl) {
    int idx = blockIdx.x * blockDim.x + threadIdx.x;
    const int TQ = MTOT * NH * 32;
    const int TK = MTOT * NKV * 32;
    if (idx >= TQ + TK) return;
    bool isQ = idx < TQ;
    int id = isQ ? idx : idx - TQ;
    int nheads = isQ ? NH : NKV;
    int d = id & 31;
    int h = (id >> 5) % nheads;
    int m = id / (32 * nheads);
    int s = m & (SS - 1);
    int b = m >> 11;

    const float* p = QKV + (size_t)m * QKVD + (isQ ? 0 : QDIM) + h * 64 + d;
    float a = p[0];
    float bb = p[32];
    int ci = s * 32 + (d >> 1);
    float c1 = cosT[ci], s1 = sinT[ci];
    float c2 = cosT[ci + 16], s2 = sinT[ci + 16];
    float ra = a * c1 - bb * s1;
    float rb = bb * c2 + a * s2;
    if (isQ) { ra *= QSCALE; rb *= QSCALE; }

    size_t o = ((size_t)(b * nheads + h) * SS + s) * 64 + d;
    __nv_bfloat16* dh = isQ ? Qh : Kh;
    __nv_bfloat16* dl = isQ ? Ql : Kl;
    __nv_bfloat16 ha = __float2bfloat16(ra);
    __nv_bfloat16 hb = __float2bfloat16(rb);
    dh[o] = ha;       dh[o + 32] = hb;
    dl[o] = __float2bfloat16(ra - __bfloat162float(ha));
    dl[o + 32] = __float2bfloat16(rb - __bfloat162float(hb));
}

// V: fp16 hi/lo split + relayout
__global__ void v_split(const float* __restrict__ QKV,
                        __half* __restrict__ Vh, __half* __restrict__ Vl) {
    int u = blockIdx.x * blockDim.x + threadIdx.x;
    if (u >= MTOT * NKV * 32) return;
    int d2 = u & 31;
    int kvh = (u >> 5) & 7;
    int m = u >> 8;
    int s = m & (SS - 1);
    int b = m >> 11;
    float2 v = *(const float2*)(QKV + (size_t)m * QKVD + QDIM + KVDIM + kvh * 64 + 2 * d2);
    __half h0 = __float2half_rn(v.x);
    __half h1 = __float2half_rn(v.y);
    __half2 hh; hh.x = h0; hh.y = h1;
    __half2 ll;
    ll.x = __float2half_rn(v.x - __half2float(h0));
    ll.y = __float2half_rn(v.y - __half2float(h1));
    size_t o = (((size_t)(b * NKV + kvh) * SS + s) * 64 + 2 * d2) >> 1;
    ((__half2*)Vh)[o] = hh;
    ((__half2*)Vl)[o] = ll;
}

// ---------------------------------------------------------------------------
// MMA flash attention v2: fp16 P (f16x2 exp), fp16 split V, ones-column sums.
// grid (S/128, NH, BB), 256 threads.
// ---------------------------------------------------------------------------
#define FSTRB 144
#define FQ_BYTES (128 * FSTRB)
#define FARR (64 * FSTRB)
#define FKV0 (2 * FQ_BYTES)
#define FSTAGE (4 * FARR)
#define FL_SMEM (FKV0 + 2 * FSTAGE)

__global__ __launch_bounds__(256, 1) void flash_mma(
    const __nv_bfloat16* __restrict__ Qh, const __nv_bfloat16* __restrict__ Ql,
    const __nv_bfloat16* __restrict__ Kh, const __nv_bfloat16* __restrict__ Kl,
    const __half* __restrict__ Vh, const __half* __restrict__ Vl,
    __nv_bfloat16* __restrict__ Oh, __nv_bfloat16* __restrict__ Ol)
{
    extern __shared__ char sm[];
    const uint32_t sb = smem_u32(sm);
    const int tid = threadIdx.x;
    const int lane = tid & 31;
    const int wm = tid >> 5;
    const int qb = blockIdx.x;
    const int h = blockIdx.y;
    const int b = blockIdx.z;
    const int kvh = h >> 2;
    const int nkt = 2 * (qb + 1);

    const size_t qg = ((size_t)(b * NH + h) * SS + qb * 128) * 64;
    const size_t kg = ((size_t)(b * NKV + kvh) * SS) * 64;

    // ---- Q load ----
    {
        const __nv_bfloat16* qarr[2] = {Qh + qg, Ql + qg};
#pragma unroll
        for (int i = 0; i < 8; i++) {
            int g = tid + i * 256;
            int arr = g >> 10;
            int w = g & 1023;
            int row = w >> 3;
            int ch = w & 7;
            cp_async16(sb + arr * FQ_BYTES + row * FSTRB + ch * 16,
                       qarr[arr] + (size_t)row * 64 + ch * 8);
        }
        asm volatile("cp.async.commit_group;" ::: "memory");
    }

#define LOADKV(kt_) do {                                                        \
    int j0_ = (kt_) * 64;                                                       \
    uint32_t stg_ = sb + FKV0 + ((kt_) & 1) * FSTAGE;                           \
    const char* karr[4] = {                                                     \
        (const char*)(Kh + kg + (size_t)j0_ * 64),                              \
        (const char*)(Kl + kg + (size_t)j0_ * 64),                              \
        (const char*)(Vh + kg + (size_t)j0_ * 64),                              \
        (const char*)(Vl + kg + (size_t)j0_ * 64)};                             \
    _Pragma("unroll")                                                           \
    for (int i = 0; i < 8; i++) {                                               \
        int g = tid + i * 256;                                                  \
        int arr = g >> 9;                                                       \
        int w = g & 511;                                                        \
        int row = w >> 3;                                                       \
        int ch = w & 7;                                                         \
        cp_async16(stg_ + arr * FARR + row * FSTRB + ch * 16,                   \
                   karr[arr] + row * 128 + ch * 16);                            \
    }                                                                           \
    asm volatile("cp.async.commit_group;" ::: "memory");                        \
} while (0)

    LOADKV(0);
    if (nkt > 1) LOADKV(1);

    // V-tile pad init: Vh pad col64 = 1.0h (rest 0), Vl pad = 0. Both stages.
    // cp.async never touches bytes [128,144) of each row, so this persists.
    if (tid < 128) {
        int stage = tid >> 6;
        int row = tid & 63;
        uint32_t off = FKV0 + stage * FSTAGE + 2 * FARR + row * FSTRB + 128;
        uint4 ones = {0x00003C00u, 0u, 0u, 0u};
        uint4 zero = {0u, 0u, 0u, 0u};
        *(uint4*)(sm + off) = ones;              // Vh pad
        *(uint4*)(sm + off + FARR) = zero;       // Vl pad
    }

    if (nkt > 1) { asm volatile("cp.async.wait_group 1;" ::: "memory"); }
    else         { asm volatile("cp.async.wait_group 0;" ::: "memory"); }
    __syncthreads();

    // ---- Q fragments ----
    uint32_t qfh[4][4], qfl[4][4];
#pragma unroll
    for (int kk = 0; kk < 4; kk++) {
        uint32_t addr = sb + (uint32_t)((wm * 16 + (lane & 15)) * FSTRB
                                        + kk * 32 + (lane >> 4) * 16);
        ldsm4(qfh[kk], addr);
        ldsm4(qfl[kk], addr + FQ_BYTES);
    }

    float co[8][4];
#pragma unroll
    for (int i = 0; i < 8; i++)
#pragma unroll
        for (int j = 0; j < 4; j++) co[i][j] = 0.0f;
    float lacc[4] = {0.0f, 0.0f, 0.0f, 0.0f};
    float m0 = -1e30f, m1 = -1e30f;

    const int lg = lane >> 3;
    const int lr = lane & 7;
    const int qr0 = qb * 128 + wm * 16 + (lane >> 2);

    for (int kt = 0; kt < nkt; kt++) {
        if (kt > 0) {
            if (kt + 1 < nkt) { asm volatile("cp.async.wait_group 1;" ::: "memory"); }
            else              { asm volatile("cp.async.wait_group 0;" ::: "memory"); }
            __syncthreads();
        }
        const uint32_t sKh = sb + FKV0 + (kt & 1) * FSTAGE;
        const uint32_t sKl = sKh + FARR;
        const uint32_t sVh = sKh + 2 * FARR;
        const uint32_t sVl = sKh + 3 * FARR;

        // ---- S = Q K^T (split bf16, 3 terms) ----
        float cs[8][4];
#pragma unroll
        for (int i = 0; i < 8; i++)
#pragma unroll
            for (int j = 0; j < 4; j++) cs[i][j] = 0.0f;

#pragma unroll
        for (int kk = 0; kk < 4; kk++) {
#pragma unroll
            for (int ng = 0; ng < 4; ng++) {
                uint32_t boff = (uint32_t)((ng * 16 + (lg >> 1) * 8 + lr) * FSTRB
                                           + kk * 32 + (lg & 1) * 16);
                uint32_t bh[4], bl[4];
                ldsm4(bh, sKh + boff);
                ldsm4(bl, sKl + boff);
                mma16816(cs[ng * 2], qfh[kk], bh);
                mma16816(cs[ng * 2], qfl[kk], bh);
                mma16816(cs[ng * 2], qfh[kk], bl);
                mma16816(cs[ng * 2 + 1], qfh[kk], bh + 2);
                mma16816(cs[ng * 2 + 1], qfl[kk], bh + 2);
                mma16816(cs[ng * 2 + 1], qfh[kk], bl + 2);
            }
        }

        // ---- causal mask on diagonal tiles ----
        if (kt >= nkt - 2) {
            int gcol0 = kt * 64 + (lane & 3) * 2;
#pragma unroll
            for (int n = 0; n < 8; n++) {
#pragma unroll
                for (int t = 0; t < 2; t++) {
                    int col = gcol0 + n * 8 + t;
                    if (col > qr0) cs[n][t] = -1e30f;
                    if (col > qr0 + 8) cs[n][t + 2] = -1e30f;
                }
            }
        }

        // ---- online softmax (base-2), P in fp16 via f16x2 exp ----
        float mx0 = -1e30f, mx1 = -1e30f;
#pragma unroll
        for (int n = 0; n < 8; n++) {
            mx0 = fmaxf(mx0, fmaxf(cs[n][0], cs[n][1]));
            mx1 = fmaxf(mx1, fmaxf(cs[n][2], cs[n][3]));
        }
        mx0 = fmaxf(mx0, __shfl_xor_sync(0xffffffffu, mx0, 1));
        mx0 = fmaxf(mx0, __shfl_xor_sync(0xffffffffu, mx0, 2));
        mx1 = fmaxf(mx1, __shfl_xor_sync(0xffffffffu, mx1, 1));
        mx1 = fmaxf(mx1, __shfl_xor_sync(0xffffffffu, mx1, 2));
        float nm0 = fmaxf(m0, mx0);
        float nm1 = fmaxf(m1, mx1);
        float f0 = ex2f(m0 - nm0);
        float f1 = ex2f(m1 - nm1);
        m0 = nm0; m1 = nm1;

        uint32_t pp[8][2];
#pragma unroll
        for (int n = 0; n < 8; n++) {
            pp[n][0] = ex2_f16x2(pack_f16x2(cs[n][0] - nm0, cs[n][1] - nm0));
            pp[n][1] = ex2_f16x2(pack_f16x2(cs[n][2] - nm1, cs[n][3] - nm1));
        }

        // rescale O and l accumulators
#pragma unroll
        for (int n = 0; n < 8; n++) {
            co[n][0] *= f0; co[n][1] *= f0;
            co[n][2] *= f1; co[n][3] *= f1;
        }
        lacc[0] *= f0; lacc[2] *= f1;

        // ---- O += P V  (fp16 P, fp16 split V) + ones-column row sums ----
#pragma unroll
        for (int kk = 0; kk < 4; kk++) {
            uint32_t pa[4] = {pp[2 * kk][0], pp[2 * kk][1],
                              pp[2 * kk + 1][0], pp[2 * kk + 1][1]};
#pragma unroll
            for (int ng = 0; ng < 4; ng++) {
                uint32_t vaddr = (uint32_t)((kk * 16 + (lane & 15)) * FSTRB
                                            + (ng * 16 + (lane >> 4) * 8) * 2);
                uint32_t vh[4], vl[4];
                ldsm4t(vh, sVh + vaddr);
                ldsm4t(vl, sVl + vaddr);
                mma16816h(co[ng * 2], pa, vh);
                mma16816h(co[ng * 2], pa, vl);
                mma16816h(co[ng * 2 + 1], pa, vh + 2);
                mma16816h(co[ng * 2 + 1], pa, vl + 2);
            }
            // ones column (col 64 of padded Vh tile) -> row sums in lacc
            uint32_t v1[2];
            ldsm2t(v1, sVh + (uint32_t)((kk * 16 + (lane & 15)) * FSTRB + 128));
            mma16816h(lacc, pa, v1);
        }

        __syncthreads();
        if (kt + 2 < nkt) LOADKV(kt + 2);
    }

    // ---- epilogue ----
    float l0 = __shfl_sync(0xffffffffu, lacc[0], lane & ~3);
    float l1 = __shfl_sync(0xffffffffu, lacc[2], lane & ~3);
    float inv0 = 1.0f / l0;
    float inv1 = 1.0f / l1;

    int srow = qb * 128 + wm * 16 + (lane >> 2);
    size_t base0 = ((size_t)(b * SS) + srow) * QDIM + h * 64 + (lane & 3) * 2;
    size_t base1 = base0 + (size_t)8 * QDIM;
#pragma unroll
    for (int nd = 0; nd < 8; nd++) {
        uint32_t hh, ll;
        pack_split(co[nd][0] * inv0, co[nd][1] * inv0, hh, ll);
        *(uint32_t*)(Oh + base0 + nd * 8) = hh;
        *(uint32_t*)(Ol + base0 + nd * 8) = ll;
        pack_split(co[nd][2] * inv1, co[nd][3] * inv1, hh, ll);
        *(uint32_t*)(Oh + base1 + nd * 8) = hh;
        *(uint32_t*)(Ol + base1 + nd * 8) = ll;
    }
#undef LOADKV
}

// ---------------------------------------------------------------------------
// Launch
// ---------------------------------------------------------------------------
extern "C" void kernel_launch(void* const* d_in, const int* in_sizes, int n_in,
                              void* d_out, int out_size) {
    const float* x = (const float*)d_in[0];
    const float* wq = (const float*)d_in[1];
    const float* wk = (const float*)d_in[2];
    const float* wv = (const float*)d_in[3];
    const float* wo = (const float*)d_in[4];
    const float* cosT = (const float*)d_in[5];
    const float* sinT = (const float*)d_in[6];
    float* out = (float*)d_out;

    float* QKVp;
    __nv_bfloat16 *xh, *xl, *Wch, *Wcl, *Woh, *Wol;
    __nv_bfloat16 *Qh, *Ql, *Kh, *Kl, *Oh, *Ol;
    __half *Vh, *Vl;
    cudaGetSymbolAddress((void**)&QKVp, g_QKV);
    cudaGetSymbolAddress((void**)&xh, g_xh);
    cudaGetSymbolAddress((void**)&xl, g_xl);
    cudaGetSymbolAddress((void**)&Wch, g_Wch);
    cudaGetSymbolAddress((void**)&Wcl, g_Wcl);
    cudaGetSymbolAddress((void**)&Woh, g_Woh);
    cudaGetSymbolAddress((void**)&Wol, g_Wol);
    cudaGetSymbolAddress((void**)&Qh, g_Qh);
    cudaGetSymbolAddress((void**)&Ql, g_Ql);
    cudaGetSymbolAddress((void**)&Kh, g_Kh);
    cudaGetSymbolAddress((void**)&Kl, g_Kl);
    cudaGetSymbolAddress((void**)&Vh, g_Vh);
    cudaGetSymbolAddress((void**)&Vl, g_Vl);
    cudaGetSymbolAddress((void**)&Oh, g_Oh);
    cudaGetSymbolAddress((void**)&Ol, g_Ol);

    cudaFuncSetAttribute(gemm_tc, cudaFuncAttributeMaxDynamicSharedMemorySize,
                         GT_SMEM_TOTAL);
    cudaFuncSetAttribute(flash_mma, cudaFuncAttributeMaxDynamicSharedMemorySize,
                         FL_SMEM);

    // Splits of inputs
    {
        int n2 = MTOT * DM / 2;
        cvt2<<<(n2 + 255) / 256, 256>>>(x, xh, xl, n2);
        n2 = QDIM * DM / 2;
        cvt2<<<(n2 + 255) / 256, 256>>>(wq, Wch, Wcl, n2);
        n2 = KVDIM * DM / 2;
        cvt2<<<(n2 + 255) / 256, 256>>>(wk, Wch + (size_t)QDIM * DM, Wcl + (size_t)QDIM * DM, n2);
        cvt2<<<(n2 + 255) / 256, 256>>>(wv, Wch + (size_t)(QDIM + KVDIM) * DM,
                                        Wcl + (size_t)(QDIM + KVDIM) * DM, n2);
        n2 = DM * QDIM / 2;
        cvt2<<<(n2 + 255) / 256, 256>>>(wo, Woh, Wol, n2);
    }

    // Fused QKV projection
    gemm_tc<<<dim3(QKVD / 128, MTOT / 128), 256, GT_SMEM_TOTAL>>>(
        xh, xl, Wch, Wcl, QKVp, QKVD, DM);

    // RoPE + split + relayout
    {
        int tot = MTOT * (NH + NKV) * 32;
        rope_split<<<(tot + 255) / 256, 256>>>(QKVp, cosT, sinT, Qh, Ql, Kh, Kl);
        int tv = MTOT * NKV * 32;
        v_split<<<(tv + 255) / 256, 256>>>(QKVp, Vh, Vl);
    }

    // Attention (writes split O directly)
    flash_mma<<<dim3(SS / 128, NH, BB), 256, FL_SMEM>>>(Qh, Ql, Kh, Kl, Vh, Vl, Oh, Ol);

    // Output projection
    gemm_tc<<<dim3(DM / 128, MTOT / 128), 256, GT_SMEM_TOTAL>>>(
        Oh, Ol, Woh, Wol, out, DM, QDIM);
}

// round 6
// speedup vs baseline: 6.1410x; 1.1005x over previous
#include <cuda_runtime.h>
#include <cuda_bf16.h>
#include <cuda_fp16.h>
#include <math.h>
#include <stdint.h>

// Problem constants
#define BB 2
#define SS 2048
#define DM 2048
#define NH 32
#define NKV 8
#define HD 64
#define MTOT (BB * SS)          // 4096
#define QDIM (NH * HD)          // 2048
#define KVDIM (NKV * HD)        // 512
#define QKVD (QDIM + 2 * KVDIM) // 3072

// scale/log2 fold: (1/sqrt(64)) * log2(e)
#define QSCALE 0.18033688011112042f

// ---------------------------------------------------------------------------
// Scratch (device globals)
// ---------------------------------------------------------------------------
__device__ float g_QKV[MTOT * QKVD];            // 48 MB
__device__ __nv_bfloat16 g_xh[MTOT * DM];
__device__ __nv_bfloat16 g_xl[MTOT * DM];
__device__ __nv_bfloat16 g_Wch[QKVD * DM];
__device__ __nv_bfloat16 g_Wcl[QKVD * DM];
__device__ __nv_bfloat16 g_Woh[DM * QDIM];
__device__ __nv_bfloat16 g_Wol[DM * QDIM];
// per-head attention operand buffers [b][h][s][64]
__device__ __nv_bfloat16 g_Qh[BB * NH * SS * HD];
__device__ __nv_bfloat16 g_Ql[BB * NH * SS * HD];
__device__ __nv_bfloat16 g_Kh[BB * NKV * SS * HD];
__device__ __nv_bfloat16 g_Kl[BB * NKV * SS * HD];
__device__ __half g_Vh[BB * NKV * SS * HD];
__device__ __half g_Vl[BB * NKV * SS * HD];
// attention output split, [b][s][2048] (GEMM-ready)
__device__ __nv_bfloat16 g_Oh[MTOT * QDIM];
__device__ __nv_bfloat16 g_Ol[MTOT * QDIM];

// ---------------------------------------------------------------------------
// PTX helpers
// ---------------------------------------------------------------------------
__device__ __forceinline__ uint32_t smem_u32(const void* p) {
    uint32_t a;
    asm("{ .reg .u64 t; cvta.to.shared.u64 t, %1; cvt.u32.u64 %0, t; }" : "=r"(a) : "l"(p));
    return a;
}
__device__ __forceinline__ void ldsm4(uint32_t* r, uint32_t addr) {
    asm volatile("ldmatrix.sync.aligned.m8n8.x4.shared.b16 {%0,%1,%2,%3}, [%4];"
                 : "=r"(r[0]), "=r"(r[1]), "=r"(r[2]), "=r"(r[3]) : "r"(addr));
}
__device__ __forceinline__ void ldsm4t(uint32_t* r, uint32_t addr) {
    asm volatile("ldmatrix.sync.aligned.m8n8.x4.trans.shared.b16 {%0,%1,%2,%3}, [%4];"
                 : "=r"(r[0]), "=r"(r[1]), "=r"(r[2]), "=r"(r[3]) : "r"(addr));
}
__device__ __forceinline__ void ldsm2t(uint32_t* r, uint32_t addr) {
    asm volatile("ldmatrix.sync.aligned.m8n8.x2.trans.shared.b16 {%0,%1}, [%2];"
                 : "=r"(r[0]), "=r"(r[1]) : "r"(addr));
}
__device__ __forceinline__ void mma16816(float* c, const uint32_t* a, const uint32_t* b) {
    asm volatile(
        "mma.sync.aligned.m16n8k16.row.col.f32.bf16.bf16.f32 "
        "{%0,%1,%2,%3}, {%4,%5,%6,%7}, {%8,%9}, {%0,%1,%2,%3};"
        : "+f"(c[0]), "+f"(c[1]), "+f"(c[2]), "+f"(c[3])
        : "r"(a[0]), "r"(a[1]), "r"(a[2]), "r"(a[3]), "r"(b[0]), "r"(b[1]));
}
__device__ __forceinline__ void mma16816h(float* c, const uint32_t* a, const uint32_t* b) {
    asm volatile(
        "mma.sync.aligned.m16n8k16.row.col.f32.f16.f16.f32 "
        "{%0,%1,%2,%3}, {%4,%5,%6,%7}, {%8,%9}, {%0,%1,%2,%3};"
        : "+f"(c[0]), "+f"(c[1]), "+f"(c[2]), "+f"(c[3])
        : "r"(a[0]), "r"(a[1]), "r"(a[2]), "r"(a[3]), "r"(b[0]), "r"(b[1]));
}
__device__ __forceinline__ void cp_async16(uint32_t saddr, const void* gaddr) {
    asm volatile("cp.async.cg.shared.global [%0], [%1], 16;" :: "r"(saddr), "l"(gaddr));
}
__device__ __forceinline__ float ex2f(float x) {
    float y;
    asm("ex2.approx.ftz.f32 %0, %1;" : "=f"(y) : "f"(x));
    return y;
}
__device__ __forceinline__ uint32_t pack_f16x2(float lo, float hi) {
    uint32_t d;
    asm("cvt.rn.f16x2.f32 %0, %1, %2;" : "=r"(d) : "f"(hi), "f"(lo));
    return d;
}
__device__ __forceinline__ uint32_t ex2_f16x2(uint32_t x) {
    uint32_t y;
    asm("ex2.approx.f16x2 %0, %1;" : "=r"(y) : "r"(x));
    return y;
}
__device__ __forceinline__ void pack_split(float x, float y, uint32_t& hi, uint32_t& lo) {
    __nv_bfloat162 h = __floats2bfloat162_rn(x, y);
    float rx = x - __bfloat162float(h.x);
    float ry = y - __bfloat162float(h.y);
    __nv_bfloat162 l = __floats2bfloat162_rn(rx, ry);
    hi = *(uint32_t*)&h;
    lo = *(uint32_t*)&l;
}

// ---------------------------------------------------------------------------
// Split-bf16 HMMA GEMM v2: C[M,NN] = A[M,K] * B[NN,K]^T
// CTA tile 256x128, BK=32, 256 threads (8 warps 4m x 2n, warp tile 64x64),
// cp.async double buffer. SMEM rows: 32 bf16 = 64B data + 16B pad (80B stride).
// ---------------------------------------------------------------------------
#define G2_AARR 20480                  // 256 rows * 80 B
#define G2_BARR 10240                  // 128 rows * 80 B
#define G2_BOFF (2 * G2_AARR)          // 40960
#define G2_STAGE (2 * G2_AARR + 2 * G2_BARR)   // 61440
#define G2_SMEM_TOTAL (2 * G2_STAGE)           // 122880

__global__ __launch_bounds__(256, 1) void gemm_tc(
    const __nv_bfloat16* __restrict__ Ah, const __nv_bfloat16* __restrict__ Al,
    const __nv_bfloat16* __restrict__ Bh, const __nv_bfloat16* __restrict__ Bl,
    float* __restrict__ C, int NN, int K)
{
    extern __shared__ char smem[];
    const uint32_t sb = smem_u32(smem);
    const int tid = threadIdx.x;
    const int wid = tid >> 5;
    const int lane = tid & 31;
    const int wm = wid & 3;          // 0..3 -> 64 rows each
    const int wn = wid >> 2;         // 0..1 -> 64 cols each
    const int m0 = blockIdx.y * 256;
    const int n0 = blockIdx.x * 128;

    const __nv_bfloat16* const Aarr[2] = {Ah + (size_t)m0 * K, Al + (size_t)m0 * K};
    const __nv_bfloat16* const Barr[2] = {Bh + (size_t)n0 * K, Bl + (size_t)n0 * K};

    float acc[4][8][4];
#pragma unroll
    for (int i = 0; i < 4; i++)
#pragma unroll
        for (int j = 0; j < 8; j++)
#pragma unroll
            for (int q = 0; q < 4; q++) acc[i][j][q] = 0.0f;

    const int NC = K / 32;
    const int lg = lane >> 3;
    const int lr = lane & 7;

#define LOADSTAGE(cc) do {                                                     \
    const uint32_t stg = ((cc) & 1) ? G2_STAGE : 0;                            \
    const int k0 = (cc) * 32;                                                  \
    _Pragma("unroll")                                                          \
    for (int i = 0; i < 12; i++) {                                             \
        int gidx = tid + i * 256;                                              \
        if (gidx < 2048) {                                                     \
            int arr = gidx >> 10;                                              \
            int w = gidx & 1023;                                               \
            int row = w >> 2;                                                  \
            int q = w & 3;                                                     \
            cp_async16(sb + stg + arr * G2_AARR + row * 80 + q * 16,           \
                       Aarr[arr] + (size_t)row * K + k0 + q * 8);              \
        } else {                                                               \
            int g2 = gidx - 2048;                                              \
            int arr = g2 >> 9;                                                 \
            int w = g2 & 511;                                                  \
            int row = w >> 2;                                                  \
            int q = w & 3;                                                     \
            cp_async16(sb + stg + G2_BOFF + arr * G2_BARR + row * 80 + q * 16, \
                       Barr[arr] + (size_t)row * K + k0 + q * 8);              \
        }                                                                      \
    }                                                                          \
    asm volatile("cp.async.commit_group;" ::: "memory");                       \
} while (0)

    LOADSTAGE(0);

    for (int c = 0; c < NC; c++) {
        asm volatile("cp.async.wait_group 0;" ::: "memory");
        __syncthreads();
        if (c + 1 < NC) LOADSTAGE(c + 1);

        const uint32_t stg = sb + ((c & 1) ? G2_STAGE : 0);
        const uint32_t sAh = stg;
        const uint32_t sAl = stg + G2_AARR;
        const uint32_t sBh = stg + G2_BOFF;
        const uint32_t sBl = stg + G2_BOFF + G2_BARR;

#pragma unroll
        for (int kk = 0; kk < 2; kk++) {
            const int kbyte = kk * 32;
            uint32_t fAh[4][4], fAl[4][4];
#pragma unroll
            for (int mt = 0; mt < 4; mt++) {
                int arow = wm * 64 + mt * 16 + (lg & 1) * 8 + lr;
                uint32_t aoff = (uint32_t)(arow * 80 + kbyte + (lg >> 1) * 16);
                ldsm4(fAh[mt], sAh + aoff);
                ldsm4(fAl[mt], sAl + aoff);
            }
#pragma unroll
            for (int np = 0; np < 4; np++) {
                int brow = wn * 64 + np * 16 + (lg >> 1) * 8 + lr;
                uint32_t boff = (uint32_t)(brow * 80 + kbyte + (lg & 1) * 16);
                uint32_t fBh[4], fBl[4];
                ldsm4(fBh, sBh + boff);
                ldsm4(fBl, sBl + boff);
#pragma unroll
                for (int mt = 0; mt < 4; mt++) {
                    mma16816(acc[mt][np * 2], fAh[mt], fBh);
                    mma16816(acc[mt][np * 2], fAl[mt], fBh);
                    mma16816(acc[mt][np * 2], fAh[mt], fBl);
                    mma16816(acc[mt][np * 2 + 1], fAh[mt], fBh + 2);
                    mma16816(acc[mt][np * 2 + 1], fAl[mt], fBh + 2);
                    mma16816(acc[mt][np * 2 + 1], fAh[mt], fBl + 2);
                }
            }
        }
        __syncthreads();
    }

#pragma unroll
    for (int mt = 0; mt < 4; mt++) {
        int row0 = m0 + wm * 64 + mt * 16 + (lane >> 2);
#pragma unroll
        for (int nt = 0; nt < 8; nt++) {
            int col = n0 + wn * 64 + nt * 8 + (lane & 3) * 2;
            float2 v0 = {acc[mt][nt][0], acc[mt][nt][1]};
            float2 v1 = {acc[mt][nt][2], acc[mt][nt][3]};
            *(float2*)(C + (size_t)row0 * NN + col) = v0;
            *(float2*)(C + (size_t)(row0 + 8) * NN + col) = v1;
        }
    }
#undef LOADSTAGE
}

// ---------------------------------------------------------------------------
// fp32 -> bf16 hi/lo split
// ---------------------------------------------------------------------------
__global__ void cvt2(const float* __restrict__ in, __nv_bfloat16* __restrict__ hi,
                     __nv_bfloat16* __restrict__ lo, int n2) {
    int i = blockIdx.x * blockDim.x + threadIdx.x;
    if (i >= n2) return;
    float2 v = ((const float2*)in)[i];
    uint32_t h, l;
    pack_split(v.x, v.y, h, l);
    ((uint32_t*)hi)[i] = h;
    ((uint32_t*)lo)[i] = l;
}

// ---------------------------------------------------------------------------
// RoPE + split + relayout for Q and K (Q gets QSCALE folded in)
// ---------------------------------------------------------------------------
__global__ void rope_split(const float* __restrict__ QKV,
                           const float* __restrict__ cosT, const float* __restrict__ sinT,
                           __nv_bfloat16* __restrict__ Qh, __nv_bfloat16* __restrict__ Ql,
                           __nv_bfloat16* __restrict__ Kh, __nv_bfloat16* __restrict__ Kl) {
    int idx = blockIdx.x * blockDim.x + threadIdx.x;
    const int TQ = MTOT * NH * 32;
    const int TK = MTOT * NKV * 32;
    if (idx >= TQ + TK) return;
    bool isQ = idx < TQ;
    int id = isQ ? idx : idx - TQ;
    int nheads = isQ ? NH : NKV;
    int d = id & 31;
    int h = (id >> 5) % nheads;
    int m = id / (32 * nheads);
    int s = m & (SS - 1);
    int b = m >> 11;

    const float* p = QKV + (size_t)m * QKVD + (isQ ? 0 : QDIM) + h * 64 + d;
    float a = p[0];
    float bb = p[32];
    int ci = s * 32 + (d >> 1);
    float c1 = cosT[ci], s1 = sinT[ci];
    float c2 = cosT[ci + 16], s2 = sinT[ci + 16];
    float ra = a * c1 - bb * s1;
    float rb = bb * c2 + a * s2;
    if (isQ) { ra *= QSCALE; rb *= QSCALE; }

    size_t o = ((size_t)(b * nheads + h) * SS + s) * 64 + d;
    __nv_bfloat16* dh = isQ ? Qh : Kh;
    __nv_bfloat16* dl = isQ ? Ql : Kl;
    __nv_bfloat16 ha = __float2bfloat16(ra);
    __nv_bfloat16 hb = __float2bfloat16(rb);
    dh[o] = ha;       dh[o + 32] = hb;
    dl[o] = __float2bfloat16(ra - __bfloat162float(ha));
    dl[o + 32] = __float2bfloat16(rb - __bfloat162float(hb));
}

// V: fp16 hi/lo split + relayout
__global__ void v_split(const float* __restrict__ QKV,
                        __half* __restrict__ Vh, __half* __restrict__ Vl) {
    int u = blockIdx.x * blockDim.x + threadIdx.x;
    if (u >= MTOT * NKV * 32) return;
    int d2 = u & 31;
    int kvh = (u >> 5) & 7;
    int m = u >> 8;
    int s = m & (SS - 1);
    int b = m >> 11;
    float2 v = *(const float2*)(QKV + (size_t)m * QKVD + QDIM + KVDIM + kvh * 64 + 2 * d2);
    __half h0 = __float2half_rn(v.x);
    __half h1 = __float2half_rn(v.y);
    __half2 hh; hh.x = h0; hh.y = h1;
    __half2 ll;
    ll.x = __float2half_rn(v.x - __half2float(h0));
    ll.y = __float2half_rn(v.y - __half2float(h1));
    size_t o = (((size_t)(b * NKV + kvh) * SS + s) * 64 + 2 * d2) >> 1;
    ((__half2*)Vh)[o] = hh;
    ((__half2*)Vl)[o] = ll;
}

// ---------------------------------------------------------------------------
// MMA flash attention (unchanged from R5)
// ---------------------------------------------------------------------------
#define FSTRB 144
#define FQ_BYTES (128 * FSTRB)
#define FARR (64 * FSTRB)
#define FKV0 (2 * FQ_BYTES)
#define FSTAGE (4 * FARR)
#define FL_SMEM (FKV0 + 2 * FSTAGE)

__global__ __launch_bounds__(256, 1) void flash_mma(
    const __nv_bfloat16* __restrict__ Qh, const __nv_bfloat16* __restrict__ Ql,
    const __nv_bfloat16* __restrict__ Kh, const __nv_bfloat16* __restrict__ Kl,
    const __half* __restrict__ Vh, const __half* __restrict__ Vl,
    __nv_bfloat16* __restrict__ Oh, __nv_bfloat16* __restrict__ Ol)
{
    extern __shared__ char sm[];
    const uint32_t sb = smem_u32(sm);
    const int tid = threadIdx.x;
    const int lane = tid & 31;
    const int wm = tid >> 5;
    const int qb = blockIdx.x;
    const int h = blockIdx.y;
    const int b = blockIdx.z;
    const int kvh = h >> 2;
    const int nkt = 2 * (qb + 1);

    const size_t qg = ((size_t)(b * NH + h) * SS + qb * 128) * 64;
    const size_t kg = ((size_t)(b * NKV + kvh) * SS) * 64;

    {
        const __nv_bfloat16* qarr[2] = {Qh + qg, Ql + qg};
#pragma unroll
        for (int i = 0; i < 8; i++) {
            int g = tid + i * 256;
            int arr = g >> 10;
            int w = g & 1023;
            int row = w >> 3;
            int ch = w & 7;
            cp_async16(sb + arr * FQ_BYTES + row * FSTRB + ch * 16,
                       qarr[arr] + (size_t)row * 64 + ch * 8);
        }
        asm volatile("cp.async.commit_group;" ::: "memory");
    }

#define LOADKV(kt_) do {                                                        \
    int j0_ = (kt_) * 64;                                                       \
    uint32_t stg_ = sb + FKV0 + ((kt_) & 1) * FSTAGE;                           \
    const char* karr[4] = {                                                     \
        (const char*)(Kh + kg + (size_t)j0_ * 64),                              \
        (const char*)(Kl + kg + (size_t)j0_ * 64),                              \
        (const char*)(Vh + kg + (size_t)j0_ * 64),                              \
        (const char*)(Vl + kg + (size_t)j0_ * 64)};                             \
    _Pragma("unroll")                                                           \
    for (int i = 0; i < 8; i++) {                                               \
        int g = tid + i * 256;                                                  \
        int arr = g >> 9;                                                       \
        int w = g & 511;                                                        \
        int row = w >> 3;                                                       \
        int ch = w & 7;                                                         \
        cp_async16(stg_ + arr * FARR + row * FSTRB + ch * 16,                   \
                   karr[arr] + row * 128 + ch * 16);                            \
    }                                                                           \
    asm volatile("cp.async.commit_group;" ::: "memory");                        \
} while (0)

    LOADKV(0);
    if (nkt > 1) LOADKV(1);

    if (tid < 128) {
        int stage = tid >> 6;
        int row = tid & 63;
        uint32_t off = FKV0 + stage * FSTAGE + 2 * FARR + row * FSTRB + 128;
        uint4 ones = {0x00003C00u, 0u, 0u, 0u};
        uint4 zero = {0u, 0u, 0u, 0u};
        *(uint4*)(sm + off) = ones;
        *(uint4*)(sm + off + FARR) = zero;
    }

    if (nkt > 1) { asm volatile("cp.async.wait_group 1;" ::: "memory"); }
    else         { asm volatile("cp.async.wait_group 0;" ::: "memory"); }
    __syncthreads();

    uint32_t qfh[4][4], qfl[4][4];
#pragma unroll
    for (int kk = 0; kk < 4; kk++) {
        uint32_t addr = sb + (uint32_t)((wm * 16 + (lane & 15)) * FSTRB
                                        + kk * 32 + (lane >> 4) * 16);
        ldsm4(qfh[kk], addr);
        ldsm4(qfl[kk], addr + FQ_BYTES);
    }

    float co[8][4];
#pragma unroll
    for (int i = 0; i < 8; i++)
#pragma unroll
        for (int j = 0; j < 4; j++) co[i][j] = 0.0f;
    float lacc[4] = {0.0f, 0.0f, 0.0f, 0.0f};
    float m0 = -1e30f, m1 = -1e30f;

    const int lg = lane >> 3;
    const int lr = lane & 7;
    const int qr0 = qb * 128 + wm * 16 + (lane >> 2);

    for (int kt = 0; kt < nkt; kt++) {
        if (kt > 0) {
            if (kt + 1 < nkt) { asm volatile("cp.async.wait_group 1;" ::: "memory"); }
            else              { asm volatile("cp.async.wait_group 0;" ::: "memory"); }
            __syncthreads();
        }
        const uint32_t sKh = sb + FKV0 + (kt & 1) * FSTAGE;
        const uint32_t sKl = sKh + FARR;
        const uint32_t sVh = sKh + 2 * FARR;
        const uint32_t sVl = sKh + 3 * FARR;

        float cs[8][4];
#pragma unroll
        for (int i = 0; i < 8; i++)
#pragma unroll
            for (int j = 0; j < 4; j++) cs[i][j] = 0.0f;

#pragma unroll
        for (int kk = 0; kk < 4; kk++) {
#pragma unroll
            for (int ng = 0; ng < 4; ng++) {
                uint32_t boff = (uint32_t)((ng * 16 + (lg >> 1) * 8 + lr) * FSTRB
                                           + kk * 32 + (lg & 1) * 16);
                uint32_t bh[4], bl[4];
                ldsm4(bh, sKh + boff);
                ldsm4(bl, sKl + boff);
                mma16816(cs[ng * 2], qfh[kk], bh);
                mma16816(cs[ng * 2], qfl[kk], bh);
                mma16816(cs[ng * 2], qfh[kk], bl);
                mma16816(cs[ng * 2 + 1], qfh[kk], bh + 2);
                mma16816(cs[ng * 2 + 1], qfl[kk], bh + 2);
                mma16816(cs[ng * 2 + 1], qfh[kk], bl + 2);
            }
        }

        if (kt >= nkt - 2) {
            int gcol0 = kt * 64 + (lane & 3) * 2;
#pragma unroll
            for (int n = 0; n < 8; n++) {
#pragma unroll
                for (int t = 0; t < 2; t++) {
                    int col = gcol0 + n * 8 + t;
                    if (col > qr0) cs[n][t] = -1e30f;
                    if (col > qr0 + 8) cs[n][t + 2] = -1e30f;
                }
            }
        }

        float mx0 = -1e30f, mx1 = -1e30f;
#pragma unroll
        for (int n = 0; n < 8; n++) {
            mx0 = fmaxf(mx0, fmaxf(cs[n][0], cs[n][1]));
            mx1 = fmaxf(mx1, fmaxf(cs[n][2], cs[n][3]));
        }
        mx0 = fmaxf(mx0, __shfl_xor_sync(0xffffffffu, mx0, 1));
        mx0 = fmaxf(mx0, __shfl_xor_sync(0xffffffffu, mx0, 2));
        mx1 = fmaxf(mx1, __shfl_xor_sync(0xffffffffu, mx1, 1));
        mx1 = fmaxf(mx1, __shfl_xor_sync(0xffffffffu, mx1, 2));
        float nm0 = fmaxf(m0, mx0);
        float nm1 = fmaxf(m1, mx1);
        float f0 = ex2f(m0 - nm0);
        float f1 = ex2f(m1 - nm1);
        m0 = nm0; m1 = nm1;

        uint32_t pp[8][2];
#pragma unroll
        for (int n = 0; n < 8; n++) {
            pp[n][0] = ex2_f16x2(pack_f16x2(cs[n][0] - nm0, cs[n][1] - nm0));
            pp[n][1] = ex2_f16x2(pack_f16x2(cs[n][2] - nm1, cs[n][3] - nm1));
        }

#pragma unroll
        for (int n = 0; n < 8; n++) {
            co[n][0] *= f0; co[n][1] *= f0;
            co[n][2] *= f1; co[n][3] *= f1;
        }
        lacc[0] *= f0; lacc[2] *= f1;

#pragma unroll
        for (int kk = 0; kk < 4; kk++) {
            uint32_t pa[4] = {pp[2 * kk][0], pp[2 * kk][1],
                              pp[2 * kk + 1][0], pp[2 * kk + 1][1]};
#pragma unroll
            for (int ng = 0; ng < 4; ng++) {
                uint32_t vaddr = (uint32_t)((kk * 16 + (lane & 15)) * FSTRB
                                            + (ng * 16 + (lane >> 4) * 8) * 2);
                uint32_t vh[4], vl[4];
                ldsm4t(vh, sVh + vaddr);
                ldsm4t(vl, sVl + vaddr);
                mma16816h(co[ng * 2], pa, vh);
                mma16816h(co[ng * 2], pa, vl);
                mma16816h(co[ng * 2 + 1], pa, vh + 2);
                mma16816h(co[ng * 2 + 1], pa, vl + 2);
            }
            uint32_t v1[2];
            ldsm2t(v1, sVh + (uint32_t)((kk * 16 + (lane & 15)) * FSTRB + 128));
            mma16816h(lacc, pa, v1);
        }

        __syncthreads();
        if (kt + 2 < nkt) LOADKV(kt + 2);
    }

    float l0 = __shfl_sync(0xffffffffu, lacc[0], lane & ~3);
    float l1 = __shfl_sync(0xffffffffu, lacc[2], lane & ~3);
    float inv0 = 1.0f / l0;
    float inv1 = 1.0f / l1;

    int srow = qb * 128 + wm * 16 + (lane >> 2);
    size_t base0 = ((size_t)(b * SS) + srow) * QDIM + h * 64 + (lane & 3) * 2;
    size_t base1 = base0 + (size_t)8 * QDIM;
#pragma unroll
    for (int nd = 0; nd < 8; nd++) {
        uint32_t hh, ll;
        pack_split(co[nd][0] * inv0, co[nd][1] * inv0, hh, ll);
        *(uint32_t*)(Oh + base0 + nd * 8) = hh;
        *(uint32_t*)(Ol + base0 + nd * 8) = ll;
        pack_split(co[nd][2] * inv1, co[nd][3] * inv1, hh, ll);
        *(uint32_t*)(Oh + base1 + nd * 8) = hh;
        *(uint32_t*)(Ol + base1 + nd * 8) = ll;
    }
#undef LOADKV
}

// ---------------------------------------------------------------------------
// Launch
// ---------------------------------------------------------------------------
extern "C" void kernel_launch(void* const* d_in, const int* in_sizes, int n_in,
                              void* d_out, int out_size) {
    const float* x = (const float*)d_in[0];
    const float* wq = (const float*)d_in[1];
    const float* wk = (const float*)d_in[2];
    const float* wv = (const float*)d_in[3];
    const float* wo = (const float*)d_in[4];
    const float* cosT = (const float*)d_in[5];
    const float* sinT = (const float*)d_in[6];
    float* out = (float*)d_out;

    float* QKVp;
    __nv_bfloat16 *xh, *xl, *Wch, *Wcl, *Woh, *Wol;
    __nv_bfloat16 *Qh, *Ql, *Kh, *Kl, *Oh, *Ol;
    __half *Vh, *Vl;
    cudaGetSymbolAddress((void**)&QKVp, g_QKV);
    cudaGetSymbolAddress((void**)&xh, g_xh);
    cudaGetSymbolAddress((void**)&xl, g_xl);
    cudaGetSymbolAddress((void**)&Wch, g_Wch);
    cudaGetSymbolAddress((void**)&Wcl, g_Wcl);
    cudaGetSymbolAddress((void**)&Woh, g_Woh);
    cudaGetSymbolAddress((void**)&Wol, g_Wol);
    cudaGetSymbolAddress((void**)&Qh, g_Qh);
    cudaGetSymbolAddress((void**)&Ql, g_Ql);
    cudaGetSymbolAddress((void**)&Kh, g_Kh);
    cudaGetSymbolAddress((void**)&Kl, g_Kl);
    cudaGetSymbolAddress((void**)&Vh, g_Vh);
    cudaGetSymbolAddress((void**)&Vl, g_Vl);
    cudaGetSymbolAddress((void**)&Oh, g_Oh);
    cudaGetSymbolAddress((void**)&Ol, g_Ol);

    cudaFuncSetAttribute(gemm_tc, cudaFuncAttributeMaxDynamicSharedMemorySize,
                         G2_SMEM_TOTAL);
    cudaFuncSetAttribute(flash_mma, cudaFuncAttributeMaxDynamicSharedMemorySize,
                         FL_SMEM);

    // Splits of inputs
    {
        int n2 = MTOT * DM / 2;
        cvt2<<<(n2 + 255) / 256, 256>>>(x, xh, xl, n2);
        n2 = QDIM * DM / 2;
        cvt2<<<(n2 + 255) / 256, 256>>>(wq, Wch, Wcl, n2);
        n2 = KVDIM * DM / 2;
        cvt2<<<(n2 + 255) / 256, 256>>>(wk, Wch + (size_t)QDIM * DM, Wcl + (size_t)QDIM * DM, n2);
        cvt2<<<(n2 + 255) / 256, 256>>>(wv, Wch + (size_t)(QDIM + KVDIM) * DM,
                                        Wcl + (size_t)(QDIM + KVDIM) * DM, n2);
        n2 = DM * QDIM / 2;
        cvt2<<<(n2 + 255) / 256, 256>>>(wo, Woh, Wol, n2);
    }

    // Fused QKV projection: [4096,3072]
    gemm_tc<<<dim3(QKVD / 128, MTOT / 256), 256, G2_SMEM_TOTAL>>>(
        xh, xl, Wch, Wcl, QKVp, QKVD, DM);

    // RoPE + split + relayout
    {
        int tot = MTOT * (NH + NKV) * 32;
        rope_split<<<(tot + 255) / 256, 256>>>(QKVp, cosT, sinT, Qh, Ql, Kh, Kl);
        int tv = MTOT * NKV * 32;
        v_split<<<(tv + 255) / 256, 256>>>(QKVp, Vh, Vl);
    }

    // Attention (writes split O directly)
    flash_mma<<<dim3(SS / 128, NH, BB), 256, FL_SMEM>>>(Qh, Ql, Kh, Kl, Vh, Vl, Oh, Ol);

    // Output projection
    gemm_tc<<<dim3(DM / 128, MTOT / 256), 256, G2_SMEM_TOTAL>>>(
        Oh, Ol, Woh, Wol, out, DM, QDIM);
}

// round 9
// speedup vs baseline: 6.6431x; 1.0818x over previous
#include <cuda_runtime.h>
#include <cuda_bf16.h>
#include <cuda_fp16.h>
#include <math.h>
#include <stdint.h>

// Problem constants
#define BB 2
#define SS 2048
#define DM 2048
#define NH 32
#define NKV 8
#define HD 64
#define MTOT (BB * SS)          // 4096
#define QDIM (NH * HD)          // 2048
#define KVDIM (NKV * HD)        // 512
#define QKVD (QDIM + 2 * KVDIM) // 3072

// scale/log2 fold: (1/sqrt(64)) * log2(e)
#define QSCALE 0.18033688011112042f

// ---------------------------------------------------------------------------
// Scratch (device globals)
// ---------------------------------------------------------------------------
__device__ float g_QKV[MTOT * QKVD];            // 48 MB
__device__ __nv_bfloat16 g_xh[MTOT * DM];
__device__ __nv_bfloat16 g_xl[MTOT * DM];
__device__ __nv_bfloat16 g_Wch[QKVD * DM];
__device__ __nv_bfloat16 g_Wcl[QKVD * DM];
__device__ __nv_bfloat16 g_Woh[DM * QDIM];
__device__ __nv_bfloat16 g_Wol[DM * QDIM];
// per-head attention operands [b][h][s][64]
__device__ __half g_Qf[BB * NH * SS * HD];       // fp16, QSCALE folded
__device__ __half g_Kh[BB * NKV * SS * HD];      // fp16 hi
__device__ __half g_Kl[BB * NKV * SS * HD];      // fp16 residual
__device__ __half g_Vf[BB * NKV * SS * HD];      // fp16
// attention output split, [b][s][2048] (GEMM-ready)
__device__ __nv_bfloat16 g_Oh[MTOT * QDIM];
__device__ __nv_bfloat16 g_Ol[MTOT * QDIM];

// ---------------------------------------------------------------------------
// PTX helpers
// ---------------------------------------------------------------------------
__device__ __forceinline__ uint32_t smem_u32(const void* p) {
    uint32_t a;
    asm("{ .reg .u64 t; cvta.to.shared.u64 t, %1; cvt.u32.u64 %0, t; }" : "=r"(a) : "l"(p));
    return a;
}
__device__ __forceinline__ void ldsm4(uint32_t* r, uint32_t addr) {
    asm volatile("ldmatrix.sync.aligned.m8n8.x4.shared.b16 {%0,%1,%2,%3}, [%4];"
                 : "=r"(r[0]), "=r"(r[1]), "=r"(r[2]), "=r"(r[3]) : "r"(addr));
}
__device__ __forceinline__ void ldsm4t(uint32_t* r, uint32_t addr) {
    asm volatile("ldmatrix.sync.aligned.m8n8.x4.trans.shared.b16 {%0,%1,%2,%3}, [%4];"
                 : "=r"(r[0]), "=r"(r[1]), "=r"(r[2]), "=r"(r[3]) : "r"(addr));
}
__device__ __forceinline__ void ldsm2t(uint32_t* r, uint32_t addr) {
    asm volatile("ldmatrix.sync.aligned.m8n8.x2.trans.shared.b16 {%0,%1}, [%2];"
                 : "=r"(r[0]), "=r"(r[1]) : "r"(addr));
}
__device__ __forceinline__ void mma16816(float* c, const uint32_t* a, const uint32_t* b) {
    asm volatile(
        "mma.sync.aligned.m16n8k16.row.col.f32.bf16.bf16.f32 "
        "{%0,%1,%2,%3}, {%4,%5,%6,%7}, {%8,%9}, {%0,%1,%2,%3};"
        : "+f"(c[0]), "+f"(c[1]), "+f"(c[2]), "+f"(c[3])
        : "r"(a[0]), "r"(a[1]), "r"(a[2]), "r"(a[3]), "r"(b[0]), "r"(b[1]));
}
__device__ __forceinline__ void mma16816h(float* c, const uint32_t* a, const uint32_t* b) {
    asm volatile(
        "mma.sync.aligned.m16n8k16.row.col.f32.f16.f16.f32 "
        "{%0,%1,%2,%3}, {%4,%5,%6,%7}, {%8,%9}, {%0,%1,%2,%3};"
        : "+f"(c[0]), "+f"(c[1]), "+f"(c[2]), "+f"(c[3])
        : "r"(a[0]), "r"(a[1]), "r"(a[2]), "r"(a[3]), "r"(b[0]), "r"(b[1]));
}
__device__ __forceinline__ void cp_async16(uint32_t saddr, const void* gaddr) {
    asm volatile("cp.async.cg.shared.global [%0], [%1], 16;" :: "r"(saddr), "l"(gaddr));
}
__device__ __forceinline__ float ex2f(float x) {
    float y;
    asm("ex2.approx.ftz.f32 %0, %1;" : "=f"(y) : "f"(x));
    return y;
}
__device__ __forceinline__ uint32_t pack_f16x2(float lo, float hi) {
    uint32_t d;
    asm("cvt.rn.f16x2.f32 %0, %1, %2;" : "=r"(d) : "f"(hi), "f"(lo));
    return d;
}
__device__ __forceinline__ uint32_t ex2_f16x2(uint32_t x) {
    uint32_t y;
    asm("ex2.approx.f16x2 %0, %1;" : "=r"(y) : "r"(x));
    return y;
}
__device__ __forceinline__ void pack_split(float x, float y, uint32_t& hi, uint32_t& lo) {
    __nv_bfloat162 h = __floats2bfloat162_rn(x, y);
    float rx = x - __bfloat162float(h.x);
    float ry = y - __bfloat162float(h.y);
    __nv_bfloat162 l = __floats2bfloat162_rn(rx, ry);
    hi = *(uint32_t*)&h;
    lo = *(uint32_t*)&l;
}

// ---------------------------------------------------------------------------
// Split-bf16 HMMA GEMM (exact R6 version that measured 1214us):
// CTA 256x128, BK=32, 2-stage cp.async double buffer.
// ---------------------------------------------------------------------------
#define G2_AARR 20480                  // 256 rows * 80 B
#define G2_BARR 10240                  // 128 rows * 80 B
#define G2_BOFF (2 * G2_AARR)          // 40960
#define G2_STAGE (2 * G2_AARR + 2 * G2_BARR)   // 61440
#define G2_SMEM_TOTAL (2 * G2_STAGE)           // 122880

__global__ __launch_bounds__(256, 1) void gemm_tc(
    const __nv_bfloat16* __restrict__ Ah, const __nv_bfloat16* __restrict__ Al,
    const __nv_bfloat16* __restrict__ Bh, const __nv_bfloat16* __restrict__ Bl,
    float* __restrict__ C, int NN, int K)
{
    extern __shared__ char smem[];
    const uint32_t sb = smem_u32(smem);
    const int tid = threadIdx.x;
    const int wid = tid >> 5;
    const int lane = tid & 31;
    const int wm = wid & 3;
    const int wn = wid >> 2;
    const int m0 = blockIdx.y * 256;
    const int n0 = blockIdx.x * 128;

    const __nv_bfloat16* const Aarr[2] = {Ah + (size_t)m0 * K, Al + (size_t)m0 * K};
    const __nv_bfloat16* const Barr[2] = {Bh + (size_t)n0 * K, Bl + (size_t)n0 * K};

    float acc[4][8][4];
#pragma unroll
    for (int i = 0; i < 4; i++)
#pragma unroll
        for (int j = 0; j < 8; j++)
#pragma unroll
            for (int q = 0; q < 4; q++) acc[i][j][q] = 0.0f;

    const int NC = K / 32;
    const int lg = lane >> 3;
    const int lr = lane & 7;

#define LOADSTAGE(cc) do {                                                     \
    const uint32_t stg = ((cc) & 1) ? G2_STAGE : 0;                            \
    const int k0 = (cc) * 32;                                                  \
    _Pragma("unroll")                                                          \
    for (int i = 0; i < 12; i++) {                                             \
        int gidx = tid + i * 256;                                              \
        if (gidx < 2048) {                                                     \
            int arr = gidx >> 10;                                              \
            int w = gidx & 1023;                                               \
            int row = w >> 2;                                                  \
            int q = w & 3;                                                     \
            cp_async16(sb + stg + arr * G2_AARR + row * 80 + q * 16,           \
                       Aarr[arr] + (size_t)row * K + k0 + q * 8);              \
        } else {                                                               \
            int g2 = gidx - 2048;                                              \
            int arr = g2 >> 9;                                                 \
            int w = g2 & 511;                                                  \
            int row = w >> 2;                                                  \
            int q = w & 3;                                                     \
            cp_async16(sb + stg + G2_BOFF + arr * G2_BARR + row * 80 + q * 16, \
                       Barr[arr] + (size_t)row * K + k0 + q * 8);              \
        }                                                                      \
    }                                                                          \
    asm volatile("cp.async.commit_group;" ::: "memory");                       \
} while (0)

    LOADSTAGE(0);

    for (int c = 0; c < NC; c++) {
        asm volatile("cp.async.wait_group 0;" ::: "memory");
        __syncthreads();
        if (c + 1 < NC) LOADSTAGE(c + 1);

        const uint32_t stg = sb + ((c & 1) ? G2_STAGE : 0);
        const uint32_t sAh = stg;
        const uint32_t sAl = stg + G2_AARR;
        const uint32_t sBh = stg + G2_BOFF;
        const uint32_t sBl = stg + G2_BOFF + G2_BARR;

#pragma unroll
        for (int kk = 0; kk < 2; kk++) {
            const int kbyte = kk * 32;
            uint32_t fAh[4][4], fAl[4][4];
#pragma unroll
            for (int mt = 0; mt < 4; mt++) {
                int arow = wm * 64 + mt * 16 + (lg & 1) * 8 + lr;
                uint32_t aoff = (uint32_t)(arow * 80 + kbyte + (lg >> 1) * 16);
                ldsm4(fAh[mt], sAh + aoff);
                ldsm4(fAl[mt], sAl + aoff);
            }
#pragma unroll
            for (int np = 0; np < 4; np++) {
                int brow = wn * 64 + np * 16 + (lg >> 1) * 8 + lr;
                uint32_t boff = (uint32_t)(brow * 80 + kbyte + (lg & 1) * 16);
                uint32_t fBh[4], fBl[4];
                ldsm4(fBh, sBh + boff);
                ldsm4(fBl, sBl + boff);
#pragma unroll
                for (int mt = 0; mt < 4; mt++) {
                    mma16816(acc[mt][np * 2], fAh[mt], fBh);
                    mma16816(acc[mt][np * 2], fAl[mt], fBh);
                    mma16816(acc[mt][np * 2], fAh[mt], fBl);
                    mma16816(acc[mt][np * 2 + 1], fAh[mt], fBh + 2);
                    mma16816(acc[mt][np * 2 + 1], fAl[mt], fBh + 2);
                    mma16816(acc[mt][np * 2 + 1], fAh[mt], fBl + 2);
                }
            }
        }
        __syncthreads();
    }

#pragma unroll
    for (int mt = 0; mt < 4; mt++) {
        int row0 = m0 + wm * 64 + mt * 16 + (lane >> 2);
#pragma unroll
        for (int nt = 0; nt < 8; nt++) {
            int col = n0 + wn * 64 + nt * 8 + (lane & 3) * 2;
            float2 v0 = {acc[mt][nt][0], acc[mt][nt][1]};
            float2 v1 = {acc[mt][nt][2], acc[mt][nt][3]};
            *(float2*)(C + (size_t)row0 * NN + col) = v0;
            *(float2*)(C + (size_t)(row0 + 8) * NN + col) = v1;
        }
    }
#undef LOADSTAGE
}

// ---------------------------------------------------------------------------
// All fp32 -> bf16 hi/lo splits in one kernel (x, wq, wk, wv, wo)
// ---------------------------------------------------------------------------
#define CV_NX (MTOT * DM / 2)
#define CV_NQ (QDIM * DM / 2)
#define CV_NK (KVDIM * DM / 2)
#define CV_TOTAL (CV_NX + 2 * CV_NQ + 2 * CV_NK)

__global__ void cvt_all(const float* __restrict__ x, const float* __restrict__ wq,
                        const float* __restrict__ wk, const float* __restrict__ wv,
                        const float* __restrict__ wo,
                        __nv_bfloat16* __restrict__ xh, __nv_bfloat16* __restrict__ xl,
                        __nv_bfloat16* __restrict__ Wch, __nv_bfloat16* __restrict__ Wcl,
                        __nv_bfloat16* __restrict__ Woh, __nv_bfloat16* __restrict__ Wol) {
    int i = blockIdx.x * blockDim.x + threadIdx.x;
    const float* src;
    __nv_bfloat16 *dh, *dl;
    int off;
    if (i < CV_NX) { src = x; dh = xh; dl = xl; off = i; }
    else if (i < CV_NX + CV_NQ) { src = wq; dh = Wch; dl = Wcl; off = i - CV_NX; }
    else if (i < CV_NX + CV_NQ + CV_NK) {
        src = wk; dh = Wch + (size_t)QDIM * DM; dl = Wcl + (size_t)QDIM * DM;
        off = i - CV_NX - CV_NQ;
    } else if (i < CV_NX + CV_NQ + 2 * CV_NK) {
        src = wv; dh = Wch + (size_t)(QDIM + KVDIM) * DM; dl = Wcl + (size_t)(QDIM + KVDIM) * DM;
        off = i - CV_NX - CV_NQ - CV_NK;
    } else if (i < CV_TOTAL) {
        src = wo; dh = Woh; dl = Wol; off = i - CV_NX - CV_NQ - 2 * CV_NK;
    } else return;
    float2 v = ((const float2*)src)[off];
    uint32_t h, l;
    pack_split(v.x, v.y, h, l);
    ((uint32_t*)dh)[off] = h;
    ((uint32_t*)dl)[off] = l;
}

// ---------------------------------------------------------------------------
// prep_attn: RoPE(Q->fp16 w/ QSCALE; K->fp16 split) + V->fp16, per-head layout
// ---------------------------------------------------------------------------
#define PA_TQ (MTOT * NH * 32)
#define PA_TK (MTOT * NKV * 32)
#define PA_TV (MTOT * NKV * 32)
#define PA_TOTAL (PA_TQ + PA_TK + PA_TV)

__global__ void prep_attn(const float* __restrict__ QKV,
                          const float* __restrict__ cosT, const float* __restrict__ sinT,
                          __half* __restrict__ Qf, __half* __restrict__ Kh,
                          __half* __restrict__ Kl, __half* __restrict__ Vf) {
    int idx = blockIdx.x * blockDim.x + threadIdx.x;
    if (idx < PA_TQ + PA_TK) {
        bool isQ = idx < PA_TQ;
        int id = isQ ? idx : idx - PA_TQ;
        int nheads = isQ ? NH : NKV;
        int d = id & 31;
        int h = (id >> 5) % nheads;
        int m = id / (32 * nheads);
        int s = m & (SS - 1);
        int b = m >> 11;
        const float* p = QKV + (size_t)m * QKVD + (isQ ? 0 : QDIM) + h * 64 + d;
        float a = p[0];
        float bb = p[32];
        int ci = s * 32 + (d >> 1);
        float c1 = cosT[ci], s1 = sinT[ci];
        float c2 = cosT[ci + 16], s2 = sinT[ci + 16];
        float ra = a * c1 - bb * s1;
        float rb = bb * c2 + a * s2;
        size_t o = ((size_t)(b * nheads + h) * SS + s) * 64 + d;
        if (isQ) {
            Qf[o] = __float2half_rn(ra * QSCALE);
            Qf[o + 32] = __float2half_rn(rb * QSCALE);
        } else {
            __half ha = __float2half_rn(ra);
            __half hb = __float2half_rn(rb);
            Kh[o] = ha;       Kh[o + 32] = hb;
            Kl[o] = __float2half_rn(ra - __half2float(ha));
            Kl[o + 32] = __float2half_rn(rb - __half2float(hb));
        }
    } else if (idx < PA_TOTAL) {
        int u = idx - PA_TQ - PA_TK;
        int d2 = u & 31;
        int kvh = (u >> 5) & 7;
        int m = u >> 8;
        int s = m & (SS - 1);
        int b = m >> 11;
        float2 v = *(const float2*)(QKV + (size_t)m * QKVD + QDIM + KVDIM + kvh * 64 + 2 * d2);
        __half2 hh;
        hh.x = __float2half_rn(v.x);
        hh.y = __float2half_rn(v.y);
        size_t o = (((size_t)(b * NKV + kvh) * SS + s) * 64 + 2 * d2) >> 1;
        ((__half2*)Vf)[o] = hh;
    }
}

// ---------------------------------------------------------------------------
// MMA flash attention v3: fp16 Q (full) x fp16 split K (2 MMA),
// fp16 P x fp16 V (1 MMA), ones-column row sums.
// grid (S/128, NH, BB), 256 threads.
// ---------------------------------------------------------------------------
#define FSTRB 144
#define FQ_BYTES (128 * FSTRB)       // 18432 (single Q array)
#define FARR (64 * FSTRB)            // 9216
#define FKV0 FQ_BYTES
#define FSTAGE (3 * FARR)            // Kh, Kl, Vf = 27648
#define FL_SMEM (FKV0 + 2 * FSTAGE)  // 73728

__global__ __launch_bounds__(256, 1) void flash_mma(
    const __half* __restrict__ Qf, const __half* __restrict__ Kh,
    const __half* __restrict__ Kl, const __half* __restrict__ Vf,
    __nv_bfloat16* __restrict__ Oh, __nv_bfloat16* __restrict__ Ol)
{
    extern __shared__ char sm[];
    const uint32_t sb = smem_u32(sm);
    const int tid = threadIdx.x;
    const int lane = tid & 31;
    const int wm = tid >> 5;
    const int qb = blockIdx.x;
    const int h = blockIdx.y;
    const int b = blockIdx.z;
    const int kvh = h >> 2;
    const int nkt = 2 * (qb + 1);

    const size_t qg = ((size_t)(b * NH + h) * SS + qb * 128) * 64;
    const size_t kg = ((size_t)(b * NKV + kvh) * SS) * 64;

    // ---- Q load (single fp16 array) ----
    {
#pragma unroll
        for (int i = 0; i < 4; i++) {
            int g = tid + i * 256;      // 0..1023
            int row = g >> 3;
            int ch = g & 7;
            cp_async16(sb + row * FSTRB + ch * 16, Qf + qg + (size_t)row * 64 + ch * 8);
        }
        asm volatile("cp.async.commit_group;" ::: "memory");
    }

#define LOADKV(kt_) do {                                                        \
    int j0_ = (kt_) * 64;                                                       \
    uint32_t stg_ = sb + FKV0 + ((kt_) & 1) * FSTAGE;                           \
    const char* karr[3] = {                                                     \
        (const char*)(Kh + kg + (size_t)j0_ * 64),                              \
        (const char*)(Kl + kg + (size_t)j0_ * 64),                              \
        (const char*)(Vf + kg + (size_t)j0_ * 64)};                             \
    _Pragma("unroll")                                                           \
    for (int i = 0; i < 6; i++) {                                               \
        int g = tid + i * 256;          /* 0..1535 */                           \
        int arr = g >> 9;                                                       \
        int w = g & 511;                                                        \
        int row = w >> 3;                                                       \
        int ch = w & 7;                                                         \
        cp_async16(stg_ + arr * FARR + row * FSTRB + ch * 16,                   \
                   karr[arr] + row * 128 + ch * 16);                            \
    }                                                                           \
    asm volatile("cp.async.commit_group;" ::: "memory");                        \
} while (0)

    LOADKV(0);
    if (nkt > 1) LOADKV(1);

    // V pad init: ones column (col 64 = 1.0h) in both stages; cp.async never
    // touches bytes [128,144) of a row so this persists across refills.
    if (tid < 128) {
        int stage = tid >> 6;
        int row = tid & 63;
        uint32_t off = FKV0 + stage * FSTAGE + 2 * FARR + row * FSTRB + 128;
        uint4 ones = {0x00003C00u, 0u, 0u, 0u};
        *(uint4*)(sm + off) = ones;
    }

    if (nkt > 1) { asm volatile("cp.async.wait_group 1;" ::: "memory"); }
    else         { asm volatile("cp.async.wait_group 0;" ::: "memory"); }
    __syncthreads();

    // ---- Q fragments (register-resident) ----
    uint32_t qf[4][4];
#pragma unroll
    for (int kk = 0; kk < 4; kk++) {
        uint32_t addr = sb + (uint32_t)((wm * 16 + (lane & 15)) * FSTRB
                                        + kk * 32 + (lane >> 4) * 16);
        ldsm4(qf[kk], addr);
    }

    float co[8][4];
#pragma unroll
    for (int i = 0; i < 8; i++)
#pragma unroll
        for (int j = 0; j < 4; j++) co[i][j] = 0.0f;
    float lacc[4] = {0.0f, 0.0f, 0.0f, 0.0f};
    float m0 = -1e30f, m1 = -1e30f;

    const int lg = lane >> 3;
    const int lr = lane & 7;
    const int qr0 = qb * 128 + wm * 16 + (lane >> 2);

    for (int kt = 0; kt < nkt; kt++) {
        if (kt > 0) {
            if (kt + 1 < nkt) { asm volatile("cp.async.wait_group 1;" ::: "memory"); }
            else              { asm volatile("cp.async.wait_group 0;" ::: "memory"); }
            __syncthreads();
        }
        const uint32_t sKh = sb + FKV0 + (kt & 1) * FSTAGE;
        const uint32_t sKl = sKh + FARR;
        const uint32_t sVf = sKh + 2 * FARR;

        // ---- S = Qf Kh^T + Qf Kl^T (2 fp16 MMAs per n8) ----
        float cs[8][4];
#pragma unroll
        for (int i = 0; i < 8; i++)
#pragma unroll
            for (int j = 0; j < 4; j++) cs[i][j] = 0.0f;

#pragma unroll
        for (int kk = 0; kk < 4; kk++) {
#pragma unroll
            for (int ng = 0; ng < 4; ng++) {
                uint32_t boff = (uint32_t)((ng * 16 + (lg >> 1) * 8 + lr) * FSTRB
                                           + kk * 32 + (lg & 1) * 16);
                uint32_t bh[4], bl[4];
                ldsm4(bh, sKh + boff);
                ldsm4(bl, sKl + boff);
                mma16816h(cs[ng * 2], qf[kk], bh);
                mma16816h(cs[ng * 2], qf[kk], bl);
                mma16816h(cs[ng * 2 + 1], qf[kk], bh + 2);
                mma16816h(cs[ng * 2 + 1], qf[kk], bl + 2);
            }
        }

        // ---- causal mask on diagonal tiles ----
        if (kt >= nkt - 2) {
            int gcol0 = kt * 64 + (lane & 3) * 2;
#pragma unroll
            for (int n = 0; n < 8; n++) {
#pragma unroll
                for (int t = 0; t < 2; t++) {
                    int col = gcol0 + n * 8 + t;
                    if (col > qr0) cs[n][t] = -1e30f;
                    if (col > qr0 + 8) cs[n][t + 2] = -1e30f;
                }
            }
        }

        // ---- online softmax (base-2), P in fp16 ----
        float mx0 = -1e30f, mx1 = -1e30f;
#pragma unroll
        for (int n = 0; n < 8; n++) {
            mx0 = fmaxf(mx0, fmaxf(cs[n][0], cs[n][1]));
            mx1 = fmaxf(mx1, fmaxf(cs[n][2], cs[n][3]));
        }
        mx0 = fmaxf(mx0, __shfl_xor_sync(0xffffffffu, mx0, 1));
        mx0 = fmaxf(mx0, __shfl_xor_sync(0xffffffffu, mx0, 2));
        mx1 = fmaxf(mx1, __shfl_xor_sync(0xffffffffu, mx1, 1));
        mx1 = fmaxf(mx1, __shfl_xor_sync(0xffffffffu, mx1, 2));
        float nm0 = fmaxf(m0, mx0);
        float nm1 = fmaxf(m1, mx1);
        float f0 = ex2f(m0 - nm0);
        float f1 = ex2f(m1 - nm1);
        m0 = nm0; m1 = nm1;

        uint32_t pp[8][2];
#pragma unroll
        for (int n = 0; n < 8; n++) {
            pp[n][0] = ex2_f16x2(pack_f16x2(cs[n][0] - nm0, cs[n][1] - nm0));
            pp[n][1] = ex2_f16x2(pack_f16x2(cs[n][2] - nm1, cs[n][3] - nm1));
        }

#pragma unroll
        for (int n = 0; n < 8; n++) {
            co[n][0] *= f0; co[n][1] *= f0;
            co[n][2] *= f1; co[n][3] *= f1;
        }
        lacc[0] *= f0; lacc[2] *= f1;

        // ---- O += P V (1 fp16 MMA per n8) + ones-column row sums ----
#pragma unroll
        for (int kk = 0; kk < 4; kk++) {
            uint32_t pa[4] = {pp[2 * kk][0], pp[2 * kk][1],
                              pp[2 * kk + 1][0], pp[2 * kk + 1][1]};
#pragma unroll
            for (int ng = 0; ng < 4; ng++) {
                uint32_t vaddr = (uint32_t)((kk * 16 + (lane & 15)) * FSTRB
                                            + (ng * 16 + (lane >> 4) * 8) * 2);
                uint32_t vf[4];
                ldsm4t(vf, sVf + vaddr);
                mma16816h(co[ng * 2], pa, vf);
                mma16816h(co[ng * 2 + 1], pa, vf + 2);
            }
            uint32_t v1[2];
            ldsm2t(v1, sVf + (uint32_t)((kk * 16 + (lane & 15)) * FSTRB + 128));
            mma16816h(lacc, pa, v1);
        }

        __syncthreads();
        if (kt + 2 < nkt) LOADKV(kt + 2);
    }

    // ---- epilogue ----
    float l0 = __shfl_sync(0xffffffffu, lacc[0], lane & ~3);
    float l1 = __shfl_sync(0xffffffffu, lacc[2], lane & ~3);
    float inv0 = 1.0f / l0;
    float inv1 = 1.0f / l1;

    int srow = qb * 128 + wm * 16 + (lane >> 2);
    size_t base0 = ((size_t)(b * SS) + srow) * QDIM + h * 64 + (lane & 3) * 2;
    size_t base1 = base0 + (size_t)8 * QDIM;
#pragma unroll
    for (int nd = 0; nd < 8; nd++) {
        uint32_t hh, ll;
        pack_split(co[nd][0] * inv0, co[nd][1] * inv0, hh, ll);
        *(uint32_t*)(Oh + base0 + nd * 8) = hh;
        *(uint32_t*)(Ol + base0 + nd * 8) = ll;
        pack_split(co[nd][2] * inv1, co[nd][3] * inv1, hh, ll);
        *(uint32_t*)(Oh + base1 + nd * 8) = hh;
        *(uint32_t*)(Ol + base1 + nd * 8) = ll;
    }
#undef LOADKV
}

// ---------------------------------------------------------------------------
// Launch: cvt_all, gemmQKV, prep_attn, flash, gemmO  (5 launches)
// ---------------------------------------------------------------------------
extern "C" void kernel_launch(void* const* d_in, const int* in_sizes, int n_in,
                              void* d_out, int out_size) {
    const float* x = (const float*)d_in[0];
    const float* wq = (const float*)d_in[1];
    const float* wk = (const float*)d_in[2];
    const float* wv = (const float*)d_in[3];
    const float* wo = (const float*)d_in[4];
    const float* cosT = (const float*)d_in[5];
    const float* sinT = (const float*)d_in[6];
    float* out = (float*)d_out;

    float* QKVp;
    __nv_bfloat16 *xh, *xl, *Wch, *Wcl, *Woh, *Wol, *Oh, *Ol;
    __half *Qf, *Kh, *Kl, *Vf;
    cudaGetSymbolAddress((void**)&QKVp, g_QKV);
    cudaGetSymbolAddress((void**)&xh, g_xh);
    cudaGetSymbolAddress((void**)&xl, g_xl);
    cudaGetSymbolAddress((void**)&Wch, g_Wch);
    cudaGetSymbolAddress((void**)&Wcl, g_Wcl);
    cudaGetSymbolAddress((void**)&Woh, g_Woh);
    cudaGetSymbolAddress((void**)&Wol, g_Wol);
    cudaGetSymbolAddress((void**)&Qf, g_Qf);
    cudaGetSymbolAddress((void**)&Kh, g_Kh);
    cudaGetSymbolAddress((void**)&Kl, g_Kl);
    cudaGetSymbolAddress((void**)&Vf, g_Vf);
    cudaGetSymbolAddress((void**)&Oh, g_Oh);
    cudaGetSymbolAddress((void**)&Ol, g_Ol);

    cudaFuncSetAttribute(gemm_tc, cudaFuncAttributeMaxDynamicSharedMemorySize,
                         G2_SMEM_TOTAL);
    cudaFuncSetAttribute(flash_mma, cudaFuncAttributeMaxDynamicSharedMemorySize,
                         FL_SMEM);

    // 1. All input splits
    cvt_all<<<(CV_TOTAL + 255) / 256, 256>>>(x, wq, wk, wv, wo,
                                             xh, xl, Wch, Wcl, Woh, Wol);

    // 2. Fused QKV projection: [4096,3072]
    gemm_tc<<<dim3(QKVD / 128, MTOT / 256), 256, G2_SMEM_TOTAL>>>(
        xh, xl, Wch, Wcl, QKVp, QKVD, DM);

    // 3. RoPE + fp16 conversion + per-head relayout
    prep_attn<<<(PA_TOTAL + 255) / 256, 256>>>(QKVp, cosT, sinT, Qf, Kh, Kl, Vf);

    // 4. Attention (writes split O directly)
    flash_mma<<<dim3(SS / 128, NH, BB), 256, FL_SMEM>>>(Qf, Kh, Kl, Vf, Oh, Ol);

    // 5. Output projection
    gemm_tc<<<dim3(DM / 128, MTOT / 256), 256, G2_SMEM_TOTAL>>>(
        Oh, Ol, Woh, Wol, out, DM, QDIM);
}

// round 10
// speedup vs baseline: 8.1995x; 1.2343x over previous
#include <cuda_runtime.h>
#include <cuda_bf16.h>
#include <cuda_fp16.h>
#include <math.h>
#include <stdint.h>

// Problem constants
#define BB 2
#define SS 2048
#define DM 2048
#define NH 32
#define NKV 8
#define HD 64
#define MTOT (BB * SS)          // 4096
#define QDIM (NH * HD)          // 2048
#define KVDIM (NKV * HD)        // 512
#define QKVD (QDIM + 2 * KVDIM) // 3072

// scale/log2 fold: (1/sqrt(64)) * log2(e)
#define QSCALE 0.18033688011112042f

// ---------------------------------------------------------------------------
// Scratch (device globals)
// ---------------------------------------------------------------------------
__device__ float g_QKV[MTOT * QKVD];            // 48 MB
__device__ __half g_xh[MTOT * DM];              // x fp16 split
__device__ __half g_xl[MTOT * DM];
__device__ __half g_Wc[QKVD * DM];              // [wq;wk;wv] fp16 full
__device__ __half g_Wof[DM * QDIM];             // wo fp16 full
// per-head attention operands [b][h][s][64]
__device__ __half g_Qf[BB * NH * SS * HD];      // fp16, QSCALE folded
__device__ __half g_Kh[BB * NKV * SS * HD];     // fp16 hi
__device__ __half g_Kl[BB * NKV * SS * HD];     // fp16 residual
__device__ __half g_Vf[BB * NKV * SS * HD];     // fp16
// attention output fp16 split, [b][s][2048] (GEMM-ready)
__device__ __half g_Oh[MTOT * QDIM];
__device__ __half g_Ol[MTOT * QDIM];

// ---------------------------------------------------------------------------
// PTX helpers
// ---------------------------------------------------------------------------
__device__ __forceinline__ uint32_t smem_u32(const void* p) {
    uint32_t a;
    asm("{ .reg .u64 t; cvta.to.shared.u64 t, %1; cvt.u32.u64 %0, t; }" : "=r"(a) : "l"(p));
    return a;
}
__device__ __forceinline__ void ldsm4(uint32_t* r, uint32_t addr) {
    asm volatile("ldmatrix.sync.aligned.m8n8.x4.shared.b16 {%0,%1,%2,%3}, [%4];"
                 : "=r"(r[0]), "=r"(r[1]), "=r"(r[2]), "=r"(r[3]) : "r"(addr));
}
__device__ __forceinline__ void ldsm4t(uint32_t* r, uint32_t addr) {
    asm volatile("ldmatrix.sync.aligned.m8n8.x4.trans.shared.b16 {%0,%1,%2,%3}, [%4];"
                 : "=r"(r[0]), "=r"(r[1]), "=r"(r[2]), "=r"(r[3]) : "r"(addr));
}
__device__ __forceinline__ void ldsm2t(uint32_t* r, uint32_t addr) {
    asm volatile("ldmatrix.sync.aligned.m8n8.x2.trans.shared.b16 {%0,%1}, [%2];"
                 : "=r"(r[0]), "=r"(r[1]) : "r"(addr));
}
__device__ __forceinline__ void mma16816h(float* c, const uint32_t* a, const uint32_t* b) {
    asm volatile(
        "mma.sync.aligned.m16n8k16.row.col.f32.f16.f16.f32 "
        "{%0,%1,%2,%3}, {%4,%5,%6,%7}, {%8,%9}, {%0,%1,%2,%3};"
        : "+f"(c[0]), "+f"(c[1]), "+f"(c[2]), "+f"(c[3])
        : "r"(a[0]), "r"(a[1]), "r"(a[2]), "r"(a[3]), "r"(b[0]), "r"(b[1]));
}
__device__ __forceinline__ void cp_async16(uint32_t saddr, const void* gaddr) {
    asm volatile("cp.async.cg.shared.global [%0], [%1], 16;" :: "r"(saddr), "l"(gaddr));
}
__device__ __forceinline__ float ex2f(float x) {
    float y;
    asm("ex2.approx.ftz.f32 %0, %1;" : "=f"(y) : "f"(x));
    return y;
}
__device__ __forceinline__ uint32_t pack_f16x2(float lo, float hi) {
    uint32_t d;
    asm("cvt.rn.f16x2.f32 %0, %1, %2;" : "=r"(d) : "f"(hi), "f"(lo));
    return d;
}
__device__ __forceinline__ uint32_t ex2_f16x2(uint32_t x) {
    uint32_t y;
    asm("ex2.approx.f16x2 %0, %1;" : "=r"(y) : "r"(x));
    return y;
}
// fp16 hi/lo split of a float pair
__device__ __forceinline__ void pack_split_h(float x, float y, uint32_t& hi, uint32_t& lo) {
    __half2 h = __floats2half2_rn(x, y);
    float rx = x - __half2float(__low2half(h));
    float ry = y - __half2float(__high2half(h));
    __half2 l = __floats2half2_rn(rx, ry);
    hi = *(uint32_t*)&h;
    lo = *(uint32_t*)&l;
}

// ---------------------------------------------------------------------------
// fp16 2-term GEMM: C[M,NN] = (A0+A1)[M,K] * B[NN,K]^T  (all fp16, fp32 acc)
// CTA 256x128, BK=32, 256 threads (8 warps 4m x 2n), 2-stage cp.async.
// ---------------------------------------------------------------------------
#define GA_ARR 20480                   // 256 rows * 80 B
#define GB_ARR 10240                   // 128 rows * 80 B
#define GB_OFF (2 * GA_ARR)            // 40960
#define G_STAGE (2 * GA_ARR + GB_ARR)  // 51200
#define G_SMEM_TOTAL (2 * G_STAGE)     // 102400

__global__ __launch_bounds__(256, 1) void gemm2(
    const __half* __restrict__ A0, const __half* __restrict__ A1,
    const __half* __restrict__ B, float* __restrict__ C, int NN, int K)
{
    extern __shared__ char smem[];
    const uint32_t sb = smem_u32(smem);
    const int tid = threadIdx.x;
    const int wid = tid >> 5;
    const int lane = tid & 31;
    const int wm = wid & 3;
    const int wn = wid >> 2;
    const int m0 = blockIdx.y * 256;
    const int n0 = blockIdx.x * 128;

    const __half* const Aarr[2] = {A0 + (size_t)m0 * K, A1 + (size_t)m0 * K};
    const __half* const Bp = B + (size_t)n0 * K;

    float acc[4][8][4];
#pragma unroll
    for (int i = 0; i < 4; i++)
#pragma unroll
        for (int j = 0; j < 8; j++)
#pragma unroll
            for (int q = 0; q < 4; q++) acc[i][j][q] = 0.0f;

    const int NC = K / 32;
    const int lg = lane >> 3;
    const int lr = lane & 7;

#define LOADSTAGE(cc) do {                                                     \
    const uint32_t stg = ((cc) & 1) ? G_STAGE : 0;                             \
    const int k0 = (cc) * 32;                                                  \
    _Pragma("unroll")                                                          \
    for (int i = 0; i < 10; i++) {                                             \
        int gidx = tid + i * 256;                                              \
        if (gidx < 2048) {                                                     \
            int arr = gidx >> 10;                                              \
            int w = gidx & 1023;                                               \
            int row = w >> 2;                                                  \
            int q = w & 3;                                                     \
            cp_async16(sb + stg + arr * GA_ARR + row * 80 + q * 16,            \
                       Aarr[arr] + (size_t)row * K + k0 + q * 8);              \
        } else {                                                               \
            int w = gidx - 2048;       /* 0..511 */                            \
            int row = w >> 2;                                                  \
            int q = w & 3;                                                     \
            cp_async16(sb + stg + GB_OFF + row * 80 + q * 16,                  \
                       Bp + (size_t)row * K + k0 + q * 8);                     \
        }                                                                      \
    }                                                                          \
    asm volatile("cp.async.commit_group;" ::: "memory");                       \
} while (0)

    LOADSTAGE(0);

    for (int c = 0; c < NC; c++) {
        asm volatile("cp.async.wait_group 0;" ::: "memory");
        __syncthreads();
        if (c + 1 < NC) LOADSTAGE(c + 1);

        const uint32_t stg = sb + ((c & 1) ? G_STAGE : 0);
        const uint32_t sA0 = stg;
        const uint32_t sA1 = stg + GA_ARR;
        const uint32_t sB = stg + GB_OFF;

#pragma unroll
        for (int kk = 0; kk < 2; kk++) {
            const int kbyte = kk * 32;
            uint32_t fA0[4][4], fA1[4][4];
#pragma unroll
            for (int mt = 0; mt < 4; mt++) {
                int arow = wm * 64 + mt * 16 + (lg & 1) * 8 + lr;
                uint32_t aoff = (uint32_t)(arow * 80 + kbyte + (lg >> 1) * 16);
                ldsm4(fA0[mt], sA0 + aoff);
                ldsm4(fA1[mt], sA1 + aoff);
            }
#pragma unroll
            for (int np = 0; np < 4; np++) {
                int brow = wn * 64 + np * 16 + (lg >> 1) * 8 + lr;
                uint32_t boff = (uint32_t)(brow * 80 + kbyte + (lg & 1) * 16);
                uint32_t fB[4];
                ldsm4(fB, sB + boff);
#pragma unroll
                for (int mt = 0; mt < 4; mt++) {
                    mma16816h(acc[mt][np * 2], fA0[mt], fB);
                    mma16816h(acc[mt][np * 2], fA1[mt], fB);
                    mma16816h(acc[mt][np * 2 + 1], fA0[mt], fB + 2);
                    mma16816h(acc[mt][np * 2 + 1], fA1[mt], fB + 2);
                }
            }
        }
        __syncthreads();
    }

#pragma unroll
    for (int mt = 0; mt < 4; mt++) {
        int row0 = m0 + wm * 64 + mt * 16 + (lane >> 2);
#pragma unroll
        for (int nt = 0; nt < 8; nt++) {
            int col = n0 + wn * 64 + nt * 8 + (lane & 3) * 2;
            float2 v0 = {acc[mt][nt][0], acc[mt][nt][1]};
            float2 v1 = {acc[mt][nt][2], acc[mt][nt][3]};
            *(float2*)(C + (size_t)row0 * NN + col) = v0;
            *(float2*)(C + (size_t)(row0 + 8) * NN + col) = v1;
        }
    }
#undef LOADSTAGE
}

// ---------------------------------------------------------------------------
// cvt_all: x -> fp16 split; [wq;wk;wv] -> fp16 full; wo -> fp16 full
// ---------------------------------------------------------------------------
#define CV_NX (MTOT * DM / 2)
#define CV_NQ (QDIM * DM / 2)
#define CV_NK (KVDIM * DM / 2)
#define CV_NO (DM * QDIM / 2)
#define CV_TOTAL (CV_NX + CV_NQ + 2 * CV_NK + CV_NO)

__global__ void cvt_all(const float* __restrict__ x, const float* __restrict__ wq,
                        const float* __restrict__ wk, const float* __restrict__ wv,
                        const float* __restrict__ wo,
                        __half* __restrict__ xh, __half* __restrict__ xl,
                        __half* __restrict__ Wc, __half* __restrict__ Wof) {
    int i = blockIdx.x * blockDim.x + threadIdx.x;
    if (i < CV_NX) {
        float2 v = ((const float2*)x)[i];
        uint32_t h, l;
        pack_split_h(v.x, v.y, h, l);
        ((uint32_t*)xh)[i] = h;
        ((uint32_t*)xl)[i] = l;
        return;
    }
    const float* src;
    __half* dst;
    int off;
    if (i < CV_NX + CV_NQ) { src = wq; dst = Wc; off = i - CV_NX; }
    else if (i < CV_NX + CV_NQ + CV_NK) {
        src = wk; dst = Wc + (size_t)QDIM * DM; off = i - CV_NX - CV_NQ;
    } else if (i < CV_NX + CV_NQ + 2 * CV_NK) {
        src = wv; dst = Wc + (size_t)(QDIM + KVDIM) * DM; off = i - CV_NX - CV_NQ - CV_NK;
    } else if (i < CV_TOTAL) {
        src = wo; dst = Wof; off = i - CV_NX - CV_NQ - 2 * CV_NK;
    } else return;
    float2 v = ((const float2*)src)[off];
    ((__half2*)dst)[off] = __floats2half2_rn(v.x, v.y);
}

// ---------------------------------------------------------------------------
// prep_attn: RoPE(Q->fp16 w/ QSCALE; K->fp16 split) + V->fp16, per-head layout
// ---------------------------------------------------------------------------
#define PA_TQ (MTOT * NH * 32)
#define PA_TK (MTOT * NKV * 32)
#define PA_TV (MTOT * NKV * 32)
#define PA_TOTAL (PA_TQ + PA_TK + PA_TV)

__global__ void prep_attn(const float* __restrict__ QKV,
                          const float* __restrict__ cosT, const float* __restrict__ sinT,
                          __half* __restrict__ Qf, __half* __restrict__ Kh,
                          __half* __restrict__ Kl, __half* __restrict__ Vf) {
    int idx = blockIdx.x * blockDim.x + threadIdx.x;
    if (idx < PA_TQ + PA_TK) {
        bool isQ = idx < PA_TQ;
        int id = isQ ? idx : idx - PA_TQ;
        int nheads = isQ ? NH : NKV;
        int d = id & 31;
        int h = (id >> 5) % nheads;
        int m = id / (32 * nheads);
        int s = m & (SS - 1);
        int b = m >> 11;
        const float* p = QKV + (size_t)m * QKVD + (isQ ? 0 : QDIM) + h * 64 + d;
        float a = p[0];
        float bb = p[32];
        int ci = s * 32 + (d >> 1);
        float c1 = cosT[ci], s1 = sinT[ci];
        float c2 = cosT[ci + 16], s2 = sinT[ci + 16];
        float ra = a * c1 - bb * s1;
        float rb = bb * c2 + a * s2;
        size_t o = ((size_t)(b * nheads + h) * SS + s) * 64 + d;
        if (isQ) {
            Qf[o] = __float2half_rn(ra * QSCALE);
            Qf[o + 32] = __float2half_rn(rb * QSCALE);
        } else {
            __half ha = __float2half_rn(ra);
            __half hb = __float2half_rn(rb);
            Kh[o] = ha;       Kh[o + 32] = hb;
            Kl[o] = __float2half_rn(ra - __half2float(ha));
            Kl[o + 32] = __float2half_rn(rb - __half2float(hb));
        }
    } else if (idx < PA_TOTAL) {
        int u = idx - PA_TQ - PA_TK;
        int d2 = u & 31;
        int kvh = (u >> 5) & 7;
        int m = u >> 8;
        int s = m & (SS - 1);
        int b = m >> 11;
        float2 v = *(const float2*)(QKV + (size_t)m * QKVD + QDIM + KVDIM + kvh * 64 + 2 * d2);
        __half2 hh;
        hh.x = __float2half_rn(v.x);
        hh.y = __float2half_rn(v.y);
        size_t o = (((size_t)(b * NKV + kvh) * SS + s) * 64 + 2 * d2) >> 1;
        ((__half2*)Vf)[o] = hh;
    }
}

// ---------------------------------------------------------------------------
// MMA flash attention v3 (validated R9): fp16 Q x fp16 split K (2 MMA),
// fp16 P x fp16 V (1 MMA), ones-column row sums. Epilogue writes fp16 split O.
// grid (S/128, NH, BB), 256 threads.
// ---------------------------------------------------------------------------
#define FSTRB 144
#define FQ_BYTES (128 * FSTRB)       // 18432
#define FARR (64 * FSTRB)            // 9216
#define FKV0 FQ_BYTES
#define FSTAGE (3 * FARR)            // 27648
#define FL_SMEM (FKV0 + 2 * FSTAGE)  // 73728

__global__ __launch_bounds__(256, 1) void flash_mma(
    const __half* __restrict__ Qf, const __half* __restrict__ Kh,
    const __half* __restrict__ Kl, const __half* __restrict__ Vf,
    __half* __restrict__ Oh, __half* __restrict__ Ol)
{
    extern __shared__ char sm[];
    const uint32_t sb = smem_u32(sm);
    const int tid = threadIdx.x;
    const int lane = tid & 31;
    const int wm = tid >> 5;
    const int qb = blockIdx.x;
    const int h = blockIdx.y;
    const int b = blockIdx.z;
    const int kvh = h >> 2;
    const int nkt = 2 * (qb + 1);

    const size_t qg = ((size_t)(b * NH + h) * SS + qb * 128) * 64;
    const size_t kg = ((size_t)(b * NKV + kvh) * SS) * 64;

    {
#pragma unroll
        for (int i = 0; i < 4; i++) {
            int g = tid + i * 256;
            int row = g >> 3;
            int ch = g & 7;
            cp_async16(sb + row * FSTRB + ch * 16, Qf + qg + (size_t)row * 64 + ch * 8);
        }
        asm volatile("cp.async.commit_group;" ::: "memory");
    }

#define LOADKV(kt_) do {                                                        \
    int j0_ = (kt_) * 64;                                                       \
    uint32_t stg_ = sb + FKV0 + ((kt_) & 1) * FSTAGE;                           \
    const char* karr[3] = {                                                     \
        (const char*)(Kh + kg + (size_t)j0_ * 64),                              \
        (const char*)(Kl + kg + (size_t)j0_ * 64),                              \
        (const char*)(Vf + kg + (size_t)j0_ * 64)};                             \
    _Pragma("unroll")                                                           \
    for (int i = 0; i < 6; i++) {                                               \
        int g = tid + i * 256;                                                  \
        int arr = g >> 9;                                                       \
        int w = g & 511;                                                        \
        int row = w >> 3;                                                       \
        int ch = w & 7;                                                         \
        cp_async16(stg_ + arr * FARR + row * FSTRB + ch * 16,                   \
                   karr[arr] + row * 128 + ch * 16);                            \
    }                                                                           \
    asm volatile("cp.async.commit_group;" ::: "memory");                        \
} while (0)

    LOADKV(0);
    if (nkt > 1) LOADKV(1);

    if (tid < 128) {
        int stage = tid >> 6;
        int row = tid & 63;
        uint32_t off = FKV0 + stage * FSTAGE + 2 * FARR + row * FSTRB + 128;
        uint4 ones = {0x00003C00u, 0u, 0u, 0u};
        *(uint4*)(sm + off) = ones;
    }

    if (nkt > 1) { asm volatile("cp.async.wait_group 1;" ::: "memory"); }
    else         { asm volatile("cp.async.wait_group 0;" ::: "memory"); }
    __syncthreads();

    uint32_t qf[4][4];
#pragma unroll
    for (int kk = 0; kk < 4; kk++) {
        uint32_t addr = sb + (uint32_t)((wm * 16 + (lane & 15)) * FSTRB
                                        + kk * 32 + (lane >> 4) * 16);
        ldsm4(qf[kk], addr);
    }

    float co[8][4];
#pragma unroll
    for (int i = 0; i < 8; i++)
#pragma unroll
        for (int j = 0; j < 4; j++) co[i][j] = 0.0f;
    float lacc[4] = {0.0f, 0.0f, 0.0f, 0.0f};
    float m0 = -1e30f, m1 = -1e30f;

    const int lg = lane >> 3;
    const int lr = lane & 7;
    const int qr0 = qb * 128 + wm * 16 + (lane >> 2);

    for (int kt = 0; kt < nkt; kt++) {
        if (kt > 0) {
            if (kt + 1 < nkt) { asm volatile("cp.async.wait_group 1;" ::: "memory"); }
            else              { asm volatile("cp.async.wait_group 0;" ::: "memory"); }
            __syncthreads();
        }
        const uint32_t sKh = sb + FKV0 + (kt & 1) * FSTAGE;
        const uint32_t sKl = sKh + FARR;
        const uint32_t sVf = sKh + 2 * FARR;

        float cs[8][4];
#pragma unroll
        for (int i = 0; i < 8; i++)
#pragma unroll
            for (int j = 0; j < 4; j++) cs[i][j] = 0.0f;

#pragma unroll
        for (int kk = 0; kk < 4; kk++) {
#pragma unroll
            for (int ng = 0; ng < 4; ng++) {
                uint32_t boff = (uint32_t)((ng * 16 + (lg >> 1) * 8 + lr) * FSTRB
                                           + kk * 32 + (lg & 1) * 16);
                uint32_t bh[4], bl[4];
                ldsm4(bh, sKh + boff);
                ldsm4(bl, sKl + boff);
                mma16816h(cs[ng * 2], qf[kk], bh);
                mma16816h(cs[ng * 2], qf[kk], bl);
                mma16816h(cs[ng * 2 + 1], qf[kk], bh + 2);
                mma16816h(cs[ng * 2 + 1], qf[kk], bl + 2);
            }
        }

        if (kt >= nkt - 2) {
            int gcol0 = kt * 64 + (lane & 3) * 2;
#pragma unroll
            for (int n = 0; n < 8; n++) {
#pragma unroll
                for (int t = 0; t < 2; t++) {
                    int col = gcol0 + n * 8 + t;
                    if (col > qr0) cs[n][t] = -1e30f;
                    if (col > qr0 + 8) cs[n][t + 2] = -1e30f;
                }
            }
        }

        float mx0 = -1e30f, mx1 = -1e30f;
#pragma unroll
        for (int n = 0; n < 8; n++) {
            mx0 = fmaxf(mx0, fmaxf(cs[n][0], cs[n][1]));
            mx1 = fmaxf(mx1, fmaxf(cs[n][2], cs[n][3]));
        }
        mx0 = fmaxf(mx0, __shfl_xor_sync(0xffffffffu, mx0, 1));
        mx0 = fmaxf(mx0, __shfl_xor_sync(0xffffffffu, mx0, 2));
        mx1 = fmaxf(mx1, __shfl_xor_sync(0xffffffffu, mx1, 1));
        mx1 = fmaxf(mx1, __shfl_xor_sync(0xffffffffu, mx1, 2));
        float nm0 = fmaxf(m0, mx0);
        float nm1 = fmaxf(m1, mx1);
        float f0 = ex2f(m0 - nm0);
        float f1 = ex2f(m1 - nm1);
        m0 = nm0; m1 = nm1;

        uint32_t pp[8][2];
#pragma unroll
        for (int n = 0; n < 8; n++) {
            pp[n][0] = ex2_f16x2(pack_f16x2(cs[n][0] - nm0, cs[n][1] - nm0));
            pp[n][1] = ex2_f16x2(pack_f16x2(cs[n][2] - nm1, cs[n][3] - nm1));
        }

#pragma unroll
        for (int n = 0; n < 8; n++) {
            co[n][0] *= f0; co[n][1] *= f0;
            co[n][2] *= f1; co[n][3] *= f1;
        }
        lacc[0] *= f0; lacc[2] *= f1;

#pragma unroll
        for (int kk = 0; kk < 4; kk++) {
            uint32_t pa[4] = {pp[2 * kk][0], pp[2 * kk][1],
                              pp[2 * kk + 1][0], pp[2 * kk + 1][1]};
#pragma unroll
            for (int ng = 0; ng < 4; ng++) {
                uint32_t vaddr = (uint32_t)((kk * 16 + (lane & 15)) * FSTRB
                                            + (ng * 16 + (lane >> 4) * 8) * 2);
                uint32_t vf[4];
                ldsm4t(vf, sVf + vaddr);
                mma16816h(co[ng * 2], pa, vf);
                mma16816h(co[ng * 2 + 1], pa, vf + 2);
            }
            uint32_t v1[2];
            ldsm2t(v1, sVf + (uint32_t)((kk * 16 + (lane & 15)) * FSTRB + 128));
            mma16816h(lacc, pa, v1);
        }

        __syncthreads();
        if (kt + 2 < nkt) LOADKV(kt + 2);
    }

    float l0 = __shfl_sync(0xffffffffu, lacc[0], lane & ~3);
    float l1 = __shfl_sync(0xffffffffu, lacc[2], lane & ~3);
    float inv0 = 1.0f / l0;
    float inv1 = 1.0f / l1;

    int srow = qb * 128 + wm * 16 + (lane >> 2);
    size_t base0 = ((size_t)(b * SS) + srow) * QDIM + h * 64 + (lane & 3) * 2;
    size_t base1 = base0 + (size_t)8 * QDIM;
#pragma unroll
    for (int nd = 0; nd < 8; nd++) {
        uint32_t hh, ll;
        pack_split_h(co[nd][0] * inv0, co[nd][1] * inv0, hh, ll);
        *(uint32_t*)(Oh + base0 + nd * 8) = hh;
        *(uint32_t*)(Ol + base0 + nd * 8) = ll;
        pack_split_h(co[nd][2] * inv1, co[nd][3] * inv1, hh, ll);
        *(uint32_t*)(Oh + base1 + nd * 8) = hh;
        *(uint32_t*)(Ol + base1 + nd * 8) = ll;
    }
#undef LOADKV
}

// ---------------------------------------------------------------------------
// Launch: cvt_all, gemmQKV, prep_attn, flash, gemmO  (5 launches)
// ---------------------------------------------------------------------------
extern "C" void kernel_launch(void* const* d_in, const int* in_sizes, int n_in,
                              void* d_out, int out_size) {
    const float* x = (const float*)d_in[0];
    const float* wq = (const float*)d_in[1];
    const float* wk = (const float*)d_in[2];
    const float* wv = (const float*)d_in[3];
    const float* wo = (const float*)d_in[4];
    const float* cosT = (const float*)d_in[5];
    const float* sinT = (const float*)d_in[6];
    float* out = (float*)d_out;

    float* QKVp;
    __half *xh, *xl, *Wc, *Wof, *Qf, *Kh, *Kl, *Vf, *Oh, *Ol;
    cudaGetSymbolAddress((void**)&QKVp, g_QKV);
    cudaGetSymbolAddress((void**)&xh, g_xh);
    cudaGetSymbolAddress((void**)&xl, g_xl);
    cudaGetSymbolAddress((void**)&Wc, g_Wc);
    cudaGetSymbolAddress((void**)&Wof, g_Wof);
    cudaGetSymbolAddress((void**)&Qf, g_Qf);
    cudaGetSymbolAddress((void**)&Kh, g_Kh);
    cudaGetSymbolAddress((void**)&Kl, g_Kl);
    cudaGetSymbolAddress((void**)&Vf, g_Vf);
    cudaGetSymbolAddress((void**)&Oh, g_Oh);
    cudaGetSymbolAddress((void**)&Ol, g_Ol);

    cudaFuncSetAttribute(gemm2, cudaFuncAttributeMaxDynamicSharedMemorySize,
                         G_SMEM_TOTAL);
    cudaFuncSetAttribute(flash_mma, cudaFuncAttributeMaxDynamicSharedMemorySize,
                         FL_SMEM);

    // 1. All input conversions
    cvt_all<<<(CV_TOTAL + 255) / 256, 256>>>(x, wq, wk, wv, wo, xh, xl, Wc, Wof);

    // 2. Fused QKV projection: [4096,3072] = (xh+xl) @ Wc^T
    gemm2<<<dim3(QKVD / 128, MTOT / 256), 256, G_SMEM_TOTAL>>>(
        xh, xl, Wc, QKVp, QKVD, DM);

    // 3. RoPE + fp16 conversion + per-head relayout
    prep_attn<<<(PA_TOTAL + 255) / 256, 256>>>(QKVp, cosT, sinT, Qf, Kh, Kl, Vf);

    // 4. Attention (writes fp16 split O)
    flash_mma<<<dim3(SS / 128, NH, BB), 256, FL_SMEM>>>(Qf, Kh, Kl, Vf, Oh, Ol);

    // 5. Output projection: out = (Oh+Ol) @ Wof^T
    gemm2<<<dim3(DM / 128, MTOT / 256), 256, G_SMEM_TOTAL>>>(
        Oh, Ol, Wof, out, DM, QDIM);
}

// round 12
// speedup vs baseline: 8.2593x; 1.0073x over previous
#include <cuda_runtime.h>
#include <cuda_bf16.h>
#include <cuda_fp16.h>
#include <math.h>
#include <stdint.h>

// Problem constants
#define BB 2
#define SS 2048
#define DM 2048
#define NH 32
#define NKV 8
#define HD 64
#define MTOT (BB * SS)          // 4096
#define QDIM (NH * HD)          // 2048
#define KVDIM (NKV * HD)        // 512
#define QKVD (QDIM + 2 * KVDIM) // 3072

// scale/log2 fold: (1/sqrt(64)) * log2(e)
#define QSCALE 0.18033688011112042f

// ---------------------------------------------------------------------------
// Scratch (device globals)
// ---------------------------------------------------------------------------
__device__ __half g_xh[MTOT * DM];              // x fp16 split
__device__ __half g_xl[MTOT * DM];
__device__ __half g_Wc[QKVD * DM];              // [wq;wk;wv] fp16 full
__device__ __half g_Wof[DM * QDIM];             // wo fp16 full
// per-head attention operands [b][h][s][64]
__device__ __half g_Qf[BB * NH * SS * HD];      // fp16, QSCALE folded
__device__ __half g_Kh[BB * NKV * SS * HD];     // fp16 hi
__device__ __half g_Kl[BB * NKV * SS * HD];     // fp16 residual
__device__ __half g_Vf[BB * NKV * SS * HD];     // fp16
// attention output fp16 split, [b][s][2048] (GEMM-ready)
__device__ __half g_Oh[MTOT * QDIM];
__device__ __half g_Ol[MTOT * QDIM];

// ---------------------------------------------------------------------------
// PTX helpers
// ---------------------------------------------------------------------------
__device__ __forceinline__ uint32_t smem_u32(const void* p) {
    uint32_t a;
    asm("{ .reg .u64 t; cvta.to.shared.u64 t, %1; cvt.u32.u64 %0, t; }" : "=r"(a) : "l"(p));
    return a;
}
__device__ __forceinline__ void ldsm4(uint32_t* r, uint32_t addr) {
    asm volatile("ldmatrix.sync.aligned.m8n8.x4.shared.b16 {%0,%1,%2,%3}, [%4];"
                 : "=r"(r[0]), "=r"(r[1]), "=r"(r[2]), "=r"(r[3]) : "r"(addr));
}
__device__ __forceinline__ void ldsm4t(uint32_t* r, uint32_t addr) {
    asm volatile("ldmatrix.sync.aligned.m8n8.x4.trans.shared.b16 {%0,%1,%2,%3}, [%4];"
                 : "=r"(r[0]), "=r"(r[1]), "=r"(r[2]), "=r"(r[3]) : "r"(addr));
}
__device__ __forceinline__ void ldsm2t(uint32_t* r, uint32_t addr) {
    asm volatile("ldmatrix.sync.aligned.m8n8.x2.trans.shared.b16 {%0,%1}, [%2];"
                 : "=r"(r[0]), "=r"(r[1]) : "r"(addr));
}
__device__ __forceinline__ void mma16816h(float* c, const uint32_t* a, const uint32_t* b) {
    asm volatile(
        "mma.sync.aligned.m16n8k16.row.col.f32.f16.f16.f32 "
        "{%0,%1,%2,%3}, {%4,%5,%6,%7}, {%8,%9}, {%0,%1,%2,%3};"
        : "+f"(c[0]), "+f"(c[1]), "+f"(c[2]), "+f"(c[3])
        : "r"(a[0]), "r"(a[1]), "r"(a[2]), "r"(a[3]), "r"(b[0]), "r"(b[1]));
}
__device__ __forceinline__ void cp_async16(uint32_t saddr, const void* gaddr) {
    asm volatile("cp.async.cg.shared.global [%0], [%1], 16;" :: "r"(saddr), "l"(gaddr));
}
__device__ __forceinline__ float ex2f(float x) {
    float y;
    asm("ex2.approx.ftz.f32 %0, %1;" : "=f"(y) : "f"(x));
    return y;
}
__device__ __forceinline__ uint32_t pack_f16x2(float lo, float hi) {
    uint32_t d;
    asm("cvt.rn.f16x2.f32 %0, %1, %2;" : "=r"(d) : "f"(hi), "f"(lo));
    return d;
}
__device__ __forceinline__ uint32_t ex2_f16x2(uint32_t x) {
    uint32_t y;
    asm("ex2.approx.f16x2 %0, %1;" : "=r"(y) : "r"(x));
    return y;
}
__device__ __forceinline__ void pack_split_h(float x, float y, uint32_t& hi, uint32_t& lo) {
    __half2 h = __floats2half2_rn(x, y);
    float rx = x - __half2float(__low2half(h));
    float ry = y - __half2float(__high2half(h));
    __half2 l = __floats2half2_rn(rx, ry);
    hi = *(uint32_t*)&h;
    lo = *(uint32_t*)&l;
}

// ---------------------------------------------------------------------------
// fp16 2-term GEMM: C = (A0+A1)[M,K] * B[NN,K]^T  (fp32 acc)
// CTA 256x128, BK=32, 256 threads (8 warps 4m x 2n), 2-stage cp.async.
// MODE 0: write fp32 C.  MODE 1 (QKV): fused RoPE + fp16 convert + per-head
// relayout epilogue writing Qf/Kh/Kl/Vf directly (no fp32 intermediate).
// ---------------------------------------------------------------------------
#define GA_ARR 20480                   // 256 rows * 80 B
#define GB_ARR 10240                   // 128 rows * 80 B
#define GB_OFF (2 * GA_ARR)            // 40960
#define G_STAGE (2 * GA_ARR + GB_ARR)  // 51200
#define G_SMEM_TOTAL (2 * G_STAGE)     // 102400

template <int MODE>
__global__ __launch_bounds__(256, 1) void gemm2(
    const __half* __restrict__ A0, const __half* __restrict__ A1,
    const __half* __restrict__ B, float* __restrict__ C, int NN, int K,
    const float* __restrict__ cosT, const float* __restrict__ sinT,
    __half* __restrict__ Qf, __half* __restrict__ Kh,
    __half* __restrict__ Kl, __half* __restrict__ Vf)
{
    extern __shared__ char smem[];
    const uint32_t sb = smem_u32(smem);
    const int tid = threadIdx.x;
    const int wid = tid >> 5;
    const int lane = tid & 31;
    const int wm = wid & 3;
    const int wn = wid >> 2;
    const int m0 = blockIdx.y * 256;
    const int n0 = blockIdx.x * 128;

    const __half* const Aarr[2] = {A0 + (size_t)m0 * K, A1 + (size_t)m0 * K};
    const __half* const Bp = B + (size_t)n0 * K;

    float acc[4][8][4];
#pragma unroll
    for (int i = 0; i < 4; i++)
#pragma unroll
        for (int j = 0; j < 8; j++)
#pragma unroll
            for (int q = 0; q < 4; q++) acc[i][j][q] = 0.0f;

    const int NC = K / 32;
    const int lg = lane >> 3;
    const int lr = lane & 7;

#define LOADSTAGE(cc) do {                                                     \
    const uint32_t stg = ((cc) & 1) ? G_STAGE : 0;                             \
    const int k0 = (cc) * 32;                                                  \
    _Pragma("unroll")                                                          \
    for (int i = 0; i < 10; i++) {                                             \
        int gidx = tid + i * 256;                                              \
        if (gidx < 2048) {                                                     \
            int arr = gidx >> 10;                                              \
            int w = gidx & 1023;                                               \
            int row = w >> 2;                                                  \
            int q = w & 3;                                                     \
            cp_async16(sb + stg + arr * GA_ARR + row * 80 + q * 16,            \
                       Aarr[arr] + (size_t)row * K + k0 + q * 8);              \
        } else {                                                               \
            int w = gidx - 2048;                                               \
            int row = w >> 2;                                                  \
            int q = w & 3;                                                     \
            cp_async16(sb + stg + GB_OFF + row * 80 + q * 16,                  \
                       Bp + (size_t)row * K + k0 + q * 8);                     \
        }                                                                      \
    }                                                                          \
    asm volatile("cp.async.commit_group;" ::: "memory");                       \
} while (0)

    LOADSTAGE(0);

    for (int c = 0; c < NC; c++) {
        asm volatile("cp.async.wait_group 0;" ::: "memory");
        __syncthreads();
        if (c + 1 < NC) LOADSTAGE(c + 1);

        const uint32_t stg = sb + ((c & 1) ? G_STAGE : 0);
        const uint32_t sA0 = stg;
        const uint32_t sA1 = stg + GA_ARR;
        const uint32_t sB = stg + GB_OFF;

#pragma unroll
        for (int kk = 0; kk < 2; kk++) {
            const int kbyte = kk * 32;
            uint32_t fA0[4][4], fA1[4][4];
#pragma unroll
            for (int mt = 0; mt < 4; mt++) {
                int arow = wm * 64 + mt * 16 + (lg & 1) * 8 + lr;
                uint32_t aoff = (uint32_t)(arow * 80 + kbyte + (lg >> 1) * 16);
                ldsm4(fA0[mt], sA0 + aoff);
                ldsm4(fA1[mt], sA1 + aoff);
            }
#pragma unroll
            for (int np = 0; np < 4; np++) {
                int brow = wn * 64 + np * 16 + (lg >> 1) * 8 + lr;
                uint32_t boff = (uint32_t)(brow * 80 + kbyte + (lg & 1) * 16);
                uint32_t fB[4];
                ldsm4(fB, sB + boff);
#pragma unroll
                for (int mt = 0; mt < 4; mt++) {
                    mma16816h(acc[mt][np * 2], fA0[mt], fB);
                    mma16816h(acc[mt][np * 2], fA1[mt], fB);
                    mma16816h(acc[mt][np * 2 + 1], fA0[mt], fB + 2);
                    mma16816h(acc[mt][np * 2 + 1], fA1[mt], fB + 2);
                }
            }
        }
        __syncthreads();
    }

    if (MODE == 0) {
#pragma unroll
        for (int mt = 0; mt < 4; mt++) {
            int row0 = m0 + wm * 64 + mt * 16 + (lane >> 2);
#pragma unroll
            for (int nt = 0; nt < 8; nt++) {
                int col = n0 + wn * 64 + nt * 8 + (lane & 3) * 2;
                float2 v0 = {acc[mt][nt][0], acc[mt][nt][1]};
                float2 v1 = {acc[mt][nt][2], acc[mt][nt][3]};
                *(float2*)(C + (size_t)row0 * NN + col) = v0;
                *(float2*)(C + (size_t)(row0 + 8) * NN + col) = v1;
            }
        }
    } else {
        // Fused QKV epilogue. Warp's 64-col tile = exactly one head.
        const int col0 = n0 + wn * 64;
#pragma unroll
        for (int mt = 0; mt < 4; mt++) {
#pragma unroll
            for (int rr = 0; rr < 2; rr++) {
                int row = m0 + wm * 64 + mt * 16 + (lane >> 2) + rr * 8;
                int s = row & (SS - 1);
                int b = row >> 11;
                if (col0 < QDIM) {
                    // Q: RoPE + QSCALE -> fp16
                    int h = col0 >> 6;
                    __half* dst = Qf + ((size_t)(b * NH + h) * SS + s) * 64;
#pragma unroll
                    for (int nt = 0; nt < 4; nt++) {
                        int d = nt * 8 + (lane & 3) * 2;
                        float a0 = acc[mt][nt][rr * 2], a1 = acc[mt][nt][rr * 2 + 1];
                        float b0 = acc[mt][nt + 4][rr * 2], b1 = acc[mt][nt + 4][rr * 2 + 1];
                        int ci = s * 32 + (d >> 1);
                        float c1 = cosT[ci], s1 = sinT[ci];
                        float c2 = cosT[ci + 16], s2 = sinT[ci + 16];
                        __half2 lo2 = __floats2half2_rn((a0 * c1 - b0 * s1) * QSCALE,
                                                        (a1 * c1 - b1 * s1) * QSCALE);
                        __half2 hi2 = __floats2half2_rn((b0 * c2 + a0 * s2) * QSCALE,
                                                        (b1 * c2 + a1 * s2) * QSCALE);
                        *(__half2*)(dst + d) = lo2;
                        *(__half2*)(dst + d + 32) = hi2;
                    }
                } else if (col0 < QDIM + KVDIM) {
                    // K: RoPE -> fp16 hi/lo split
                    int kvh = (col0 - QDIM) >> 6;
                    size_t o = ((size_t)(b * NKV + kvh) * SS + s) * 64;
#pragma unroll
                    for (int nt = 0; nt < 4; nt++) {
                        int d = nt * 8 + (lane & 3) * 2;
                        float a0 = acc[mt][nt][rr * 2], a1 = acc[mt][nt][rr * 2 + 1];
                        float b0 = acc[mt][nt + 4][rr * 2], b1 = acc[mt][nt + 4][rr * 2 + 1];
                        int ci = s * 32 + (d >> 1);
                        float c1 = cosT[ci], s1 = sinT[ci];
                        float c2 = cosT[ci + 16], s2 = sinT[ci + 16];
                        float ra0 = a0 * c1 - b0 * s1, ra1 = a1 * c1 - b1 * s1;
                        float rb0 = b0 * c2 + a0 * s2, rb1 = b1 * c2 + a1 * s2;
                        uint32_t hh, ll;
                        pack_split_h(ra0, ra1, hh, ll);
                        *(uint32_t*)(Kh + o + d) = hh;
                        *(uint32_t*)(Kl + o + d) = ll;
                        pack_split_h(rb0, rb1, hh, ll);
                        *(uint32_t*)(Kh + o + d + 32) = hh;
                        *(uint32_t*)(Kl + o + d + 32) = ll;
                    }
                } else {
                    // V: plain fp16
                    int kvh = (col0 - QDIM - KVDIM) >> 6;
                    __half* dst = Vf + ((size_t)(b * NKV + kvh) * SS + s) * 64;
#pragma unroll
                    for (int nt = 0; nt < 8; nt++) {
                        int d = nt * 8 + (lane & 3) * 2;
                        *(__half2*)(dst + d) =
                            __floats2half2_rn(acc[mt][nt][rr * 2], acc[mt][nt][rr * 2 + 1]);
                    }
                }
            }
        }
    }
#undef LOADSTAGE
}

// ---------------------------------------------------------------------------
// cvt_all: x -> fp16 split; [wq;wk;wv] -> fp16 full; wo -> fp16 full
// ---------------------------------------------------------------------------
#define CV_NX (MTOT * DM / 2)
#define CV_NQ (QDIM * DM / 2)
#define CV_NK (KVDIM * DM / 2)
#define CV_NO (DM * QDIM / 2)
#define CV_TOTAL (CV_NX + CV_NQ + 2 * CV_NK + CV_NO)

__global__ void cvt_all(const float* __restrict__ x, const float* __restrict__ wq,
                        const float* __restrict__ wk, const float* __restrict__ wv,
                        const float* __restrict__ wo,
                        __half* __restrict__ xh, __half* __restrict__ xl,
                        __half* __restrict__ Wc, __half* __restrict__ Wof) {
    int i = blockIdx.x * blockDim.x + threadIdx.x;
    if (i < CV_NX) {
        float2 v = ((const float2*)x)[i];
        uint32_t h, l;
        pack_split_h(v.x, v.y, h, l);
        ((uint32_t*)xh)[i] = h;
        ((uint32_t*)xl)[i] = l;
        return;
    }
    const float* src;
    __half* dst;
    int off;
    if (i < CV_NX + CV_NQ) { src = wq; dst = Wc; off = i - CV_NX; }
    else if (i < CV_NX + CV_NQ + CV_NK) {
        src = wk; dst = Wc + (size_t)QDIM * DM; off = i - CV_NX - CV_NQ;
    } else if (i < CV_NX + CV_NQ + 2 * CV_NK) {
        src = wv; dst = Wc + (size_t)(QDIM + KVDIM) * DM; off = i - CV_NX - CV_NQ - CV_NK;
    } else if (i < CV_TOTAL) {
        src = wo; dst = Wof; off = i - CV_NX - CV_NQ - 2 * CV_NK;
    } else return;
    float2 v = ((const float2*)src)[off];
    ((__half2*)dst)[off] = __floats2half2_rn(v.x, v.y);
}

// ---------------------------------------------------------------------------
// MMA flash attention (validated R9/R10, unchanged)
// ---------------------------------------------------------------------------
#define FSTRB 144
#define FQ_BYTES (128 * FSTRB)
#define FARR (64 * FSTRB)
#define FKV0 FQ_BYTES
#define FSTAGE (3 * FARR)
#define FL_SMEM (FKV0 + 2 * FSTAGE)  // 73728

__global__ __launch_bounds__(256, 1) void flash_mma(
    const __half* __restrict__ Qf, const __half* __restrict__ Kh,
    const __half* __restrict__ Kl, const __half* __restrict__ Vf,
    __half* __restrict__ Oh, __half* __restrict__ Ol)
{
    extern __shared__ char sm[];
    const uint32_t sb = smem_u32(sm);
    const int tid = threadIdx.x;
    const int lane = tid & 31;
    const int wm = tid >> 5;
    const int qb = blockIdx.x;
    const int h = blockIdx.y;
    const int b = blockIdx.z;
    const int kvh = h >> 2;
    const int nkt = 2 * (qb + 1);

    const size_t qg = ((size_t)(b * NH + h) * SS + qb * 128) * 64;
    const size_t kg = ((size_t)(b * NKV + kvh) * SS) * 64;

    {
#pragma unroll
        for (int i = 0; i < 4; i++) {
            int g = tid + i * 256;
            int row = g >> 3;
            int ch = g & 7;
            cp_async16(sb + row * FSTRB + ch * 16, Qf + qg + (size_t)row * 64 + ch * 8);
        }
        asm volatile("cp.async.commit_group;" ::: "memory");
    }

#define LOADKV(kt_) do {                                                        \
    int j0_ = (kt_) * 64;                                                       \
    uint32_t stg_ = sb + FKV0 + ((kt_) & 1) * FSTAGE;                           \
    const char* karr[3] = {                                                     \
        (const char*)(Kh + kg + (size_t)j0_ * 64),                              \
        (const char*)(Kl + kg + (size_t)j0_ * 64),                              \
        (const char*)(Vf + kg + (size_t)j0_ * 64)};                             \
    _Pragma("unroll")                                                           \
    for (int i = 0; i < 6; i++) {                                               \
        int g = tid + i * 256;                                                  \
        int arr = g >> 9;                                                       \
        int w = g & 511;                                                        \
        int row = w >> 3;                                                       \
        int ch = w & 7;                                                         \
        cp_async16(stg_ + arr * FARR + row * FSTRB + ch * 16,                   \
                   karr[arr] + row * 128 + ch * 16);                            \
    }                                                                           \
    asm volatile("cp.async.commit_group;" ::: "memory");                        \
} while (0)

    LOADKV(0);
    if (nkt > 1) LOADKV(1);

    if (tid < 128) {
        int stage = tid >> 6;
        int row = tid & 63;
        uint32_t off = FKV0 + stage * FSTAGE + 2 * FARR + row * FSTRB + 128;
        uint4 ones = {0x00003C00u, 0u, 0u, 0u};
        *(uint4*)(sm + off) = ones;
    }

    if (nkt > 1) { asm volatile("cp.async.wait_group 1;" ::: "memory"); }
    else         { asm volatile("cp.async.wait_group 0;" ::: "memory"); }
    __syncthreads();

    uint32_t qf[4][4];
#pragma unroll
    for (int kk = 0; kk < 4; kk++) {
        uint32_t addr = sb + (uint32_t)((wm * 16 + (lane & 15)) * FSTRB
                                        + kk * 32 + (lane >> 4) * 16);
        ldsm4(qf[kk], addr);
    }

    float co[8][4];
#pragma unroll
    for (int i = 0; i < 8; i++)
#pragma unroll
        for (int j = 0; j < 4; j++) co[i][j] = 0.0f;
    float lacc[4] = {0.0f, 0.0f, 0.0f, 0.0f};
    float m0 = -1e30f, m1 = -1e30f;

    const int lg = lane >> 3;
    const int lr = lane & 7;
    const int qr0 = qb * 128 + wm * 16 + (lane >> 2);

    for (int kt = 0; kt < nkt; kt++) {
        if (kt > 0) {
            if (kt + 1 < nkt) { asm volatile("cp.async.wait_group 1;" ::: "memory"); }
            else              { asm volatile("cp.async.wait_group 0;" ::: "memory"); }
            __syncthreads();
        }
        const uint32_t sKh = sb + FKV0 + (kt & 1) * FSTAGE;
        const uint32_t sKl = sKh + FARR;
        const uint32_t sVf = sKh + 2 * FARR;

        float cs[8][4];
#pragma unroll
        for (int i = 0; i < 8; i++)
#pragma unroll
            for (int j = 0; j < 4; j++) cs[i][j] = 0.0f;

#pragma unroll
        for (int kk = 0; kk < 4; kk++) {
#pragma unroll
            for (int ng = 0; ng < 4; ng++) {
                uint32_t boff = (uint32_t)((ng * 16 + (lg >> 1) * 8 + lr) * FSTRB
                                           + kk * 32 + (lg & 1) * 16);
                uint32_t bh[4], bl[4];
                ldsm4(bh, sKh + boff);
                ldsm4(bl, sKl + boff);
                mma16816h(cs[ng * 2], qf[kk], bh);
                mma16816h(cs[ng * 2], qf[kk], bl);
                mma16816h(cs[ng * 2 + 1], qf[kk], bh + 2);
                mma16816h(cs[ng * 2 + 1], qf[kk], bl + 2);
            }
        }

        if (kt >= nkt - 2) {
            int gcol0 = kt * 64 + (lane & 3) * 2;
#pragma unroll
            for (int n = 0; n < 8; n++) {
#pragma unroll
                for (int t = 0; t < 2; t++) {
                    int col = gcol0 + n * 8 + t;
                    if (col > qr0) cs[n][t] = -1e30f;
                    if (col > qr0 + 8) cs[n][t + 2] = -1e30f;
                }
            }
        }

        float mx0 = -1e30f, mx1 = -1e30f;
#pragma unroll
        for (int n = 0; n < 8; n++) {
            mx0 = fmaxf(mx0, fmaxf(cs[n][0], cs[n][1]));
            mx1 = fmaxf(mx1, fmaxf(cs[n][2], cs[n][3]));
        }
        mx0 = fmaxf(mx0, __shfl_xor_sync(0xffffffffu, mx0, 1));
        mx0 = fmaxf(mx0, __shfl_xor_sync(0xffffffffu, mx0, 2));
        mx1 = fmaxf(mx1, __shfl_xor_sync(0xffffffffu, mx1, 1));
        mx1 = fmaxf(mx1, __shfl_xor_sync(0xffffffffu, mx1, 2));
        float nm0 = fmaxf(m0, mx0);
        float nm1 = fmaxf(m1, mx1);
        float f0 = ex2f(m0 - nm0);
        float f1 = ex2f(m1 - nm1);
        m0 = nm0; m1 = nm1;

        uint32_t pp[8][2];
#pragma unroll
        for (int n = 0; n < 8; n++) {
            pp[n][0] = ex2_f16x2(pack_f16x2(cs[n][0] - nm0, cs[n][1] - nm0));
            pp[n][1] = ex2_f16x2(pack_f16x2(cs[n][2] - nm1, cs[n][3] - nm1));
        }

#pragma unroll
        for (int n = 0; n < 8; n++) {
            co[n][0] *= f0; co[n][1] *= f0;
            co[n][2] *= f1; co[n][3] *= f1;
        }
        lacc[0] *= f0; lacc[2] *= f1;

#pragma unroll
        for (int kk = 0; kk < 4; kk++) {
            uint32_t pa[4] = {pp[2 * kk][0], pp[2 * kk][1],
                              pp[2 * kk + 1][0], pp[2 * kk + 1][1]};
#pragma unroll
            for (int ng = 0; ng < 4; ng++) {
                uint32_t vaddr = (uint32_t)((kk * 16 + (lane & 15)) * FSTRB
                                            + (ng * 16 + (lane >> 4) * 8) * 2);
                uint32_t vf[4];
                ldsm4t(vf, sVf + vaddr);
                mma16816h(co[ng * 2], pa, vf);
                mma16816h(co[ng * 2 + 1], pa, vf + 2);
            }
            uint32_t v1[2];
            ldsm2t(v1, sVf + (uint32_t)((kk * 16 + (lane & 15)) * FSTRB + 128));
            mma16816h(lacc, pa, v1);
        }

        __syncthreads();
        if (kt + 2 < nkt) LOADKV(kt + 2);
    }

    float l0 = __shfl_sync(0xffffffffu, lacc[0], lane & ~3);
    float l1 = __shfl_sync(0xffffffffu, lacc[2], lane & ~3);
    float inv0 = 1.0f / l0;
    float inv1 = 1.0f / l1;

    int srow = qb * 128 + wm * 16 + (lane >> 2);
    size_t base0 = ((size_t)(b * SS) + srow) * QDIM + h * 64 + (lane & 3) * 2;
    size_t base1 = base0 + (size_t)8 * QDIM;
#pragma unroll
    for (int nd = 0; nd < 8; nd++) {
        uint32_t hh, ll;
        pack_split_h(co[nd][0] * inv0, co[nd][1] * inv0, hh, ll);
        *(uint32_t*)(Oh + base0 + nd * 8) = hh;
        *(uint32_t*)(Ol + base0 + nd * 8) = ll;
        pack_split_h(co[nd][2] * inv1, co[nd][3] * inv1, hh, ll);
        *(uint32_t*)(Oh + base1 + nd * 8) = hh;
        *(uint32_t*)(Ol + base1 + nd * 8) = ll;
    }
#undef LOADKV
}

// ---------------------------------------------------------------------------
// Launch: cvt_all, gemmQKV(fused rope), flash, gemmO  (4 launches)
// ---------------------------------------------------------------------------
extern "C" void kernel_launch(void* const* d_in, const int* in_sizes, int n_in,
                              void* d_out, int out_size) {
    const float* x = (const float*)d_in[0];
    const float* wq = (const float*)d_in[1];
    const float* wk = (const float*)d_in[2];
    const float* wv = (const float*)d_in[3];
    const float* wo = (const float*)d_in[4];
    const float* cosT = (const float*)d_in[5];
    const float* sinT = (const float*)d_in[6];
    float* out = (float*)d_out;

    __half *xh, *xl, *Wc, *Wof, *Qf, *Kh, *Kl, *Vf, *Oh, *Ol;
    cudaGetSymbolAddress((void**)&xh, g_xh);
    cudaGetSymbolAddress((void**)&xl, g_xl);
    cudaGetSymbolAddress((void**)&Wc, g_Wc);
    cudaGetSymbolAddress((void**)&Wof, g_Wof);
    cudaGetSymbolAddress((void**)&Qf, g_Qf);
    cudaGetSymbolAddress((void**)&Kh, g_Kh);
    cudaGetSymbolAddress((void**)&Kl, g_Kl);
    cudaGetSymbolAddress((void**)&Vf, g_Vf);
    cudaGetSymbolAddress((void**)&Oh, g_Oh);
    cudaGetSymbolAddress((void**)&Ol, g_Ol);

    cudaFuncSetAttribute(gemm2<0>, cudaFuncAttributeMaxDynamicSharedMemorySize,
                         G_SMEM_TOTAL);
    cudaFuncSetAttribute(gemm2<1>, cudaFuncAttributeMaxDynamicSharedMemorySize,
                         G_SMEM_TOTAL);
    cudaFuncSetAttribute(flash_mma, cudaFuncAttributeMaxDynamicSharedMemorySize,
                         FL_SMEM);

    // 1. All input conversions
    cvt_all<<<(CV_TOTAL + 255) / 256, 256>>>(x, wq, wk, wv, wo, xh, xl, Wc, Wof);

    // 2. Fused QKV projection + RoPE + relayout (no fp32 intermediate)
    gemm2<1><<<dim3(QKVD / 128, MTOT / 256), 256, G_SMEM_TOTAL>>>(
        xh, xl, Wc, nullptr, QKVD, DM, cosT, sinT, Qf, Kh, Kl, Vf);

    // 3. Attention (writes fp16 split O)
    flash_mma<<<dim3(SS / 128, NH, BB), 256, FL_SMEM>>>(Qf, Kh, Kl, Vf, Oh, Ol);

    // 4. Output projection: out = (Oh+Ol) @ Wof^T
    gemm2<0><<<dim3(DM / 128, MTOT / 256), 256, G_SMEM_TOTAL>>>(
        Oh, Ol, Wof, out, DM, QDIM, nullptr, nullptr,
        nullptr, nullptr, nullptr, nullptr);
}

// round 13
// speedup vs baseline: 8.3616x; 1.0124x over previous
#include <cuda_runtime.h>
#include <cuda_bf16.h>
#include <cuda_fp16.h>
#include <math.h>
#include <stdint.h>

// Problem constants
#define BB 2
#define SS 2048
#define DM 2048
#define NH 32
#define NKV 8
#define HD 64
#define MTOT (BB * SS)          // 4096
#define QDIM (NH * HD)          // 2048
#define KVDIM (NKV * HD)        // 512
#define QKVD (QDIM + 2 * KVDIM) // 3072

// scale/log2 fold: (1/sqrt(64)) * log2(e)
#define QSCALE 0.18033688011112042f

// ---------------------------------------------------------------------------
// Scratch (device globals)
// ---------------------------------------------------------------------------
__device__ __half g_xh[MTOT * DM];              // x fp16 split
__device__ __half g_xl[MTOT * DM];
__device__ __half g_Wc[QKVD * DM];              // [wq;wk;wv] fp16 full
__device__ __half g_Wof[DM * QDIM];             // wo fp16 full
// per-head attention operands [b][h][s][64]
__device__ __half g_Qf[BB * NH * SS * HD];      // fp16, QSCALE folded
__device__ __half g_Kh[BB * NKV * SS * HD];     // fp16 hi
__device__ __half g_Kl[BB * NKV * SS * HD];     // fp16 residual
__device__ __half g_Vf[BB * NKV * SS * HD];     // fp16
// attention output fp16 split, [b][s][2048] (GEMM-ready)
__device__ __half g_Oh[MTOT * QDIM];
__device__ __half g_Ol[MTOT * QDIM];

// ---------------------------------------------------------------------------
// PTX helpers
// ---------------------------------------------------------------------------
__device__ __forceinline__ uint32_t smem_u32(const void* p) {
    uint32_t a;
    asm("{ .reg .u64 t; cvta.to.shared.u64 t, %1; cvt.u32.u64 %0, t; }" : "=r"(a) : "l"(p));
    return a;
}
__device__ __forceinline__ void ldsm4(uint32_t* r, uint32_t addr) {
    asm volatile("ldmatrix.sync.aligned.m8n8.x4.shared.b16 {%0,%1,%2,%3}, [%4];"
                 : "=r"(r[0]), "=r"(r[1]), "=r"(r[2]), "=r"(r[3]) : "r"(addr));
}
__device__ __forceinline__ void ldsm4t(uint32_t* r, uint32_t addr) {
    asm volatile("ldmatrix.sync.aligned.m8n8.x4.trans.shared.b16 {%0,%1,%2,%3}, [%4];"
                 : "=r"(r[0]), "=r"(r[1]), "=r"(r[2]), "=r"(r[3]) : "r"(addr));
}
__device__ __forceinline__ void ldsm2t(uint32_t* r, uint32_t addr) {
    asm volatile("ldmatrix.sync.aligned.m8n8.x2.trans.shared.b16 {%0,%1}, [%2];"
                 : "=r"(r[0]), "=r"(r[1]) : "r"(addr));
}
__device__ __forceinline__ void mma16816h(float* c, const uint32_t* a, const uint32_t* b) {
    asm volatile(
        "mma.sync.aligned.m16n8k16.row.col.f32.f16.f16.f32 "
        "{%0,%1,%2,%3}, {%4,%5,%6,%7}, {%8,%9}, {%0,%1,%2,%3};"
        : "+f"(c[0]), "+f"(c[1]), "+f"(c[2]), "+f"(c[3])
        : "r"(a[0]), "r"(a[1]), "r"(a[2]), "r"(a[3]), "r"(b[0]), "r"(b[1]));
}
__device__ __forceinline__ void cp_async16(uint32_t saddr, const void* gaddr) {
    asm volatile("cp.async.cg.shared.global [%0], [%1], 16;" :: "r"(saddr), "l"(gaddr));
}
__device__ __forceinline__ float ex2f(float x) {
    float y;
    asm("ex2.approx.ftz.f32 %0, %1;" : "=f"(y) : "f"(x));
    return y;
}
__device__ __forceinline__ uint32_t pack_f16x2(float lo, float hi) {
    uint32_t d;
    asm("cvt.rn.f16x2.f32 %0, %1, %2;" : "=r"(d) : "f"(hi), "f"(lo));
    return d;
}
__device__ __forceinline__ uint32_t ex2_f16x2(uint32_t x) {
    uint32_t y;
    asm("ex2.approx.f16x2 %0, %1;" : "=r"(y) : "r"(x));
    return y;
}
__device__ __forceinline__ void pack_split_h(float x, float y, uint32_t& hi, uint32_t& lo) {
    __half2 h = __floats2half2_rn(x, y);
    float rx = x - __half2float(__low2half(h));
    float ry = y - __half2float(__high2half(h));
    __half2 l = __floats2half2_rn(rx, ry);
    hi = *(uint32_t*)&h;
    lo = *(uint32_t*)&l;
}

// ---------------------------------------------------------------------------
// fp16 2-term GEMM: C = (A0+A1)[M,K] * B[NN,K]^T  (fp32 acc)
// CTA 256x128, BK=32, 256 threads (8 warps 4m x 2n), 3-stage cp.async
// pipeline (tail-corrected wait_group). MODE 0: fp32 C. MODE 1: fused
// RoPE + fp16 convert + per-head relayout epilogue.
// ---------------------------------------------------------------------------
#define GA_ARR 20480                   // 256 rows * 80 B
#define GB_ARR 10240                   // 128 rows * 80 B
#define GB_OFF (2 * GA_ARR)            // 40960
#define G_STAGE (2 * GA_ARR + GB_ARR)  // 51200
#define G_SMEM_TOTAL (3 * G_STAGE)     // 153600

template <int MODE>
__global__ __launch_bounds__(256, 1) void gemm2(
    const __half* __restrict__ A0, const __half* __restrict__ A1,
    const __half* __restrict__ B, float* __restrict__ C, int NN, int K,
    const float* __restrict__ cosT, const float* __restrict__ sinT,
    __half* __restrict__ Qf, __half* __restrict__ Kh,
    __half* __restrict__ Kl, __half* __restrict__ Vf)
{
    extern __shared__ char smem[];
    const uint32_t sb = smem_u32(smem);
    const int tid = threadIdx.x;
    const int wid = tid >> 5;
    const int lane = tid & 31;
    const int wm = wid & 3;
    const int wn = wid >> 2;
    const int m0 = blockIdx.y * 256;
    const int n0 = blockIdx.x * 128;

    const __half* const Aarr[2] = {A0 + (size_t)m0 * K, A1 + (size_t)m0 * K};
    const __half* const Bp = B + (size_t)n0 * K;

    float acc[4][8][4];
#pragma unroll
    for (int i = 0; i < 4; i++)
#pragma unroll
        for (int j = 0; j < 8; j++)
#pragma unroll
            for (int q = 0; q < 4; q++) acc[i][j][q] = 0.0f;

    const int NC = K / 32;
    const int lg = lane >> 3;
    const int lr = lane & 7;

#define LOADSTAGE(cc) do {                                                     \
    const uint32_t stg = ((cc) % 3) * G_STAGE;                                 \
    const int k0 = (cc) * 32;                                                  \
    _Pragma("unroll")                                                          \
    for (int i = 0; i < 10; i++) {                                             \
        int gidx = tid + i * 256;                                              \
        if (gidx < 2048) {                                                     \
            int arr = gidx >> 10;                                              \
            int w = gidx & 1023;                                               \
            int row = w >> 2;                                                  \
            int q = w & 3;                                                     \
            cp_async16(sb + stg + arr * GA_ARR + row * 80 + q * 16,            \
                       Aarr[arr] + (size_t)row * K + k0 + q * 8);              \
        } else {                                                               \
            int w = gidx - 2048;                                               \
            int row = w >> 2;                                                  \
            int q = w & 3;                                                     \
            cp_async16(sb + stg + GB_OFF + row * 80 + q * 16,                  \
                       Bp + (size_t)row * K + k0 + q * 8);                     \
        }                                                                      \
    }                                                                          \
    asm volatile("cp.async.commit_group;" ::: "memory");                       \
} while (0)

    LOADSTAGE(0);
    LOADSTAGE(1);

    for (int c = 0; c < NC; c++) {
        // In flight at this point: group c, and (if c+1 < NC) group c+1.
        // Wait for group c only; keep the newer one in flight. Tail iteration
        // (c == NC-1) has exactly one group pending -> wait_group 0.
        if (c + 1 < NC) { asm volatile("cp.async.wait_group 1;" ::: "memory"); }
        else            { asm volatile("cp.async.wait_group 0;" ::: "memory"); }
        __syncthreads();   // also orders: all warps finished compute on stage (c+2)%3
        if (c + 2 < NC) LOADSTAGE(c + 2);

        const uint32_t stg = sb + (c % 3) * G_STAGE;
        const uint32_t sA0 = stg;
        const uint32_t sA1 = stg + GA_ARR;
        const uint32_t sB = stg + GB_OFF;

#pragma unroll
        for (int kk = 0; kk < 2; kk++) {
            const int kbyte = kk * 32;
            uint32_t fA0[4][4], fA1[4][4];
#pragma unroll
            for (int mt = 0; mt < 4; mt++) {
                int arow = wm * 64 + mt * 16 + (lg & 1) * 8 + lr;
                uint32_t aoff = (uint32_t)(arow * 80 + kbyte + (lg >> 1) * 16);
                ldsm4(fA0[mt], sA0 + aoff);
                ldsm4(fA1[mt], sA1 + aoff);
            }
#pragma unroll
            for (int np = 0; np < 4; np++) {
                int brow = wn * 64 + np * 16 + (lg >> 1) * 8 + lr;
                uint32_t boff = (uint32_t)(brow * 80 + kbyte + (lg & 1) * 16);
                uint32_t fB[4];
                ldsm4(fB, sB + boff);
#pragma unroll
                for (int mt = 0; mt < 4; mt++) {
                    mma16816h(acc[mt][np * 2], fA0[mt], fB);
                    mma16816h(acc[mt][np * 2], fA1[mt], fB);
                    mma16816h(acc[mt][np * 2 + 1], fA0[mt], fB + 2);
                    mma16816h(acc[mt][np * 2 + 1], fA1[mt], fB + 2);
                }
            }
        }
    }

    if (MODE == 0) {
#pragma unroll
        for (int mt = 0; mt < 4; mt++) {
            int row0 = m0 + wm * 64 + mt * 16 + (lane >> 2);
#pragma unroll
            for (int nt = 0; nt < 8; nt++) {
                int col = n0 + wn * 64 + nt * 8 + (lane & 3) * 2;
                float2 v0 = {acc[mt][nt][0], acc[mt][nt][1]};
                float2 v1 = {acc[mt][nt][2], acc[mt][nt][3]};
                *(float2*)(C + (size_t)row0 * NN + col) = v0;
                *(float2*)(C + (size_t)(row0 + 8) * NN + col) = v1;
            }
        }
    } else {
        // Fused QKV epilogue. Warp's 64-col tile = exactly one head.
        const int col0 = n0 + wn * 64;
#pragma unroll
        for (int mt = 0; mt < 4; mt++) {
#pragma unroll
            for (int rr = 0; rr < 2; rr++) {
                int row = m0 + wm * 64 + mt * 16 + (lane >> 2) + rr * 8;
                int s = row & (SS - 1);
                int b = row >> 11;
                if (col0 < QDIM) {
                    // Q: RoPE + QSCALE -> fp16
                    int h = col0 >> 6;
                    __half* dst = Qf + ((size_t)(b * NH + h) * SS + s) * 64;
#pragma unroll
                    for (int nt = 0; nt < 4; nt++) {
                        int d = nt * 8 + (lane & 3) * 2;
                        float a0 = acc[mt][nt][rr * 2], a1 = acc[mt][nt][rr * 2 + 1];
                        float b0 = acc[mt][nt + 4][rr * 2], b1 = acc[mt][nt + 4][rr * 2 + 1];
                        int ci = s * 32 + (d >> 1);
                        float c1 = cosT[ci], s1 = sinT[ci];
                        float c2 = cosT[ci + 16], s2 = sinT[ci + 16];
                        __half2 lo2 = __floats2half2_rn((a0 * c1 - b0 * s1) * QSCALE,
                                                        (a1 * c1 - b1 * s1) * QSCALE);
                        __half2 hi2 = __floats2half2_rn((b0 * c2 + a0 * s2) * QSCALE,
                                                        (b1 * c2 + a1 * s2) * QSCALE);
                        *(__half2*)(dst + d) = lo2;
                        *(__half2*)(dst + d + 32) = hi2;
                    }
                } else if (col0 < QDIM + KVDIM) {
                    // K: RoPE -> fp16 hi/lo split
                    int kvh = (col0 - QDIM) >> 6;
                    size_t o = ((size_t)(b * NKV + kvh) * SS + s) * 64;
#pragma unroll
                    for (int nt = 0; nt < 4; nt++) {
                        int d = nt * 8 + (lane & 3) * 2;
                        float a0 = acc[mt][nt][rr * 2], a1 = acc[mt][nt][rr * 2 + 1];
                        float b0 = acc[mt][nt + 4][rr * 2], b1 = acc[mt][nt + 4][rr * 2 + 1];
                        int ci = s * 32 + (d >> 1);
                        float c1 = cosT[ci], s1 = sinT[ci];
                        float c2 = cosT[ci + 16], s2 = sinT[ci + 16];
                        float ra0 = a0 * c1 - b0 * s1, ra1 = a1 * c1 - b1 * s1;
                        float rb0 = b0 * c2 + a0 * s2, rb1 = b1 * c2 + a1 * s2;
                        uint32_t hh, ll;
                        pack_split_h(ra0, ra1, hh, ll);
                        *(uint32_t*)(Kh + o + d) = hh;
                        *(uint32_t*)(Kl + o + d) = ll;
                        pack_split_h(rb0, rb1, hh, ll);
                        *(uint32_t*)(Kh + o + d + 32) = hh;
                        *(uint32_t*)(Kl + o + d + 32) = ll;
                    }
                } else {
                    // V: plain fp16
                    int kvh = (col0 - QDIM - KVDIM) >> 6;
                    __half* dst = Vf + ((size_t)(b * NKV + kvh) * SS + s) * 64;
#pragma unroll
                    for (int nt = 0; nt < 8; nt++) {
                        int d = nt * 8 + (lane & 3) * 2;
                        *(__half2*)(dst + d) =
                            __floats2half2_rn(acc[mt][nt][rr * 2], acc[mt][nt][rr * 2 + 1]);
                    }
                }
            }
        }
    }
#undef LOADSTAGE
}

// ---------------------------------------------------------------------------
// cvt_all: x -> fp16 split; [wq;wk;wv] -> fp16 full; wo -> fp16 full
// ---------------------------------------------------------------------------
#define CV_NX (MTOT * DM / 2)
#define CV_NQ (QDIM * DM / 2)
#define CV_NK (KVDIM * DM / 2)
#define CV_NO (DM * QDIM / 2)
#define CV_TOTAL (CV_NX + CV_NQ + 2 * CV_NK + CV_NO)

__global__ void cvt_all(const float* __restrict__ x, const float* __restrict__ wq,
                        const float* __restrict__ wk, const float* __restrict__ wv,
                        const float* __restrict__ wo,
                        __half* __restrict__ xh, __half* __restrict__ xl,
                        __half* __restrict__ Wc, __half* __restrict__ Wof) {
    int i = blockIdx.x * blockDim.x + threadIdx.x;
    if (i < CV_NX) {
        float2 v = ((const float2*)x)[i];
        uint32_t h, l;
        pack_split_h(v.x, v.y, h, l);
        ((uint32_t*)xh)[i] = h;
        ((uint32_t*)xl)[i] = l;
        return;
    }
    const float* src;
    __half* dst;
    int off;
    if (i < CV_NX + CV_NQ) { src = wq; dst = Wc; off = i - CV_NX; }
    else if (i < CV_NX + CV_NQ + CV_NK) {
        src = wk; dst = Wc + (size_t)QDIM * DM; off = i - CV_NX - CV_NQ;
    } else if (i < CV_NX + CV_NQ + 2 * CV_NK) {
        src = wv; dst = Wc + (size_t)(QDIM + KVDIM) * DM; off = i - CV_NX - CV_NQ - CV_NK;
    } else if (i < CV_TOTAL) {
        src = wo; dst = Wof; off = i - CV_NX - CV_NQ - 2 * CV_NK;
    } else return;
    float2 v = ((const float2*)src)[off];
    ((__half2*)dst)[off] = __floats2half2_rn(v.x, v.y);
}

// ---------------------------------------------------------------------------
// MMA flash attention (validated R9/R10/R12, unchanged)
// ---------------------------------------------------------------------------
#define FSTRB 144
#define FQ_BYTES (128 * FSTRB)
#define FARR (64 * FSTRB)
#define FKV0 FQ_BYTES
#define FSTAGE (3 * FARR)
#define FL_SMEM (FKV0 + 2 * FSTAGE)  // 73728

__global__ __launch_bounds__(256, 1) void flash_mma(
    const __half* __restrict__ Qf, const __half* __restrict__ Kh,
    const __half* __restrict__ Kl, const __half* __restrict__ Vf,
    __half* __restrict__ Oh, __half* __restrict__ Ol)
{
    extern __shared__ char sm[];
    const uint32_t sb = smem_u32(sm);
    const int tid = threadIdx.x;
    const int lane = tid & 31;
    const int wm = tid >> 5;
    const int qb = blockIdx.x;
    const int h = blockIdx.y;
    const int b = blockIdx.z;
    const int kvh = h >> 2;
    const int nkt = 2 * (qb + 1);

    const size_t qg = ((size_t)(b * NH + h) * SS + qb * 128) * 64;
    const size_t kg = ((size_t)(b * NKV + kvh) * SS) * 64;

    {
#pragma unroll
        for (int i = 0; i < 4; i++) {
            int g = tid + i * 256;
            int row = g >> 3;
            int ch = g & 7;
            cp_async16(sb + row * FSTRB + ch * 16, Qf + qg + (size_t)row * 64 + ch * 8);
        }
        asm volatile("cp.async.commit_group;" ::: "memory");
    }

#define LOADKV(kt_) do {                                                        \
    int j0_ = (kt_) * 64;                                                       \
    uint32_t stg_ = sb + FKV0 + ((kt_) & 1) * FSTAGE;                           \
    const char* karr[3] = {                                                     \
        (const char*)(Kh + kg + (size_t)j0_ * 64),                              \
        (const char*)(Kl + kg + (size_t)j0_ * 64),                              \
        (const char*)(Vf + kg + (size_t)j0_ * 64)};                             \
    _Pragma("unroll")                                                           \
    for (int i = 0; i < 6; i++) {                                               \
        int g = tid + i * 256;                                                  \
        int arr = g >> 9;                                                       \
        int w = g & 511;                                                        \
        int row = w >> 3;                                                       \
        int ch = w & 7;                                                         \
        cp_async16(stg_ + arr * FARR + row * FSTRB + ch * 16,                   \
                   karr[arr] + row * 128 + ch * 16);                            \
    }                                                                           \
    asm volatile("cp.async.commit_group;" ::: "memory");                        \
} while (0)

    LOADKV(0);
    if (nkt > 1) LOADKV(1);

    if (tid < 128) {
        int stage = tid >> 6;
        int row = tid & 63;
        uint32_t off = FKV0 + stage * FSTAGE + 2 * FARR + row * FSTRB + 128;
        uint4 ones = {0x00003C00u, 0u, 0u, 0u};
        *(uint4*)(sm + off) = ones;
    }

    if (nkt > 1) { asm volatile("cp.async.wait_group 1;" ::: "memory"); }
    else         { asm volatile("cp.async.wait_group 0;" ::: "memory"); }
    __syncthreads();

    uint32_t qf[4][4];
#pragma unroll
    for (int kk = 0; kk < 4; kk++) {
        uint32_t addr = sb + (uint32_t)((wm * 16 + (lane & 15)) * FSTRB
                                        + kk * 32 + (lane >> 4) * 16);
        ldsm4(qf[kk], addr);
    }

    float co[8][4];
#pragma unroll
    for (int i = 0; i < 8; i++)
#pragma unroll
        for (int j = 0; j < 4; j++) co[i][j] = 0.0f;
    float lacc[4] = {0.0f, 0.0f, 0.0f, 0.0f};
    float m0 = -1e30f, m1 = -1e30f;

    const int lg = lane >> 3;
    const int lr = lane & 7;
    const int qr0 = qb * 128 + wm * 16 + (lane >> 2);

    for (int kt = 0; kt < nkt; kt++) {
        if (kt > 0) {
            if (kt + 1 < nkt) { asm volatile("cp.async.wait_group 1;" ::: "memory"); }
            else              { asm volatile("cp.async.wait_group 0;" ::: "memory"); }
            __syncthreads();
        }
        const uint32_t sKh = sb + FKV0 + (kt & 1) * FSTAGE;
        const uint32_t sKl = sKh + FARR;
        const uint32_t sVf = sKh + 2 * FARR;

        float cs[8][4];
#pragma unroll
        for (int i = 0; i < 8; i++)
#pragma unroll
            for (int j = 0; j < 4; j++) cs[i][j] = 0.0f;

#pragma unroll
        for (int kk = 0; kk < 4; kk++) {
#pragma unroll
            for (int ng = 0; ng < 4; ng++) {
                uint32_t boff = (uint32_t)((ng * 16 + (lg >> 1) * 8 + lr) * FSTRB
                                           + kk * 32 + (lg & 1) * 16);
                uint32_t bh[4], bl[4];
                ldsm4(bh, sKh + boff);
                ldsm4(bl, sKl + boff);
                mma16816h(cs[ng * 2], qf[kk], bh);
                mma16816h(cs[ng * 2], qf[kk], bl);
                mma16816h(cs[ng * 2 + 1], qf[kk], bh + 2);
                mma16816h(cs[ng * 2 + 1], qf[kk], bl + 2);
            }
        }

        if (kt >= nkt - 2) {
            int gcol0 = kt * 64 + (lane & 3) * 2;
#pragma unroll
            for (int n = 0; n < 8; n++) {
#pragma unroll
                for (int t = 0; t < 2; t++) {
                    int col = gcol0 + n * 8 + t;
                    if (col > qr0) cs[n][t] = -1e30f;
                    if (col > qr0 + 8) cs[n][t + 2] = -1e30f;
                }
            }
        }

        float mx0 = -1e30f, mx1 = -1e30f;
#pragma unroll
        for (int n = 0; n < 8; n++) {
            mx0 = fmaxf(mx0, fmaxf(cs[n][0], cs[n][1]));
            mx1 = fmaxf(mx1, fmaxf(cs[n][2], cs[n][3]));
        }
        mx0 = fmaxf(mx0, __shfl_xor_sync(0xffffffffu, mx0, 1));
        mx0 = fmaxf(mx0, __shfl_xor_sync(0xffffffffu, mx0, 2));
        mx1 = fmaxf(mx1, __shfl_xor_sync(0xffffffffu, mx1, 1));
        mx1 = fmaxf(mx1, __shfl_xor_sync(0xffffffffu, mx1, 2));
        float nm0 = fmaxf(m0, mx0);
        float nm1 = fmaxf(m1, mx1);
        float f0 = ex2f(m0 - nm0);
        float f1 = ex2f(m1 - nm1);
        m0 = nm0; m1 = nm1;

        uint32_t pp[8][2];
#pragma unroll
        for (int n = 0; n < 8; n++) {
            pp[n][0] = ex2_f16x2(pack_f16x2(cs[n][0] - nm0, cs[n][1] - nm0));
            pp[n][1] = ex2_f16x2(pack_f16x2(cs[n][2] - nm1, cs[n][3] - nm1));
        }

#pragma unroll
        for (int n = 0; n < 8; n++) {
            co[n][0] *= f0; co[n][1] *= f0;
            co[n][2] *= f1; co[n][3] *= f1;
        }
        lacc[0] *= f0; lacc[2] *= f1;

#pragma unroll
        for (int kk = 0; kk < 4; kk++) {
            uint32_t pa[4] = {pp[2 * kk][0], pp[2 * kk][1],
                              pp[2 * kk + 1][0], pp[2 * kk + 1][1]};
#pragma unroll
            for (int ng = 0; ng < 4; ng++) {
                uint32_t vaddr = (uint32_t)((kk * 16 + (lane & 15)) * FSTRB
                                            + (ng * 16 + (lane >> 4) * 8) * 2);
                uint32_t vf[4];
                ldsm4t(vf, sVf + vaddr);
                mma16816h(co[ng * 2], pa, vf);
                mma16816h(co[ng * 2 + 1], pa, vf + 2);
            }
            uint32_t v1[2];
            ldsm2t(v1, sVf + (uint32_t)((kk * 16 + (lane & 15)) * FSTRB + 128));
            mma16816h(lacc, pa, v1);
        }

        __syncthreads();
        if (kt + 2 < nkt) LOADKV(kt + 2);
    }

    float l0 = __shfl_sync(0xffffffffu, lacc[0], lane & ~3);
    float l1 = __shfl_sync(0xffffffffu, lacc[2], lane & ~3);
    float inv0 = 1.0f / l0;
    float inv1 = 1.0f / l1;

    int srow = qb * 128 + wm * 16 + (lane >> 2);
    size_t base0 = ((size_t)(b * SS) + srow) * QDIM + h * 64 + (lane & 3) * 2;
    size_t base1 = base0 + (size_t)8 * QDIM;
#pragma unroll
    for (int nd = 0; nd < 8; nd++) {
        uint32_t hh, ll;
        pack_split_h(co[nd][0] * inv0, co[nd][1] * inv0, hh, ll);
        *(uint32_t*)(Oh + base0 + nd * 8) = hh;
        *(uint32_t*)(Ol + base0 + nd * 8) = ll;
        pack_split_h(co[nd][2] * inv1, co[nd][3] * inv1, hh, ll);
        *(uint32_t*)(Oh + base1 + nd * 8) = hh;
        *(uint32_t*)(Ol + base1 + nd * 8) = ll;
    }
#undef LOADKV
}

// ---------------------------------------------------------------------------
// Launch: cvt_all, gemmQKV(fused rope), flash, gemmO  (4 launches)
// ---------------------------------------------------------------------------
extern "C" void kernel_launch(void* const* d_in, const int* in_sizes, int n_in,
                              void* d_out, int out_size) {
    const float* x = (const float*)d_in[0];
    const float* wq = (const float*)d_in[1];
    const float* wk = (const float*)d_in[2];
    const float* wv = (const float*)d_in[3];
    const float* wo = (const float*)d_in[4];
    const float* cosT = (const float*)d_in[5];
    const float* sinT = (const float*)d_in[6];
    float* out = (float*)d_out;

    __half *xh, *xl, *Wc, *Wof, *Qf, *Kh, *Kl, *Vf, *Oh, *Ol;
    cudaGetSymbolAddress((void**)&xh, g_xh);
    cudaGetSymbolAddress((void**)&xl, g_xl);
    cudaGetSymbolAddress((void**)&Wc, g_Wc);
    cudaGetSymbolAddress((void**)&Wof, g_Wof);
    cudaGetSymbolAddress((void**)&Qf, g_Qf);
    cudaGetSymbolAddress((void**)&Kh, g_Kh);
    cudaGetSymbolAddress((void**)&Kl, g_Kl);
    cudaGetSymbolAddress((void**)&Vf, g_Vf);
    cudaGetSymbolAddress((void**)&Oh, g_Oh);
    cudaGetSymbolAddress((void**)&Ol, g_Ol);

    cudaFuncSetAttribute(gemm2<0>, cudaFuncAttributeMaxDynamicSharedMemorySize,
                         G_SMEM_TOTAL);
    cudaFuncSetAttribute(gemm2<1>, cudaFuncAttributeMaxDynamicSharedMemorySize,
                         G_SMEM_TOTAL);
    cudaFuncSetAttribute(flash_mma, cudaFuncAttributeMaxDynamicSharedMemorySize,
                         FL_SMEM);

    // 1. All input conversions
    cvt_all<<<(CV_TOTAL + 255) / 256, 256>>>(x, wq, wk, wv, wo, xh, xl, Wc, Wof);

    // 2. Fused QKV projection + RoPE + relayout (no fp32 intermediate)
    gemm2<1><<<dim3(QKVD / 128, MTOT / 256), 256, G_SMEM_TOTAL>>>(
        xh, xl, Wc, nullptr, QKVD, DM, cosT, sinT, Qf, Kh, Kl, Vf);

    // 3. Attention (writes fp16 split O)
    flash_mma<<<dim3(SS / 128, NH, BB), 256, FL_SMEM>>>(Qf, Kh, Kl, Vf, Oh, Ol);

    // 4. Output projection: out = (Oh+Ol) @ Wof^T
    gemm2<0><<<dim3(DM / 128, MTOT / 256), 256, G_SMEM_TOTAL>>>(
        Oh, Ol, Wof, out, DM, QDIM, nullptr, nullptr,
        nullptr, nullptr, nullptr, nullptr);
}

// round 14
// speedup vs baseline: 11.7754x; 1.4083x over previous
#include <cuda_runtime.h>
#include <cuda_bf16.h>
#include <cuda_fp16.h>
#include <math.h>
#include <stdint.h>

// Problem constants
#define BB 2
#define SS 2048
#define DM 2048
#define NH 32
#define NKV 8
#define HD 64
#define MTOT (BB * SS)          // 4096
#define QDIM (NH * HD)          // 2048
#define KVDIM (NKV * HD)        // 512
#define QKVD (QDIM + 2 * KVDIM) // 3072

// scale/log2 fold: (1/sqrt(64)) * log2(e)
#define QSCALE 0.18033688011112042f

// ---------------------------------------------------------------------------
// Scratch (device globals)
// ---------------------------------------------------------------------------
__device__ __half g_xf[MTOT * DM];              // x fp16
__device__ __half g_Wc[QKVD * DM];              // [wq;wk;wv] fp16
__device__ __half g_Wof[DM * QDIM];             // wo fp16
// per-head attention operands [b][h][s][64]
__device__ __half g_Qf[BB * NH * SS * HD];      // fp16, QSCALE folded
__device__ __half g_Kh[BB * NKV * SS * HD];     // fp16 hi
__device__ __half g_Kl[BB * NKV * SS * HD];     // fp16 residual
__device__ __half g_Vf[BB * NKV * SS * HD];     // fp16
// attention output fp16, [b][s][2048] (GEMM-ready)
__device__ __half g_Of[MTOT * QDIM];

// ---------------------------------------------------------------------------
// PTX helpers
// ---------------------------------------------------------------------------
__device__ __forceinline__ uint32_t smem_u32(const void* p) {
    uint32_t a;
    asm("{ .reg .u64 t; cvta.to.shared.u64 t, %1; cvt.u32.u64 %0, t; }" : "=r"(a) : "l"(p));
    return a;
}
__device__ __forceinline__ void ldsm4(uint32_t* r, uint32_t addr) {
    asm volatile("ldmatrix.sync.aligned.m8n8.x4.shared.b16 {%0,%1,%2,%3}, [%4];"
                 : "=r"(r[0]), "=r"(r[1]), "=r"(r[2]), "=r"(r[3]) : "r"(addr));
}
__device__ __forceinline__ void ldsm4t(uint32_t* r, uint32_t addr) {
    asm volatile("ldmatrix.sync.aligned.m8n8.x4.trans.shared.b16 {%0,%1,%2,%3}, [%4];"
                 : "=r"(r[0]), "=r"(r[1]), "=r"(r[2]), "=r"(r[3]) : "r"(addr));
}
__device__ __forceinline__ void ldsm2t(uint32_t* r, uint32_t addr) {
    asm volatile("ldmatrix.sync.aligned.m8n8.x2.trans.shared.b16 {%0,%1}, [%2];"
                 : "=r"(r[0]), "=r"(r[1]) : "r"(addr));
}
__device__ __forceinline__ void mma16816h(float* c, const uint32_t* a, const uint32_t* b) {
    asm volatile(
        "mma.sync.aligned.m16n8k16.row.col.f32.f16.f16.f32 "
        "{%0,%1,%2,%3}, {%4,%5,%6,%7}, {%8,%9}, {%0,%1,%2,%3};"
        : "+f"(c[0]), "+f"(c[1]), "+f"(c[2]), "+f"(c[3])
        : "r"(a[0]), "r"(a[1]), "r"(a[2]), "r"(a[3]), "r"(b[0]), "r"(b[1]));
}
__device__ __forceinline__ void cp_async16(uint32_t saddr, const void* gaddr) {
    asm volatile("cp.async.cg.shared.global [%0], [%1], 16;" :: "r"(saddr), "l"(gaddr));
}
__device__ __forceinline__ float ex2f(float x) {
    float y;
    asm("ex2.approx.ftz.f32 %0, %1;" : "=f"(y) : "f"(x));
    return y;
}
__device__ __forceinline__ uint32_t pack_f16x2(float lo, float hi) {
    uint32_t d;
    asm("cvt.rn.f16x2.f32 %0, %1, %2;" : "=r"(d) : "f"(hi), "f"(lo));
    return d;
}
__device__ __forceinline__ uint32_t ex2_f16x2(uint32_t x) {
    uint32_t y;
    asm("ex2.approx.f16x2 %0, %1;" : "=r"(y) : "r"(x));
    return y;
}
__device__ __forceinline__ void pack_split_h(float x, float y, uint32_t& hi, uint32_t& lo) {
    __half2 h = __floats2half2_rn(x, y);
    float rx = x - __half2float(__low2half(h));
    float ry = y - __half2float(__high2half(h));
    __half2 l = __floats2half2_rn(rx, ry);
    hi = *(uint32_t*)&h;
    lo = *(uint32_t*)&l;
}

// ---------------------------------------------------------------------------
// fp16 1-term GEMM: C = A[M,K] * B[NN,K]^T  (fp32 acc)
// CTA 256x128, BK=32, 256 threads (8 warps 4m x 2n), 3-stage cp.async.
// MODE 0: fp32 C.  MODE 1 (QKV): fused RoPE + fp16 + per-head relayout.
// ---------------------------------------------------------------------------
#define GA_ARR 20480                   // 256 rows * 80 B
#define GB_ARR 10240                   // 128 rows * 80 B
#define G_STAGE (GA_ARR + GB_ARR)      // 30720
#define G_SMEM_TOTAL (3 * G_STAGE)     // 92160

template <int MODE>
__global__ __launch_bounds__(256, 1) void gemm2(
    const __half* __restrict__ A, const __half* __restrict__ B,
    float* __restrict__ C, int NN, int K,
    const float* __restrict__ cosT, const float* __restrict__ sinT,
    __half* __restrict__ Qf, __half* __restrict__ Kh,
    __half* __restrict__ Kl, __half* __restrict__ Vf)
{
    extern __shared__ char smem[];
    const uint32_t sb = smem_u32(smem);
    const int tid = threadIdx.x;
    const int wid = tid >> 5;
    const int lane = tid & 31;
    const int wm = wid & 3;
    const int wn = wid >> 2;
    const int m0 = blockIdx.y * 256;
    const int n0 = blockIdx.x * 128;

    const __half* const Ap = A + (size_t)m0 * K;
    const __half* const Bp = B + (size_t)n0 * K;

    float acc[4][8][4];
#pragma unroll
    for (int i = 0; i < 4; i++)
#pragma unroll
        for (int j = 0; j < 8; j++)
#pragma unroll
            for (int q = 0; q < 4; q++) acc[i][j][q] = 0.0f;

    const int NC = K / 32;
    const int lg = lane >> 3;
    const int lr = lane & 7;

#define LOADSTAGE(cc) do {                                                     \
    const uint32_t stg = ((cc) % 3) * G_STAGE;                                 \
    const int k0 = (cc) * 32;                                                  \
    _Pragma("unroll")                                                          \
    for (int i = 0; i < 6; i++) {                                              \
        int gidx = tid + i * 256;       /* 0..1535 */                          \
        if (gidx < 1024) {              /* A: 256 rows x 2 chunks */           \
            int row = gidx >> 2;                                               \
            int q = gidx & 3;                                                  \
            cp_async16(sb + stg + row * 80 + q * 16,                           \
                       Ap + (size_t)row * K + k0 + q * 8);                     \
        } else {                        /* B: 128 rows x 4 chunks */           \
            int w = gidx - 1024;                                               \
            int row = w >> 2;                                                  \
            int q = w & 3;                                                     \
            cp_async16(sb + stg + GA_ARR + row * 80 + q * 16,                  \
                       Bp + (size_t)row * K + k0 + q * 8);                     \
        }                                                                      \
    }                                                                          \
    asm volatile("cp.async.commit_group;" ::: "memory");                       \
} while (0)

    LOADSTAGE(0);
    LOADSTAGE(1);

    for (int c = 0; c < NC; c++) {
        if (c + 1 < NC) { asm volatile("cp.async.wait_group 1;" ::: "memory"); }
        else            { asm volatile("cp.async.wait_group 0;" ::: "memory"); }
        __syncthreads();
        if (c + 2 < NC) LOADSTAGE(c + 2);

        const uint32_t stg = sb + (c % 3) * G_STAGE;
        const uint32_t sA = stg;
        const uint32_t sB = stg + GA_ARR;

#pragma unroll
        for (int kk = 0; kk < 2; kk++) {
            const int kbyte = kk * 32;
            uint32_t fA[4][4];
#pragma unroll
            for (int mt = 0; mt < 4; mt++) {
                int arow = wm * 64 + mt * 16 + (lg & 1) * 8 + lr;
                uint32_t aoff = (uint32_t)(arow * 80 + kbyte + (lg >> 1) * 16);
                ldsm4(fA[mt], sA + aoff);
            }
#pragma unroll
            for (int np = 0; np < 4; np++) {
                int brow = wn * 64 + np * 16 + (lg >> 1) * 8 + lr;
                uint32_t boff = (uint32_t)(brow * 80 + kbyte + (lg & 1) * 16);
                uint32_t fB[4];
                ldsm4(fB, sB + boff);
#pragma unroll
                for (int mt = 0; mt < 4; mt++) {
                    mma16816h(acc[mt][np * 2], fA[mt], fB);
                    mma16816h(acc[mt][np * 2 + 1], fA[mt], fB + 2);
                }
            }
        }
    }

    if (MODE == 0) {
#pragma unroll
        for (int mt = 0; mt < 4; mt++) {
            int row0 = m0 + wm * 64 + mt * 16 + (lane >> 2);
#pragma unroll
            for (int nt = 0; nt < 8; nt++) {
                int col = n0 + wn * 64 + nt * 8 + (lane & 3) * 2;
                float2 v0 = {acc[mt][nt][0], acc[mt][nt][1]};
                float2 v1 = {acc[mt][nt][2], acc[mt][nt][3]};
                *(float2*)(C + (size_t)row0 * NN + col) = v0;
                *(float2*)(C + (size_t)(row0 + 8) * NN + col) = v1;
            }
        }
    } else {
        // Fused QKV epilogue. Warp's 64-col tile = exactly one head.
        const int col0 = n0 + wn * 64;
#pragma unroll
        for (int mt = 0; mt < 4; mt++) {
#pragma unroll
            for (int rr = 0; rr < 2; rr++) {
                int row = m0 + wm * 64 + mt * 16 + (lane >> 2) + rr * 8;
                int s = row & (SS - 1);
                int b = row >> 11;
                if (col0 < QDIM) {
                    int h = col0 >> 6;
                    __half* dst = Qf + ((size_t)(b * NH + h) * SS + s) * 64;
#pragma unroll
                    for (int nt = 0; nt < 4; nt++) {
                        int d = nt * 8 + (lane & 3) * 2;
                        float a0 = acc[mt][nt][rr * 2], a1 = acc[mt][nt][rr * 2 + 1];
                        float b0 = acc[mt][nt + 4][rr * 2], b1 = acc[mt][nt + 4][rr * 2 + 1];
                        int ci = s * 32 + (d >> 1);
                        float c1 = cosT[ci], s1 = sinT[ci];
                        float c2 = cosT[ci + 16], s2 = sinT[ci + 16];
                        __half2 lo2 = __floats2half2_rn((a0 * c1 - b0 * s1) * QSCALE,
                                                        (a1 * c1 - b1 * s1) * QSCALE);
                        __half2 hi2 = __floats2half2_rn((b0 * c2 + a0 * s2) * QSCALE,
                                                        (b1 * c2 + a1 * s2) * QSCALE);
                        *(__half2*)(dst + d) = lo2;
                        *(__half2*)(dst + d + 32) = hi2;
                    }
                } else if (col0 < QDIM + KVDIM) {
                    int kvh = (col0 - QDIM) >> 6;
                    size_t o = ((size_t)(b * NKV + kvh) * SS + s) * 64;
#pragma unroll
                    for (int nt = 0; nt < 4; nt++) {
                        int d = nt * 8 + (lane & 3) * 2;
                        float a0 = acc[mt][nt][rr * 2], a1 = acc[mt][nt][rr * 2 + 1];
                        float b0 = acc[mt][nt + 4][rr * 2], b1 = acc[mt][nt + 4][rr * 2 + 1];
                        int ci = s * 32 + (d >> 1);
                        float c1 = cosT[ci], s1 = sinT[ci];
                        float c2 = cosT[ci + 16], s2 = sinT[ci + 16];
                        float ra0 = a0 * c1 - b0 * s1, ra1 = a1 * c1 - b1 * s1;
                        float rb0 = b0 * c2 + a0 * s2, rb1 = b1 * c2 + a1 * s2;
                        uint32_t hh, ll;
                        pack_split_h(ra0, ra1, hh, ll);
                        *(uint32_t*)(Kh + o + d) = hh;
                        *(uint32_t*)(Kl + o + d) = ll;
                        pack_split_h(rb0, rb1, hh, ll);
                        *(uint32_t*)(Kh + o + d + 32) = hh;
                        *(uint32_t*)(Kl + o + d + 32) = ll;
                    }
                } else {
                    int kvh = (col0 - QDIM - KVDIM) >> 6;
                    __half* dst = Vf + ((size_t)(b * NKV + kvh) * SS + s) * 64;
#pragma unroll
                    for (int nt = 0; nt < 8; nt++) {
                        int d = nt * 8 + (lane & 3) * 2;
                        *(__half2*)(dst + d) =
                            __floats2half2_rn(acc[mt][nt][rr * 2], acc[mt][nt][rr * 2 + 1]);
                    }
                }
            }
        }
    }
#undef LOADSTAGE
}

// ---------------------------------------------------------------------------
// cvt_all: x, [wq;wk;wv], wo -> fp16 (no residuals)
// ---------------------------------------------------------------------------
#define CV_NX (MTOT * DM / 2)
#define CV_NQ (QDIM * DM / 2)
#define CV_NK (KVDIM * DM / 2)
#define CV_NO (DM * QDIM / 2)
#define CV_TOTAL (CV_NX + CV_NQ + 2 * CV_NK + CV_NO)

__global__ void cvt_all(const float* __restrict__ x, const float* __restrict__ wq,
                        const float* __restrict__ wk, const float* __restrict__ wv,
                        const float* __restrict__ wo,
                        __half* __restrict__ xf, __half* __restrict__ Wc,
                        __half* __restrict__ Wof) {
    int i = blockIdx.x * blockDim.x + threadIdx.x;
    const float* src;
    __half* dst;
    int off;
    if (i < CV_NX) { src = x; dst = xf; off = i; }
    else if (i < CV_NX + CV_NQ) { src = wq; dst = Wc; off = i - CV_NX; }
    else if (i < CV_NX + CV_NQ + CV_NK) {
        src = wk; dst = Wc + (size_t)QDIM * DM; off = i - CV_NX - CV_NQ;
    } else if (i < CV_NX + CV_NQ + 2 * CV_NK) {
        src = wv; dst = Wc + (size_t)(QDIM + KVDIM) * DM; off = i - CV_NX - CV_NQ - CV_NK;
    } else if (i < CV_TOTAL) {
        src = wo; dst = Wof; off = i - CV_NX - CV_NQ - 2 * CV_NK;
    } else return;
    float2 v = ((const float2*)src)[off];
    ((__half2*)dst)[off] = __floats2half2_rn(v.x, v.y);
}

// ---------------------------------------------------------------------------
// MMA flash attention (validated R9-R13): fp16 Q x fp16 split K (2 MMA),
// fp16 P x fp16 V (1 MMA), ones-column row sums. Epilogue writes fp16 O.
// ---------------------------------------------------------------------------
#define FSTRB 144
#define FQ_BYTES (128 * FSTRB)
#define FARR (64 * FSTRB)
#define FKV0 FQ_BYTES
#define FSTAGE (3 * FARR)
#define FL_SMEM (FKV0 + 2 * FSTAGE)  // 73728

__global__ __launch_bounds__(256, 1) void flash_mma(
    const __half* __restrict__ Qf, const __half* __restrict__ Kh,
    const __half* __restrict__ Kl, const __half* __restrict__ Vf,
    __half* __restrict__ Of)
{
    extern __shared__ char sm[];
    const uint32_t sb = smem_u32(sm);
    const int tid = threadIdx.x;
    const int lane = tid & 31;
    const int wm = tid >> 5;
    const int qb = blockIdx.x;
    const int h = blockIdx.y;
    const int b = blockIdx.z;
    const int kvh = h >> 2;
    const int nkt = 2 * (qb + 1);

    const size_t qg = ((size_t)(b * NH + h) * SS + qb * 128) * 64;
    const size_t kg = ((size_t)(b * NKV + kvh) * SS) * 64;

    {
#pragma unroll
        for (int i = 0; i < 4; i++) {
            int g = tid + i * 256;
            int row = g >> 3;
            int ch = g & 7;
            cp_async16(sb + row * FSTRB + ch * 16, Qf + qg + (size_t)row * 64 + ch * 8);
        }
        asm volatile("cp.async.commit_group;" ::: "memory");
    }

#define LOADKV(kt_) do {                                                        \
    int j0_ = (kt_) * 64;                                                       \
    uint32_t stg_ = sb + FKV0 + ((kt_) & 1) * FSTAGE;                           \
    const char* karr[3] = {                                                     \
        (const char*)(Kh + kg + (size_t)j0_ * 64),                              \
        (const char*)(Kl + kg + (size_t)j0_ * 64),                              \
        (const char*)(Vf + kg + (size_t)j0_ * 64)};                             \
    _Pragma("unroll")                                                           \
    for (int i = 0; i < 6; i++) {                                               \
        int g = tid + i * 256;                                                  \
        int arr = g >> 9;                                                       \
        int w = g & 511;                                                        \
        int row = w >> 3;                                                       \
        int ch = w & 7;                                                         \
        cp_async16(stg_ + arr * FARR + row * FSTRB + ch * 16,                   \
                   karr[arr] + row * 128 + ch * 16);                            \
    }                                                                           \
    asm volatile("cp.async.commit_group;" ::: "memory");                        \
} while (0)

    LOADKV(0);
    if (nkt > 1) LOADKV(1);

    if (tid < 128) {
        int stage = tid >> 6;
        int row = tid & 63;
        uint32_t off = FKV0 + stage * FSTAGE + 2 * FARR + row * FSTRB + 128;
        uint4 ones = {0x00003C00u, 0u, 0u, 0u};
        *(uint4*)(sm + off) = ones;
    }

    if (nkt > 1) { asm volatile("cp.async.wait_group 1;" ::: "memory"); }
    else         { asm volatile("cp.async.wait_group 0;" ::: "memory"); }
    __syncthreads();

    uint32_t qf[4][4];
#pragma unroll
    for (int kk = 0; kk < 4; kk++) {
        uint32_t addr = sb + (uint32_t)((wm * 16 + (lane & 15)) * FSTRB
                                        + kk * 32 + (lane >> 4) * 16);
        ldsm4(qf[kk], addr);
    }

    float co[8][4];
#pragma unroll
    for (int i = 0; i < 8; i++)
#pragma unroll
        for (int j = 0; j < 4; j++) co[i][j] = 0.0f;
    float lacc[4] = {0.0f, 0.0f, 0.0f, 0.0f};
    float m0 = -1e30f, m1 = -1e30f;

    const int lg = lane >> 3;
    const int lr = lane & 7;
    const int qr0 = qb * 128 + wm * 16 + (lane >> 2);

    for (int kt = 0; kt < nkt; kt++) {
        if (kt > 0) {
            if (kt + 1 < nkt) { asm volatile("cp.async.wait_group 1;" ::: "memory"); }
            else              { asm volatile("cp.async.wait_group 0;" ::: "memory"); }
            __syncthreads();
        }
        const uint32_t sKh = sb + FKV0 + (kt & 1) * FSTAGE;
        const uint32_t sKl = sKh + FARR;
        const uint32_t sVf = sKh + 2 * FARR;

        float cs[8][4];
#pragma unroll
        for (int i = 0; i < 8; i++)
#pragma unroll
            for (int j = 0; j < 4; j++) cs[i][j] = 0.0f;

#pragma unroll
        for (int kk = 0; kk < 4; kk++) {
#pragma unroll
            for (int ng = 0; ng < 4; ng++) {
                uint32_t boff = (uint32_t)((ng * 16 + (lg >> 1) * 8 + lr) * FSTRB
                                           + kk * 32 + (lg & 1) * 16);
                uint32_t bh[4], bl[4];
                ldsm4(bh, sKh + boff);
                ldsm4(bl, sKl + boff);
                mma16816h(cs[ng * 2], qf[kk], bh);
                mma16816h(cs[ng * 2], qf[kk], bl);
                mma16816h(cs[ng * 2 + 1], qf[kk], bh + 2);
                mma16816h(cs[ng * 2 + 1], qf[kk], bl + 2);
            }
        }

        if (kt >= nkt - 2) {
            int gcol0 = kt * 64 + (lane & 3) * 2;
#pragma unroll
            for (int n = 0; n < 8; n++) {
#pragma unroll
                for (int t = 0; t < 2; t++) {
                    int col = gcol0 + n * 8 + t;
                    if (col > qr0) cs[n][t] = -1e30f;
                    if (col > qr0 + 8) cs[n][t + 2] = -1e30f;
                }
            }
        }

        float mx0 = -1e30f, mx1 = -1e30f;
#pragma unroll
        for (int n = 0; n < 8; n++) {
            mx0 = fmaxf(mx0, fmaxf(cs[n][0], cs[n][1]));
            mx1 = fmaxf(mx1, fmaxf(cs[n][2], cs[n][3]));
        }
        mx0 = fmaxf(mx0, __shfl_xor_sync(0xffffffffu, mx0, 1));
        mx0 = fmaxf(mx0, __shfl_xor_sync(0xffffffffu, mx0, 2));
        mx1 = fmaxf(mx1, __shfl_xor_sync(0xffffffffu, mx1, 1));
        mx1 = fmaxf(mx1, __shfl_xor_sync(0xffffffffu, mx1, 2));
        float nm0 = fmaxf(m0, mx0);
        float nm1 = fmaxf(m1, mx1);
        float f0 = ex2f(m0 - nm0);
        float f1 = ex2f(m1 - nm1);
        m0 = nm0; m1 = nm1;

        uint32_t pp[8][2];
#pragma unroll
        for (int n = 0; n < 8; n++) {
            pp[n][0] = ex2_f16x2(pack_f16x2(cs[n][0] - nm0, cs[n][1] - nm0));
            pp[n][1] = ex2_f16x2(pack_f16x2(cs[n][2] - nm1, cs[n][3] - nm1));
        }

#pragma unroll
        for (int n = 0; n < 8; n++) {
            co[n][0] *= f0; co[n][1] *= f0;
            co[n][2] *= f1; co[n][3] *= f1;
        }
        lacc[0] *= f0; lacc[2] *= f1;

#pragma unroll
        for (int kk = 0; kk < 4; kk++) {
            uint32_t pa[4] = {pp[2 * kk][0], pp[2 * kk][1],
                              pp[2 * kk + 1][0], pp[2 * kk + 1][1]};
#pragma unroll
            for (int ng = 0; ng < 4; ng++) {
                uint32_t vaddr = (uint32_t)((kk * 16 + (lane & 15)) * FSTRB
                                            + (ng * 16 + (lane >> 4) * 8) * 2);
                uint32_t vf[4];
                ldsm4t(vf, sVf + vaddr);
                mma16816h(co[ng * 2], pa, vf);
                mma16816h(co[ng * 2 + 1], pa, vf + 2);
            }
            uint32_t v1[2];
            ldsm2t(v1, sVf + (uint32_t)((kk * 16 + (lane & 15)) * FSTRB + 128));
            mma16816h(lacc, pa, v1);
        }

        __syncthreads();
        if (kt + 2 < nkt) LOADKV(kt + 2);
    }

    float l0 = __shfl_sync(0xffffffffu, lacc[0], lane & ~3);
    float l1 = __shfl_sync(0xffffffffu, lacc[2], lane & ~3);
    float inv0 = 1.0f / l0;
    float inv1 = 1.0f / l1;

    int srow = qb * 128 + wm * 16 + (lane >> 2);
    size_t base0 = ((size_t)(b * SS) + srow) * QDIM + h * 64 + (lane & 3) * 2;
    size_t base1 = base0 + (size_t)8 * QDIM;
#pragma unroll
    for (int nd = 0; nd < 8; nd++) {
        *(__half2*)(Of + base0 + nd * 8) =
            __floats2half2_rn(co[nd][0] * inv0, co[nd][1] * inv0);
        *(__half2*)(Of + base1 + nd * 8) =
            __floats2half2_rn(co[nd][2] * inv1, co[nd][3] * inv1);
    }
#undef LOADKV
}

// ---------------------------------------------------------------------------
// Launch: cvt_all, gemmQKV(fused rope), flash, gemmO  (4 launches)
// ---------------------------------------------------------------------------
extern "C" void kernel_launch(void* const* d_in, const int* in_sizes, int n_in,
                              void* d_out, int out_size) {
    const float* x = (const float*)d_in[0];
    const float* wq = (const float*)d_in[1];
    const float* wk = (const float*)d_in[2];
    const float* wv = (const float*)d_in[3];
    const float* wo = (const float*)d_in[4];
    const float* cosT = (const float*)d_in[5];
    const float* sinT = (const float*)d_in[6];
    float* out = (float*)d_out;

    __half *xf, *Wc, *Wof, *Qf, *Kh, *Kl, *Vf, *Of;
    cudaGetSymbolAddress((void**)&xf, g_xf);
    cudaGetSymbolAddress((void**)&Wc, g_Wc);
    cudaGetSymbolAddress((void**)&Wof, g_Wof);
    cudaGetSymbolAddress((void**)&Qf, g_Qf);
    cudaGetSymbolAddress((void**)&Kh, g_Kh);
    cudaGetSymbolAddress((void**)&Kl, g_Kl);
    cudaGetSymbolAddress((void**)&Vf, g_Vf);
    cudaGetSymbolAddress((void**)&Of, g_Of);

    cudaFuncSetAttribute(gemm2<0>, cudaFuncAttributeMaxDynamicSharedMemorySize,
                         G_SMEM_TOTAL);
    cudaFuncSetAttribute(gemm2<1>, cudaFuncAttributeMaxDynamicSharedMemorySize,
                         G_SMEM_TOTAL);
    cudaFuncSetAttribute(flash_mma, cudaFuncAttributeMaxDynamicSharedMemorySize,
                         FL_SMEM);

    // 1. All input conversions (plain fp16)
    cvt_all<<<(CV_TOTAL + 255) / 256, 256>>>(x, wq, wk, wv, wo, xf, Wc, Wof);

    // 2. Fused QKV projection + RoPE + relayout
    gemm2<1><<<dim3(QKVD / 128, MTOT / 256), 256, G_SMEM_TOTAL>>>(
        xf, Wc, nullptr, QKVD, DM, cosT, sinT, Qf, Kh, Kl, Vf);

    // 3. Attention (writes fp16 O)
    flash_mma<<<dim3(SS / 128, NH, BB), 256, FL_SMEM>>>(Qf, Kh, Kl, Vf, Of);

    // 4. Output projection: out = Of @ Wof^T
    gemm2<0><<<dim3(DM / 128, MTOT / 256), 256, G_SMEM_TOTAL>>>(
        Of, Wof, out, DM, QDIM, nullptr, nullptr,
        nullptr, nullptr, nullptr, nullptr);
}

// round 15
// speedup vs baseline: 12.9965x; 1.1037x over previous
#include <cuda_runtime.h>
#include <cuda_bf16.h>
#include <cuda_fp16.h>
#include <math.h>
#include <stdint.h>

// Problem constants
#define BB 2
#define SS 2048
#define DM 2048
#define NH 32
#define NKV 8
#define HD 64
#define MTOT (BB * SS)          // 4096
#define QDIM (NH * HD)          // 2048
#define KVDIM (NKV * HD)        // 512
#define QKVD (QDIM + 2 * KVDIM) // 3072

// scale/log2 fold: (1/sqrt(64)) * log2(e)
#define QSCALE 0.18033688011112042f

// ---------------------------------------------------------------------------
// Scratch (device globals)
// ---------------------------------------------------------------------------
__device__ __half g_xf[MTOT * DM];              // x fp16
__device__ __half g_Wc[QKVD * DM];              // [wq;wk;wv] fp16
__device__ __half g_Wof[DM * QDIM];             // wo fp16
// per-head attention operands [b][h][s][64]
__device__ __half g_Qf[BB * NH * SS * HD];      // fp16, QSCALE folded
__device__ __half g_Kf[BB * NKV * SS * HD];     // fp16
__device__ __half g_Vf[BB * NKV * SS * HD];     // fp16
// attention output fp16, [b][s][2048] (GEMM-ready)
__device__ __half g_Of[MTOT * QDIM];

// ---------------------------------------------------------------------------
// PTX helpers
// ---------------------------------------------------------------------------
__device__ __forceinline__ uint32_t smem_u32(const void* p) {
    uint32_t a;
    asm("{ .reg .u64 t; cvta.to.shared.u64 t, %1; cvt.u32.u64 %0, t; }" : "=r"(a) : "l"(p));
    return a;
}
__device__ __forceinline__ void ldsm4(uint32_t* r, uint32_t addr) {
    asm volatile("ldmatrix.sync.aligned.m8n8.x4.shared.b16 {%0,%1,%2,%3}, [%4];"
                 : "=r"(r[0]), "=r"(r[1]), "=r"(r[2]), "=r"(r[3]) : "r"(addr));
}
__device__ __forceinline__ void ldsm4t(uint32_t* r, uint32_t addr) {
    asm volatile("ldmatrix.sync.aligned.m8n8.x4.trans.shared.b16 {%0,%1,%2,%3}, [%4];"
                 : "=r"(r[0]), "=r"(r[1]), "=r"(r[2]), "=r"(r[3]) : "r"(addr));
}
__device__ __forceinline__ void ldsm2t(uint32_t* r, uint32_t addr) {
    asm volatile("ldmatrix.sync.aligned.m8n8.x2.trans.shared.b16 {%0,%1}, [%2];"
                 : "=r"(r[0]), "=r"(r[1]) : "r"(addr));
}
__device__ __forceinline__ void mma16816h(float* c, const uint32_t* a, const uint32_t* b) {
    asm volatile(
        "mma.sync.aligned.m16n8k16.row.col.f32.f16.f16.f32 "
        "{%0,%1,%2,%3}, {%4,%5,%6,%7}, {%8,%9}, {%0,%1,%2,%3};"
        : "+f"(c[0]), "+f"(c[1]), "+f"(c[2]), "+f"(c[3])
        : "r"(a[0]), "r"(a[1]), "r"(a[2]), "r"(a[3]), "r"(b[0]), "r"(b[1]));
}
__device__ __forceinline__ void cp_async16(uint32_t saddr, const void* gaddr) {
    asm volatile("cp.async.cg.shared.global [%0], [%1], 16;" :: "r"(saddr), "l"(gaddr));
}
__device__ __forceinline__ float ex2f(float x) {
    float y;
    asm("ex2.approx.ftz.f32 %0, %1;" : "=f"(y) : "f"(x));
    return y;
}
__device__ __forceinline__ uint32_t pack_f16x2(float lo, float hi) {
    uint32_t d;
    asm("cvt.rn.f16x2.f32 %0, %1, %2;" : "=r"(d) : "f"(hi), "f"(lo));
    return d;
}
__device__ __forceinline__ uint32_t ex2_f16x2(uint32_t x) {
    uint32_t y;
    asm("ex2.approx.f16x2 %0, %1;" : "=r"(y) : "r"(x));
    return y;
}

// ---------------------------------------------------------------------------
// fp16 1-term GEMM: C = A[M,K] * B[NN,K]^T  (fp32 acc)
// CTA 256x128, BK=32, 256 threads (8 warps 4m x 2n), 3-stage cp.async.
// MODE 0: fp32 C.  MODE 1 (QKV): fused RoPE + fp16 + per-head relayout.
// ---------------------------------------------------------------------------
#define GA_ARR 20480                   // 256 rows * 80 B
#define GB_ARR 10240                   // 128 rows * 80 B
#define G_STAGE (GA_ARR + GB_ARR)      // 30720
#define G_SMEM_TOTAL (3 * G_STAGE)     // 92160

template <int MODE>
__global__ __launch_bounds__(256, 1) void gemm2(
    const __half* __restrict__ A, const __half* __restrict__ B,
    float* __restrict__ C, int NN, int K,
    const float* __restrict__ cosT, const float* __restrict__ sinT,
    __half* __restrict__ Qf, __half* __restrict__ Kf, __half* __restrict__ Vf)
{
    extern __shared__ char smem[];
    const uint32_t sb = smem_u32(smem);
    const int tid = threadIdx.x;
    const int wid = tid >> 5;
    const int lane = tid & 31;
    const int wm = wid & 3;
    const int wn = wid >> 2;
    const int m0 = blockIdx.y * 256;
    const int n0 = blockIdx.x * 128;

    const __half* const Ap = A + (size_t)m0 * K;
    const __half* const Bp = B + (size_t)n0 * K;

    float acc[4][8][4];
#pragma unroll
    for (int i = 0; i < 4; i++)
#pragma unroll
        for (int j = 0; j < 8; j++)
#pragma unroll
            for (int q = 0; q < 4; q++) acc[i][j][q] = 0.0f;

    const int NC = K / 32;
    const int lg = lane >> 3;
    const int lr = lane & 7;

#define LOADSTAGE(cc) do {                                                     \
    const uint32_t stg = ((cc) % 3) * G_STAGE;                                 \
    const int k0 = (cc) * 32;                                                  \
    _Pragma("unroll")                                                          \
    for (int i = 0; i < 6; i++) {                                              \
        int gidx = tid + i * 256;                                              \
        if (gidx < 1024) {                                                     \
            int row = gidx >> 2;                                               \
            int q = gidx & 3;                                                  \
            cp_async16(sb + stg + row * 80 + q * 16,                           \
                       Ap + (size_t)row * K + k0 + q * 8);                     \
        } else {                                                               \
            int w = gidx - 1024;                                               \
            int row = w >> 2;                                                  \
            int q = w & 3;                                                     \
            cp_async16(sb + stg + GA_ARR + row * 80 + q * 16,                  \
                       Bp + (size_t)row * K + k0 + q * 8);                     \
        }                                                                      \
    }                                                                          \
    asm volatile("cp.async.commit_group;" ::: "memory");                       \
} while (0)

    LOADSTAGE(0);
    LOADSTAGE(1);

    for (int c = 0; c < NC; c++) {
        if (c + 1 < NC) { asm volatile("cp.async.wait_group 1;" ::: "memory"); }
        else            { asm volatile("cp.async.wait_group 0;" ::: "memory"); }
        __syncthreads();
        if (c + 2 < NC) LOADSTAGE(c + 2);

        const uint32_t stg = sb + (c % 3) * G_STAGE;
        const uint32_t sA = stg;
        const uint32_t sB = stg + GA_ARR;

#pragma unroll
        for (int kk = 0; kk < 2; kk++) {
            const int kbyte = kk * 32;
            uint32_t fA[4][4];
#pragma unroll
            for (int mt = 0; mt < 4; mt++) {
                int arow = wm * 64 + mt * 16 + (lg & 1) * 8 + lr;
                uint32_t aoff = (uint32_t)(arow * 80 + kbyte + (lg >> 1) * 16);
                ldsm4(fA[mt], sA + aoff);
            }
#pragma unroll
            for (int np = 0; np < 4; np++) {
                int brow = wn * 64 + np * 16 + (lg >> 1) * 8 + lr;
                uint32_t boff = (uint32_t)(brow * 80 + kbyte + (lg & 1) * 16);
                uint32_t fB[4];
                ldsm4(fB, sB + boff);
#pragma unroll
                for (int mt = 0; mt < 4; mt++) {
                    mma16816h(acc[mt][np * 2], fA[mt], fB);
                    mma16816h(acc[mt][np * 2 + 1], fA[mt], fB + 2);
                }
            }
        }
    }

    if (MODE == 0) {
#pragma unroll
        for (int mt = 0; mt < 4; mt++) {
            int row0 = m0 + wm * 64 + mt * 16 + (lane >> 2);
#pragma unroll
            for (int nt = 0; nt < 8; nt++) {
                int col = n0 + wn * 64 + nt * 8 + (lane & 3) * 2;
                float2 v0 = {acc[mt][nt][0], acc[mt][nt][1]};
                float2 v1 = {acc[mt][nt][2], acc[mt][nt][3]};
                *(float2*)(C + (size_t)row0 * NN + col) = v0;
                *(float2*)(C + (size_t)(row0 + 8) * NN + col) = v1;
            }
        }
    } else {
        // Fused QKV epilogue. Warp's 64-col tile = exactly one head.
        const int col0 = n0 + wn * 64;
#pragma unroll
        for (int mt = 0; mt < 4; mt++) {
#pragma unroll
            for (int rr = 0; rr < 2; rr++) {
                int row = m0 + wm * 64 + mt * 16 + (lane >> 2) + rr * 8;
                int s = row & (SS - 1);
                int b = row >> 11;
                if (col0 < QDIM + KVDIM) {
                    // Q or K: RoPE -> fp16 (QSCALE folded for Q)
                    bool isQ = col0 < QDIM;
                    __half* dst;
                    if (isQ) {
                        int h = col0 >> 6;
                        dst = Qf + ((size_t)(b * NH + h) * SS + s) * 64;
                    } else {
                        int kvh = (col0 - QDIM) >> 6;
                        dst = Kf + ((size_t)(b * NKV + kvh) * SS + s) * 64;
                    }
                    float sc = isQ ? QSCALE : 1.0f;
#pragma unroll
                    for (int nt = 0; nt < 4; nt++) {
                        int d = nt * 8 + (lane & 3) * 2;
                        float a0 = acc[mt][nt][rr * 2], a1 = acc[mt][nt][rr * 2 + 1];
                        float b0 = acc[mt][nt + 4][rr * 2], b1 = acc[mt][nt + 4][rr * 2 + 1];
                        int ci = s * 32 + (d >> 1);
                        float c1 = cosT[ci], s1 = sinT[ci];
                        float c2 = cosT[ci + 16], s2 = sinT[ci + 16];
                        __half2 lo2 = __floats2half2_rn((a0 * c1 - b0 * s1) * sc,
                                                        (a1 * c1 - b1 * s1) * sc);
                        __half2 hi2 = __floats2half2_rn((b0 * c2 + a0 * s2) * sc,
                                                        (b1 * c2 + a1 * s2) * sc);
                        *(__half2*)(dst + d) = lo2;
                        *(__half2*)(dst + d + 32) = hi2;
                    }
                } else {
                    // V: plain fp16
                    int kvh = (col0 - QDIM - KVDIM) >> 6;
                    __half* dst = Vf + ((size_t)(b * NKV + kvh) * SS + s) * 64;
#pragma unroll
                    for (int nt = 0; nt < 8; nt++) {
                        int d = nt * 8 + (lane & 3) * 2;
                        *(__half2*)(dst + d) =
                            __floats2half2_rn(acc[mt][nt][rr * 2], acc[mt][nt][rr * 2 + 1]);
                    }
                }
            }
        }
    }
#undef LOADSTAGE
}

// ---------------------------------------------------------------------------
// cvt_all: x, [wq;wk;wv], wo -> fp16
// ---------------------------------------------------------------------------
#define CV_NX (MTOT * DM / 2)
#define CV_NQ (QDIM * DM / 2)
#define CV_NK (KVDIM * DM / 2)
#define CV_NO (DM * QDIM / 2)
#define CV_TOTAL (CV_NX + CV_NQ + 2 * CV_NK + CV_NO)

__global__ void cvt_all(const float* __restrict__ x, const float* __restrict__ wq,
                        const float* __restrict__ wk, const float* __restrict__ wv,
                        const float* __restrict__ wo,
                        __half* __restrict__ xf, __half* __restrict__ Wc,
                        __half* __restrict__ Wof) {
    int i = blockIdx.x * blockDim.x + threadIdx.x;
    const float* src;
    __half* dst;
    int off;
    if (i < CV_NX) { src = x; dst = xf; off = i; }
    else if (i < CV_NX + CV_NQ) { src = wq; dst = Wc; off = i - CV_NX; }
    else if (i < CV_NX + CV_NQ + CV_NK) {
        src = wk; dst = Wc + (size_t)QDIM * DM; off = i - CV_NX - CV_NQ;
    } else if (i < CV_NX + CV_NQ + 2 * CV_NK) {
        src = wv; dst = Wc + (size_t)(QDIM + KVDIM) * DM; off = i - CV_NX - CV_NQ - CV_NK;
    } else if (i < CV_TOTAL) {
        src = wo; dst = Wof; off = i - CV_NX - CV_NQ - 2 * CV_NK;
    } else return;
    float2 v = ((const float2*)src)[off];
    ((__half2*)dst)[off] = __floats2half2_rn(v.x, v.y);
}

// ---------------------------------------------------------------------------
// MMA flash attention v4: fp16 Q x fp16 K (1 MMA), fp16 P x fp16 V (1 MMA),
// ones-column row sums. grid (S/128, NH, BB), 256 threads.
// ---------------------------------------------------------------------------
#define FSTRB 144
#define FQ_BYTES (128 * FSTRB)
#define FARR (64 * FSTRB)
#define FKV0 FQ_BYTES
#define FSTAGE (2 * FARR)            // Kf, Vf = 18432
#define FL_SMEM (FKV0 + 2 * FSTAGE)  // 55296

__global__ __launch_bounds__(256, 1) void flash_mma(
    const __half* __restrict__ Qf, const __half* __restrict__ Kf,
    const __half* __restrict__ Vf, __half* __restrict__ Of)
{
    extern __shared__ char sm[];
    const uint32_t sb = smem_u32(sm);
    const int tid = threadIdx.x;
    const int lane = tid & 31;
    const int wm = tid >> 5;
    const int qb = blockIdx.x;
    const int h = blockIdx.y;
    const int b = blockIdx.z;
    const int kvh = h >> 2;
    const int nkt = 2 * (qb + 1);

    const size_t qg = ((size_t)(b * NH + h) * SS + qb * 128) * 64;
    const size_t kg = ((size_t)(b * NKV + kvh) * SS) * 64;

    {
#pragma unroll
        for (int i = 0; i < 4; i++) {
            int g = tid + i * 256;
            int row = g >> 3;
            int ch = g & 7;
            cp_async16(sb + row * FSTRB + ch * 16, Qf + qg + (size_t)row * 64 + ch * 8);
        }
        asm volatile("cp.async.commit_group;" ::: "memory");
    }

#define LOADKV(kt_) do {                                                        \
    int j0_ = (kt_) * 64;                                                       \
    uint32_t stg_ = sb + FKV0 + ((kt_) & 1) * FSTAGE;                           \
    const char* karr[2] = {                                                     \
        (const char*)(Kf + kg + (size_t)j0_ * 64),                              \
        (const char*)(Vf + kg + (size_t)j0_ * 64)};                             \
    _Pragma("unroll")                                                           \
    for (int i = 0; i < 4; i++) {                                               \
        int g = tid + i * 256;          /* 0..1023 */                           \
        int arr = g >> 9;                                                       \
        int w = g & 511;                                                        \
        int row = w >> 3;                                                       \
        int ch = w & 7;                                                         \
        cp_async16(stg_ + arr * FARR + row * FSTRB + ch * 16,                   \
                   karr[arr] + row * 128 + ch * 16);                            \
    }                                                                           \
    asm volatile("cp.async.commit_group;" ::: "memory");                        \
} while (0)

    LOADKV(0);
    if (nkt > 1) LOADKV(1);

    // V pad init: ones column (col 64 = 1.0h) in both stages; cp.async never
    // touches bytes [128,144) of a row so this persists across refills.
    if (tid < 128) {
        int stage = tid >> 6;
        int row = tid & 63;
        uint32_t off = FKV0 + stage * FSTAGE + FARR + row * FSTRB + 128;
        uint4 ones = {0x00003C00u, 0u, 0u, 0u};
        *(uint4*)(sm + off) = ones;
    }

    if (nkt > 1) { asm volatile("cp.async.wait_group 1;" ::: "memory"); }
    else         { asm volatile("cp.async.wait_group 0;" ::: "memory"); }
    __syncthreads();

    uint32_t qf[4][4];
#pragma unroll
    for (int kk = 0; kk < 4; kk++) {
        uint32_t addr = sb + (uint32_t)((wm * 16 + (lane & 15)) * FSTRB
                                        + kk * 32 + (lane >> 4) * 16);
        ldsm4(qf[kk], addr);
    }

    float co[8][4];
#pragma unroll
    for (int i = 0; i < 8; i++)
#pragma unroll
        for (int j = 0; j < 4; j++) co[i][j] = 0.0f;
    float lacc[4] = {0.0f, 0.0f, 0.0f, 0.0f};
    float m0 = -1e30f, m1 = -1e30f;

    const int lg = lane >> 3;
    const int lr = lane & 7;
    const int qr0 = qb * 128 + wm * 16 + (lane >> 2);

    for (int kt = 0; kt < nkt; kt++) {
        if (kt > 0) {
            if (kt + 1 < nkt) { asm volatile("cp.async.wait_group 1;" ::: "memory"); }
            else              { asm volatile("cp.async.wait_group 0;" ::: "memory"); }
            __syncthreads();
        }
        const uint32_t sKf = sb + FKV0 + (kt & 1) * FSTAGE;
        const uint32_t sVf = sKf + FARR;

        // ---- S = Qf Kf^T (1 fp16 MMA per n8) ----
        float cs[8][4];
#pragma unroll
        for (int i = 0; i < 8; i++)
#pragma unroll
            for (int j = 0; j < 4; j++) cs[i][j] = 0.0f;

#pragma unroll
        for (int kk = 0; kk < 4; kk++) {
#pragma unroll
            for (int ng = 0; ng < 4; ng++) {
                uint32_t boff = (uint32_t)((ng * 16 + (lg >> 1) * 8 + lr) * FSTRB
                                           + kk * 32 + (lg & 1) * 16);
                uint32_t bk[4];
                ldsm4(bk, sKf + boff);
                mma16816h(cs[ng * 2], qf[kk], bk);
                mma16816h(cs[ng * 2 + 1], qf[kk], bk + 2);
            }
        }

        if (kt >= nkt - 2) {
            int gcol0 = kt * 64 + (lane & 3) * 2;
#pragma unroll
            for (int n = 0; n < 8; n++) {
#pragma unroll
                for (int t = 0; t < 2; t++) {
                    int col = gcol0 + n * 8 + t;
                    if (col > qr0) cs[n][t] = -1e30f;
                    if (col > qr0 + 8) cs[n][t + 2] = -1e30f;
                }
            }
        }

        float mx0 = -1e30f, mx1 = -1e30f;
#pragma unroll
        for (int n = 0; n < 8; n++) {
            mx0 = fmaxf(mx0, fmaxf(cs[n][0], cs[n][1]));
            mx1 = fmaxf(mx1, fmaxf(cs[n][2], cs[n][3]));
        }
        mx0 = fmaxf(mx0, __shfl_xor_sync(0xffffffffu, mx0, 1));
        mx0 = fmaxf(mx0, __shfl_xor_sync(0xffffffffu, mx0, 2));
        mx1 = fmaxf(mx1, __shfl_xor_sync(0xffffffffu, mx1, 1));
        mx1 = fmaxf(mx1, __shfl_xor_sync(0xffffffffu, mx1, 2));
        float nm0 = fmaxf(m0, mx0);
        float nm1 = fmaxf(m1, mx1);
        float f0 = ex2f(m0 - nm0);
        float f1 = ex2f(m1 - nm1);
        m0 = nm0; m1 = nm1;

        uint32_t pp[8][2];
#pragma unroll
        for (int n = 0; n < 8; n++) {
            pp[n][0] = ex2_f16x2(pack_f16x2(cs[n][0] - nm0, cs[n][1] - nm0));
            pp[n][1] = ex2_f16x2(pack_f16x2(cs[n][2] - nm1, cs[n][3] - nm1));
        }

#pragma unroll
        for (int n = 0; n < 8; n++) {
            co[n][0] *= f0; co[n][1] *= f0;
            co[n][2] *= f1; co[n][3] *= f1;
        }
        lacc[0] *= f0; lacc[2] *= f1;

#pragma unroll
        for (int kk = 0; kk < 4; kk++) {
            uint32_t pa[4] = {pp[2 * kk][0], pp[2 * kk][1],
                              pp[2 * kk + 1][0], pp[2 * kk + 1][1]};
#pragma unroll
            for (int ng = 0; ng < 4; ng++) {
                uint32_t vaddr = (uint32_t)((kk * 16 + (lane & 15)) * FSTRB
                                            + (ng * 16 + (lane >> 4) * 8) * 2);
                uint32_t vf[4];
                ldsm4t(vf, sVf + vaddr);
                mma16816h(co[ng * 2], pa, vf);
                mma16816h(co[ng * 2 + 1], pa, vf + 2);
            }
            uint32_t v1[2];
            ldsm2t(v1, sVf + (uint32_t)((kk * 16 + (lane & 15)) * FSTRB + 128));
            mma16816h(lacc, pa, v1);
        }

        __syncthreads();
        if (kt + 2 < nkt) LOADKV(kt + 2);
    }

    float l0 = __shfl_sync(0xffffffffu, lacc[0], lane & ~3);
    float l1 = __shfl_sync(0xffffffffu, lacc[2], lane & ~3);
    float inv0 = 1.0f / l0;
    float inv1 = 1.0f / l1;

    int srow = qb * 128 + wm * 16 + (lane >> 2);
    size_t base0 = ((size_t)(b * SS) + srow) * QDIM + h * 64 + (lane & 3) * 2;
    size_t base1 = base0 + (size_t)8 * QDIM;
#pragma unroll
    for (int nd = 0; nd < 8; nd++) {
        *(__half2*)(Of + base0 + nd * 8) =
            __floats2half2_rn(co[nd][0] * inv0, co[nd][1] * inv0);
        *(__half2*)(Of + base1 + nd * 8) =
            __floats2half2_rn(co[nd][2] * inv1, co[nd][3] * inv1);
    }
#undef LOADKV
}

// ---------------------------------------------------------------------------
// Launch: cvt_all, gemmQKV(fused rope), flash, gemmO  (4 launches)
// ---------------------------------------------------------------------------
extern "C" void kernel_launch(void* const* d_in, const int* in_sizes, int n_in,
                              void* d_out, int out_size) {
    const float* x = (const float*)d_in[0];
    const float* wq = (const float*)d_in[1];
    const float* wk = (const float*)d_in[2];
    const float* wv = (const float*)d_in[3];
    const float* wo = (const float*)d_in[4];
    const float* cosT = (const float*)d_in[5];
    const float* sinT = (const float*)d_in[6];
    float* out = (float*)d_out;

    __half *xf, *Wc, *Wof, *Qf, *Kf, *Vf, *Of;
    cudaGetSymbolAddress((void**)&xf, g_xf);
    cudaGetSymbolAddress((void**)&Wc, g_Wc);
    cudaGetSymbolAddress((void**)&Wof, g_Wof);
    cudaGetSymbolAddress((void**)&Qf, g_Qf);
    cudaGetSymbolAddress((void**)&Kf, g_Kf);
    cudaGetSymbolAddress((void**)&Vf, g_Vf);
    cudaGetSymbolAddress((void**)&Of, g_Of);

    cudaFuncSetAttribute(gemm2<0>, cudaFuncAttributeMaxDynamicSharedMemorySize,
                         G_SMEM_TOTAL);
    cudaFuncSetAttribute(gemm2<1>, cudaFuncAttributeMaxDynamicSharedMemorySize,
                         G_SMEM_TOTAL);
    cudaFuncSetAttribute(flash_mma, cudaFuncAttributeMaxDynamicSharedMemorySize,
                         FL_SMEM);

    // 1. All input conversions (plain fp16)
    cvt_all<<<(CV_TOTAL + 255) / 256, 256>>>(x, wq, wk, wv, wo, xf, Wc, Wof);

    // 2. Fused QKV projection + RoPE + relayout
    gemm2<1><<<dim3(QKVD / 128, MTOT / 256), 256, G_SMEM_TOTAL>>>(
        xf, Wc, nullptr, QKVD, DM, cosT, sinT, Qf, Kf, Vf);

    // 3. Attention (writes fp16 O)
    flash_mma<<<dim3(SS / 128, NH, BB), 256, FL_SMEM>>>(Qf, Kf, Vf, Of);

    // 4. Output projection: out = Of @ Wof^T
    gemm2<0><<<dim3(DM / 128, MTOT / 256), 256, G_SMEM_TOTAL>>>(
        Of, Wof, out, DM, QDIM, nullptr, nullptr, nullptr, nullptr, nullptr);
}